// round 3
// baseline (speedup 1.0000x reference)
#include <cuda_runtime.h>
#include <cstdint>
#include <cstddef>

#define MTOK 32768      // B*T
#define HD   768
#define NENT 2048
#define PDIM 300
#define PPAD 320
#define TB   512
#define NB   64

// ---------------- scratch (static device globals; no allocations) ------------
__device__ float g_H[(size_t)MTOK * HD];        // relu(X@W1^T+b1)
__device__ float g_pooled[(size_t)MTOK * HD];   // pooled (reused for both passes)
__device__ float g_pm[(size_t)MTOK * PPAD];     // pooled@Wm^T (K padded to 320)
__device__ float g_pd[(size_t)NENT * PPAD];     // ent@Wd^T   (K padded to 320)
__device__ unsigned char g_valid1[MTOK];
__device__ unsigned char g_valid2[MTOK];
__device__ int g_pred[MTOK];
__device__ unsigned int g_segse[NB * TB];       // per segment: start | end<<16
__device__ int g_nseg[NB];
__device__ int g_dest[NB];

// =============================================================================
// Generic tiled GEMM:  C[m,n] = act( sum_k A[m,k]*B[n,k] + bias[n] )
// BM=BN=128, BK=16, 256 threads, 8x8 microtiles.
// valid != null -> skip 128-row band if no valid row (band left untouched).
// B rows >= NloadB treated as zero; stores guarded by n < Nstore.
// M must be a multiple of 128 (true for 32768 and 2048). K multiple of 16.
// =============================================================================
__global__ void __launch_bounds__(256, 2) gemm_abT(
    const float* __restrict__ A, const float* __restrict__ B,
    float* __restrict__ C, const float* __restrict__ bias,
    const unsigned char* __restrict__ valid,
    int Nstore, int NloadB, int K,
    int lda, int ldb, int ldc, int do_relu)
{
    __shared__ float As[16][132];
    __shared__ float Bs[16][132];
    __shared__ int s_any;

    const int tid = threadIdx.x;
    const int m0 = blockIdx.y * 128;
    const int n0 = blockIdx.x * 128;

    if (valid != nullptr) {
        if (tid == 0) s_any = 0;
        __syncthreads();
        if (tid < 128 && valid[m0 + tid]) s_any = 1;
        __syncthreads();
        if (!s_any) return;
    }

    const int tx = tid & 15, ty = tid >> 4;
    const int lrow = tid >> 2;          // 0..63
    const int lk4  = (tid & 3) * 4;     // 0,4,8,12

    float acc[8][8];
#pragma unroll
    for (int i = 0; i < 8; i++)
#pragma unroll
        for (int j = 0; j < 8; j++) acc[i][j] = 0.f;

    const int nk = K / 16;
    const float* Ap0 = A + (size_t)(m0 + lrow) * lda + lk4;
    const float* Ap1 = Ap0 + (size_t)64 * lda;
    const int gn0 = n0 + lrow, gn1 = n0 + lrow + 64;
    const float* Bp0 = B + (size_t)gn0 * ldb + lk4;
    const float* Bp1 = B + (size_t)gn1 * ldb + lk4;
    const bool bok0 = gn0 < NloadB, bok1 = gn1 < NloadB;
    const float4 zero4 = make_float4(0.f, 0.f, 0.f, 0.f);

    float4 ar0, ar1, br0, br1;
    ar0 = *(const float4*)(Ap0);
    ar1 = *(const float4*)(Ap1);
    br0 = bok0 ? *(const float4*)(Bp0) : zero4;
    br1 = bok1 ? *(const float4*)(Bp1) : zero4;

    // store tile 0
    As[lk4 + 0][lrow] = ar0.x; As[lk4 + 1][lrow] = ar0.y;
    As[lk4 + 2][lrow] = ar0.z; As[lk4 + 3][lrow] = ar0.w;
    As[lk4 + 0][lrow + 64] = ar1.x; As[lk4 + 1][lrow + 64] = ar1.y;
    As[lk4 + 2][lrow + 64] = ar1.z; As[lk4 + 3][lrow + 64] = ar1.w;
    Bs[lk4 + 0][lrow] = br0.x; Bs[lk4 + 1][lrow] = br0.y;
    Bs[lk4 + 2][lrow] = br0.z; Bs[lk4 + 3][lrow] = br0.w;
    Bs[lk4 + 0][lrow + 64] = br1.x; Bs[lk4 + 1][lrow + 64] = br1.y;
    Bs[lk4 + 2][lrow + 64] = br1.z; Bs[lk4 + 3][lrow + 64] = br1.w;
    __syncthreads();

    for (int kt = 0; kt < nk; kt++) {
        if (kt + 1 < nk) {
            const int ko = (kt + 1) * 16;
            ar0 = *(const float4*)(Ap0 + ko);
            ar1 = *(const float4*)(Ap1 + ko);
            br0 = bok0 ? *(const float4*)(Bp0 + ko) : zero4;
            br1 = bok1 ? *(const float4*)(Bp1 + ko) : zero4;
        }
#pragma unroll
        for (int k = 0; k < 16; k++) {
            float a[8], b[8];
            *(float4*)&a[0] = *(const float4*)&As[k][ty * 4];
            *(float4*)&a[4] = *(const float4*)&As[k][64 + ty * 4];
            *(float4*)&b[0] = *(const float4*)&Bs[k][tx * 4];
            *(float4*)&b[4] = *(const float4*)&Bs[k][64 + tx * 4];
#pragma unroll
            for (int i = 0; i < 8; i++)
#pragma unroll
                for (int j = 0; j < 8; j++)
                    acc[i][j] = fmaf(a[i], b[j], acc[i][j]);
        }
        if (kt + 1 < nk) {
            __syncthreads();
            As[lk4 + 0][lrow] = ar0.x; As[lk4 + 1][lrow] = ar0.y;
            As[lk4 + 2][lrow] = ar0.z; As[lk4 + 3][lrow] = ar0.w;
            As[lk4 + 0][lrow + 64] = ar1.x; As[lk4 + 1][lrow + 64] = ar1.y;
            As[lk4 + 2][lrow + 64] = ar1.z; As[lk4 + 3][lrow + 64] = ar1.w;
            Bs[lk4 + 0][lrow] = br0.x; Bs[lk4 + 1][lrow] = br0.y;
            Bs[lk4 + 2][lrow] = br0.z; Bs[lk4 + 3][lrow] = br0.w;
            Bs[lk4 + 0][lrow + 64] = br1.x; Bs[lk4 + 1][lrow + 64] = br1.y;
            Bs[lk4 + 2][lrow + 64] = br1.z; Bs[lk4 + 3][lrow + 64] = br1.w;
            __syncthreads();
        }
    }

#pragma unroll
    for (int ih = 0; ih < 2; ih++)
#pragma unroll
        for (int i = 0; i < 4; i++) {
            const int gm = m0 + ih * 64 + ty * 4 + i;
            float* Cr = C + (size_t)gm * ldc;
#pragma unroll
            for (int jh = 0; jh < 2; jh++) {
                const int gn = n0 + jh * 64 + tx * 4;
                if (gn < Nstore) {
                    float4 v;
                    v.x = acc[ih * 4 + i][jh * 4 + 0];
                    v.y = acc[ih * 4 + i][jh * 4 + 1];
                    v.z = acc[ih * 4 + i][jh * 4 + 2];
                    v.w = acc[ih * 4 + i][jh * 4 + 3];
                    if (bias) {
                        const float4 bv = *(const float4*)(bias + gn);
                        v.x += bv.x; v.y += bv.y; v.z += bv.z; v.w += bv.w;
                    }
                    if (do_relu) {
                        v.x = fmaxf(v.x, 0.f); v.y = fmaxf(v.y, 0.f);
                        v.z = fmaxf(v.z, 0.f); v.w = fmaxf(v.w, 0.f);
                    }
                    *(float4*)(Cr + gn) = v;
                }
            }
        }
}

// =============================================================================
// Bio head: per token  logits3 = h@W2^T + b2 ; log_softmax ; argmax (first max)
// one warp per token row
// =============================================================================
__global__ void __launch_bounds__(256) head_kernel(
    const float* __restrict__ Hb, const float* __restrict__ W2,
    const float* __restrict__ b2, float* __restrict__ out0,
    int* __restrict__ pred)
{
    __shared__ float w2s[3 * HD];
    __shared__ float b2s[3];
    const int tid = threadIdx.x;
    for (int i = tid; i < 3 * HD; i += 256) w2s[i] = W2[i];
    if (tid < 3) b2s[tid] = b2[tid];
    __syncthreads();

    const int warp = tid >> 5, lane = tid & 31;
    const int row = blockIdx.x * 8 + warp;
    const float* hr = Hb + (size_t)row * HD;
    float d0 = 0.f, d1 = 0.f, d2 = 0.f;
#pragma unroll
    for (int q = 0; q < 6; q++) {
        const int off = q * 128 + lane * 4;
        const float4 h  = *(const float4*)(hr + off);
        const float4 w0 = *(const float4*)(w2s + 0 * HD + off);
        const float4 w1 = *(const float4*)(w2s + 1 * HD + off);
        const float4 w2v = *(const float4*)(w2s + 2 * HD + off);
        d0 += h.x * w0.x + h.y * w0.y + h.z * w0.z + h.w * w0.w;
        d1 += h.x * w1.x + h.y * w1.y + h.z * w1.z + h.w * w1.w;
        d2 += h.x * w2v.x + h.y * w2v.y + h.z * w2v.z + h.w * w2v.w;
    }
#pragma unroll
    for (int o = 16; o >= 1; o >>= 1) {
        d0 += __shfl_xor_sync(0xffffffffu, d0, o);
        d1 += __shfl_xor_sync(0xffffffffu, d1, o);
        d2 += __shfl_xor_sync(0xffffffffu, d2, o);
    }
    if (lane == 0) {
        const float l0 = d0 + b2s[0], l1 = d1 + b2s[1], l2 = d2 + b2s[2];
        const float m = fmaxf(l0, fmaxf(l1, l2));
        const float s = __expf(l0 - m) + __expf(l1 - m) + __expf(l2 - m);
        const float lse = m + __logf(s);
        out0[row * 3 + 0] = l0 - lse;
        out0[row * 3 + 1] = l1 - lse;
        out0[row * 3 + 2] = l2 - lse;
        int p = 0; float bst = l0;
        if (l1 > bst) { bst = l1; p = 1; }
        if (l2 > bst) { p = 2; }
        pred[row] = p;
    }
}

// =============================================================================
// Segment scan: per batch, BIO segmentation. Segment = tokens from a label==1
// (inclusive) up to the next 1; leading segment exists if a kept (==2) token
// precedes the first 1. label==0 tokens are dropped but stay in the range.
// Also computes batch compaction destinations.
// =============================================================================
__global__ void seg_scan(const int* __restrict__ lab,
                         unsigned int* __restrict__ segse,
                         int* __restrict__ nseg, int* __restrict__ dest)
{
    __shared__ int sh_ns[NB];
    const int b = threadIdx.x;
    if (b < NB) {
        const int* L = lab + b * TB;
        int ns = 0, start = 0, count = 0;
        for (int t0 = 0; t0 < TB; t0 += 16) {
            int lv[16];
#pragma unroll
            for (int j = 0; j < 16; j++) lv[j] = L[t0 + j];
#pragma unroll
            for (int j = 0; j < 16; j++) {
                const int t = t0 + j;
                const int l = lv[j];
                if (l == 1) {
                    if (count > 0)
                        segse[b * TB + ns++] = (unsigned)start | ((unsigned)t << 16);
                    start = t; count = 1;
                } else if (l != 0) {
                    count++;
                }
            }
        }
        if (count > 0)
            segse[b * TB + ns++] = (unsigned)start | ((unsigned)TB << 16);
        nseg[b] = ns;
        sh_ns[b] = ns;
    }
    __syncthreads();
    if (b == 0) {
        int p = 0;
        for (int i = 0; i < NB; i++)
            dest[i] = (sh_ns[i] > 0) ? p++ : -1;
    }
}

// =============================================================================
// Pool phase 2: one block per (segment r, batch b): mean of kept tokens.
// pooled is pre-zeroed; only valid rows are written; valid flag set.
// =============================================================================
__global__ void __launch_bounds__(256) pool_phase2(
    const float* __restrict__ hidden, const int* __restrict__ lab,
    const unsigned int* __restrict__ segse, const int* __restrict__ nseg,
    const int* __restrict__ dest, float* __restrict__ pooled,
    unsigned char* __restrict__ valid)
{
    const int b = blockIdx.y, r = blockIdx.x;
    if (r >= nseg[b]) return;
    const unsigned se = segse[b * TB + r];
    const int start = (int)(se & 0xffffu), end = (int)(se >> 16);
    const int tid = threadIdx.x;
    float a0 = 0.f, a1 = 0.f, a2 = 0.f;
    int cnt = 0;
    for (int t = start; t < end; t++) {
        const int l = lab[b * TB + t];
        if (l != 0) {
            const float* hp = hidden + (size_t)(b * TB + t) * HD;
            a0 += hp[tid]; a1 += hp[tid + 256]; a2 += hp[tid + 512];
            cnt++;
        }
    }
    const float c = (float)cnt;
    const int outr = dest[b] * TB + r;
    float* pp = pooled + (size_t)outr * HD;
    pp[tid] = a0 / c; pp[tid + 256] = a1 / c; pp[tid + 512] = a2 / c;
    if (tid == 0) valid[outr] = 1;
}

// =============================================================================
// Score: s = pm @ pd^T then log_softmax over N=2048, fused (online max/sum).
// One block owns a 64-row band across all 2048 cols (16 col tiles of 128).
// Raw tiles written to out, then L2-hot fixup subtracts rowMax+log(rowSum).
// Bands with no valid row -> constant -ln(2048).
// =============================================================================
__global__ void __launch_bounds__(256, 2) score_kernel(
    const float* __restrict__ pm, const float* __restrict__ pd,
    const unsigned char* __restrict__ valid, float* __restrict__ out)
{
    __shared__ float Ams[16][68];
    __shared__ float Bms[16][132];
    __shared__ float rowM[64];
    __shared__ float rowS[64];
    __shared__ int s_any;

    const int tid = threadIdx.x;
    const int m0 = blockIdx.x * 64;
    if (tid == 0) s_any = 0;
    __syncthreads();
    if (tid < 64 && valid[m0 + tid]) s_any = 1;
    __syncthreads();

    float* orow = out + (size_t)m0 * NENT;
    if (!s_any) {
        const float C0 = -7.6246190f;   // -ln(2048)
        const float4 v = make_float4(C0, C0, C0, C0);
        float4* o4 = (float4*)orow;
        for (int i = tid; i < 64 * NENT / 4; i += 256) o4[i] = v;
        return;
    }
    if (tid < 64) { rowM[tid] = -3.0e38f; rowS[tid] = 0.f; }

    const int tx = tid & 15, ty = tid >> 4;
    const int lrow = tid >> 2;
    const int lk4  = (tid & 3) * 4;
    const float* Ap = pm + (size_t)(m0 + lrow) * PPAD + lk4;

    for (int nt = 0; nt < 16; nt++) {
        const int n0 = nt * 128;
        const float* Bp0 = pd + (size_t)(n0 + lrow) * PPAD + lk4;
        const float* Bp1 = Bp0 + (size_t)64 * PPAD;
        float acc[4][8];
#pragma unroll
        for (int i = 0; i < 4; i++)
#pragma unroll
            for (int j = 0; j < 8; j++) acc[i][j] = 0.f;

        float4 ar = *(const float4*)(Ap);
        float4 br0 = *(const float4*)(Bp0);
        float4 br1 = *(const float4*)(Bp1);

        for (int kt = 0; kt < PPAD / 16; kt++) {
            __syncthreads();
            Ams[lk4 + 0][lrow] = ar.x; Ams[lk4 + 1][lrow] = ar.y;
            Ams[lk4 + 2][lrow] = ar.z; Ams[lk4 + 3][lrow] = ar.w;
            Bms[lk4 + 0][lrow] = br0.x; Bms[lk4 + 1][lrow] = br0.y;
            Bms[lk4 + 2][lrow] = br0.z; Bms[lk4 + 3][lrow] = br0.w;
            Bms[lk4 + 0][lrow + 64] = br1.x; Bms[lk4 + 1][lrow + 64] = br1.y;
            Bms[lk4 + 2][lrow + 64] = br1.z; Bms[lk4 + 3][lrow + 64] = br1.w;
            __syncthreads();
            if (kt + 1 < PPAD / 16) {
                const int ko = (kt + 1) * 16;
                ar  = *(const float4*)(Ap + ko);
                br0 = *(const float4*)(Bp0 + ko);
                br1 = *(const float4*)(Bp1 + ko);
            }
#pragma unroll
            for (int k = 0; k < 16; k++) {
                float a[4], b[8];
                *(float4*)&a[0] = *(const float4*)&Ams[k][ty * 4];
                *(float4*)&b[0] = *(const float4*)&Bms[k][tx * 4];
                *(float4*)&b[4] = *(const float4*)&Bms[k][64 + tx * 4];
#pragma unroll
                for (int i = 0; i < 4; i++)
#pragma unroll
                    for (int j = 0; j < 8; j++)
                        acc[i][j] = fmaf(a[i], b[j], acc[i][j]);
            }
        }

        // epilogue: per-row tile max / sumexp, online update, raw store
#pragma unroll
        for (int i = 0; i < 4; i++) {
            float tm = acc[i][0];
#pragma unroll
            for (int j = 1; j < 8; j++) tm = fmaxf(tm, acc[i][j]);
#pragma unroll
            for (int o = 8; o >= 1; o >>= 1)
                tm = fmaxf(tm, __shfl_xor_sync(0xffffffffu, tm, o, 16));
            float ts = 0.f;
#pragma unroll
            for (int j = 0; j < 8; j++) ts += __expf(acc[i][j] - tm);
#pragma unroll
            for (int o = 8; o >= 1; o >>= 1)
                ts += __shfl_xor_sync(0xffffffffu, ts, o, 16);
            if (tx == 0) {
                const int r = ty * 4 + i;
                const float M = rowM[r], S = rowS[r];
                const float nm = fmaxf(M, tm);
                rowS[r] = S * __expf(M - nm) + ts * __expf(tm - nm);
                rowM[r] = nm;
            }
            float* op = orow + (size_t)(ty * 4 + i) * NENT + n0;
            *(float4*)(op + tx * 4) =
                make_float4(acc[i][0], acc[i][1], acc[i][2], acc[i][3]);
            *(float4*)(op + 64 + tx * 4) =
                make_float4(acc[i][4], acc[i][5], acc[i][6], acc[i][7]);
        }
    }

    __syncthreads();
    if (tid < 64) rowM[tid] += __logf(rowS[tid]);
    __syncthreads();
    float4* o4 = (float4*)orow;
    for (int i = tid; i < 64 * NENT / 4; i += 256) {
        const int r = i >> 9;           // 512 float4 per row
        const float c = rowM[r];
        float4 v = o4[i];
        v.x -= c; v.y -= c; v.z -= c; v.w -= c;
        o4[i] = v;
    }
}

// =============================================================================
extern "C" void kernel_launch(void* const* d_in, const int* in_sizes, int n_in,
                              void* d_out, int out_size)
{
    (void)in_sizes; (void)n_in; (void)out_size;
    const int*   labels = (const int*)d_in[0];
    const float* hidden = (const float*)d_in[1];
    const float* ent    = (const float*)d_in[2];
    const float* W1     = (const float*)d_in[3];
    const float* b1     = (const float*)d_in[4];
    const float* W2     = (const float*)d_in[5];
    const float* b2     = (const float*)d_in[6];
    const float* Wm     = (const float*)d_in[7];
    const float* Wd     = (const float*)d_in[8];

    float* out0 = (float*)d_out;
    float* out1 = out0 + (size_t)MTOK * 3;
    float* out2 = out1 + (size_t)MTOK * NENT;

    float *pH, *pPooled, *pPm, *pPd;
    unsigned char *pV1, *pV2;
    int *pPred, *pNseg, *pDest;
    unsigned int *pSegse;
    cudaGetSymbolAddress((void**)&pH,      g_H);
    cudaGetSymbolAddress((void**)&pPooled, g_pooled);
    cudaGetSymbolAddress((void**)&pPm,     g_pm);
    cudaGetSymbolAddress((void**)&pPd,     g_pd);
    cudaGetSymbolAddress((void**)&pV1,     g_valid1);
    cudaGetSymbolAddress((void**)&pV2,     g_valid2);
    cudaGetSymbolAddress((void**)&pPred,   g_pred);
    cudaGetSymbolAddress((void**)&pNseg,   g_nseg);
    cudaGetSymbolAddress((void**)&pDest,   g_dest);
    cudaGetSymbolAddress((void**)&pSegse,  g_segse);

    // 1) h = relu(X@W1^T + b1)
    gemm_abT<<<dim3(HD / 128, MTOK / 128), 256>>>(
        hidden, W1, pH, b1, nullptr, HD, HD, HD, HD, HD, HD, 1);

    // 2) bio head: log_softmax logits + predicted labels
    head_kernel<<<MTOK / 8, 256>>>(pH, W2, b2, out0, pPred);

    // 3) pd = ent @ Wd^T (padded K to 320, cols 300..319 zero)
    gemm_abT<<<dim3(PPAD / 128 + 1, NENT / 128), 256>>>(
        ent, Wd, pPd, nullptr, nullptr, PPAD, PDIM, HD, HD, HD, PPAD, 0);

    // ---- pass 1: true labels ----
    cudaMemsetAsync(pPooled, 0, (size_t)MTOK * HD * sizeof(float));
    cudaMemsetAsync(pV1, 0, MTOK);
    seg_scan<<<1, NB>>>(labels, pSegse, pNseg, pDest);
    pool_phase2<<<dim3(TB, NB), 256>>>(hidden, labels, pSegse, pNseg, pDest,
                                       pPooled, pV1);
    gemm_abT<<<dim3(PPAD / 128 + 1, MTOK / 128), 256>>>(
        pPooled, Wm, pPm, nullptr, pV1, PPAD, PDIM, HD, HD, HD, PPAD, 0);
    score_kernel<<<MTOK / 64, 256>>>(pPm, pPd, pV1, out1);

    // ---- pass 2: predicted labels ----
    cudaMemsetAsync(pPooled, 0, (size_t)MTOK * HD * sizeof(float));
    cudaMemsetAsync(pV2, 0, MTOK);
    seg_scan<<<1, NB>>>(pPred, pSegse, pNseg, pDest);
    pool_phase2<<<dim3(TB, NB), 256>>>(hidden, pPred, pSegse, pNseg, pDest,
                                       pPooled, pV2);
    gemm_abT<<<dim3(PPAD / 128 + 1, MTOK / 128), 256>>>(
        pPooled, Wm, pPm, nullptr, pV2, PPAD, PDIM, HD, HD, HD, PPAD, 0);
    score_kernel<<<MTOK / 64, 256>>>(pPm, pPd, pV2, out2);
}

// round 7
// speedup vs baseline: 1.1411x; 1.1411x over previous
#include <cuda_runtime.h>
#include <cstdint>
#include <cstddef>

#define MTOK 32768      // B*T
#define HD   768
#define NENT 2048
#define PDIM 300
#define PPAD 320
#define TB   512
#define NB   64

// ---------------- scratch (static device globals; no allocations) ------------
__device__ float g_H[(size_t)MTOK * HD];        // relu(X@W1^T+b1)  (split-tf32 accurate)
__device__ float g_pooled[(size_t)MTOK * HD];
__device__ float g_pm[(size_t)MTOK * PPAD];
__device__ float g_pd[(size_t)NENT * PPAD];
__device__ unsigned char g_valid1[MTOK];
__device__ unsigned char g_valid2[MTOK];
__device__ int g_pred[MTOK];
__device__ unsigned int g_segse[NB * TB];
__device__ int g_nseg[NB];
__device__ int g_dest[NB];

// ---------------------------------------------------------------------------
// tf32 helpers
// ---------------------------------------------------------------------------
__device__ __forceinline__ unsigned f2t(float x) {
    unsigned r;
    asm("cvt.rna.tf32.f32 %0, %1;" : "=r"(r) : "f"(x));
    return r;
}

__device__ __forceinline__ void mma8(float* c, const unsigned* a, const unsigned* b) {
    asm volatile(
        "mma.sync.aligned.m16n8k8.row.col.f32.tf32.tf32.f32 "
        "{%0,%1,%2,%3},{%4,%5,%6,%7},{%8,%9},{%0,%1,%2,%3};\n"
        : "+f"(c[0]), "+f"(c[1]), "+f"(c[2]), "+f"(c[3])
        : "r"(a[0]), "r"(a[1]), "r"(a[2]), "r"(a[3]), "r"(b[0]), "r"(b[1]));
}

// =============================================================================
// Tensor-core GEMM: C[m,n] = act( sum_k A[m,k]*B[n,k] + bias[n] )
// BM=128, BN=64, BK=32, 256 threads, warps 4(m)x2(n), warp tile 32x32... (32m x 32n)
// SPLIT=1: 2-term tf32 split (3 products) => ~fp32 accuracy.
// valid != null -> skip 128-row band with no valid row.
// B rows >= NloadB read as zero. Stores guarded col < Nstore. M%128==0, K%32==0.
// =============================================================================
template<int SPLIT, int RELU>
__global__ void __launch_bounds__(256, 2) gemm_tc(
    const float* __restrict__ A, const float* __restrict__ B,
    float* __restrict__ C, const float* __restrict__ bias,
    const unsigned char* __restrict__ valid,
    int Nstore, int NloadB, int K, int lda, int ldb, int ldc)
{
    __shared__ float As[32][132];   // [k][m]
    __shared__ float Bs[32][68];    // [k][n]
    __shared__ int s_any;

    const int tid = threadIdx.x;
    const int m0 = blockIdx.y * 128;
    const int n0 = blockIdx.x * 64;

    if (valid != nullptr) {
        if (tid == 0) s_any = 0;
        __syncthreads();
        if (tid < 128 && valid[m0 + tid]) s_any = 1;
        __syncthreads();
        if (!s_any) return;
    }

    const int warp = tid >> 5, lane = tid & 31;
    const int wm = warp & 3;        // 0..3 -> m offset wm*32
    const int wn = warp >> 2;       // 0..1 -> n offset wn*32
    const int g = lane >> 2, tig = lane & 3;

    float acc[2][4][4];
#pragma unroll
    for (int i = 0; i < 2; i++)
#pragma unroll
        for (int j = 0; j < 4; j++)
#pragma unroll
            for (int r = 0; r < 4; r++) acc[i][j][r] = 0.f;

    // staged global loads: A tile 128x32 (4 float4/thread), B tile 64x32 (2/thread)
    int arow[4], acol[4];
#pragma unroll
    for (int i = 0; i < 4; i++) {
        const int idx = tid + 256 * i;
        arow[i] = idx >> 3; acol[i] = (idx & 7) * 4;
    }
    int brow[2], bcol[2]; bool bok[2];
#pragma unroll
    for (int i = 0; i < 2; i++) {
        const int idx = tid + 256 * i;
        brow[i] = idx >> 3; bcol[i] = (idx & 7) * 4;
        bok[i] = (n0 + brow[i]) < NloadB;
    }
    const float* Ap[4]; const float* Bp[2];
#pragma unroll
    for (int i = 0; i < 4; i++) Ap[i] = A + (size_t)(m0 + arow[i]) * lda + acol[i];
#pragma unroll
    for (int i = 0; i < 2; i++) Bp[i] = B + (size_t)(n0 + brow[i]) * ldb + bcol[i];

    const float4 z4 = make_float4(0.f, 0.f, 0.f, 0.f);
    float4 ar[4], br[2];
#pragma unroll
    for (int i = 0; i < 4; i++) ar[i] = *(const float4*)Ap[i];
#pragma unroll
    for (int i = 0; i < 2; i++) br[i] = bok[i] ? *(const float4*)Bp[i] : z4;

#pragma unroll
    for (int i = 0; i < 4; i++) {
        As[acol[i] + 0][arow[i]] = ar[i].x; As[acol[i] + 1][arow[i]] = ar[i].y;
        As[acol[i] + 2][arow[i]] = ar[i].z; As[acol[i] + 3][arow[i]] = ar[i].w;
    }
#pragma unroll
    for (int i = 0; i < 2; i++) {
        Bs[bcol[i] + 0][brow[i]] = br[i].x; Bs[bcol[i] + 1][brow[i]] = br[i].y;
        Bs[bcol[i] + 2][brow[i]] = br[i].z; Bs[bcol[i] + 3][brow[i]] = br[i].w;
    }
    __syncthreads();

    const int nk = K / 32;
    for (int kt = 0; kt < nk; kt++) {
        if (kt + 1 < nk) {
            const int ko = (kt + 1) * 32;
#pragma unroll
            for (int i = 0; i < 4; i++) ar[i] = *(const float4*)(Ap[i] + ko);
#pragma unroll
            for (int i = 0; i < 2; i++) br[i] = bok[i] ? *(const float4*)(Bp[i] + ko) : z4;
        }
#pragma unroll
        for (int ks = 0; ks < 4; ks++) {
            const int kb = ks * 8;
            unsigned ah[2][4], al[2][4];
#pragma unroll
            for (int mt = 0; mt < 2; mt++) {
                const int r = wm * 32 + mt * 16 + g;
                const float f0 = As[kb + tig][r];
                const float f1 = As[kb + tig][r + 8];
                const float f2 = As[kb + tig + 4][r];
                const float f3 = As[kb + tig + 4][r + 8];
                ah[mt][0] = f2t(f0); ah[mt][1] = f2t(f1);
                ah[mt][2] = f2t(f2); ah[mt][3] = f2t(f3);
                if (SPLIT) {
                    al[mt][0] = f2t(f0 - __uint_as_float(ah[mt][0]));
                    al[mt][1] = f2t(f1 - __uint_as_float(ah[mt][1]));
                    al[mt][2] = f2t(f2 - __uint_as_float(ah[mt][2]));
                    al[mt][3] = f2t(f3 - __uint_as_float(ah[mt][3]));
                }
            }
#pragma unroll
            for (int nt = 0; nt < 4; nt++) {
                const int cn = wn * 32 + nt * 8 + g;
                const float fb0 = Bs[kb + tig][cn];
                const float fb1 = Bs[kb + tig + 4][cn];
                unsigned bh[2] = { f2t(fb0), f2t(fb1) };
                unsigned bl[2];
                if (SPLIT) {
                    bl[0] = f2t(fb0 - __uint_as_float(bh[0]));
                    bl[1] = f2t(fb1 - __uint_as_float(bh[1]));
                }
#pragma unroll
                for (int mt = 0; mt < 2; mt++) {
                    mma8(acc[mt][nt], ah[mt], bh);
                    if (SPLIT) {
                        mma8(acc[mt][nt], ah[mt], bl);
                        mma8(acc[mt][nt], al[mt], bh);
                    }
                }
            }
        }
        if (kt + 1 < nk) {
            __syncthreads();
#pragma unroll
            for (int i = 0; i < 4; i++) {
                As[acol[i] + 0][arow[i]] = ar[i].x; As[acol[i] + 1][arow[i]] = ar[i].y;
                As[acol[i] + 2][arow[i]] = ar[i].z; As[acol[i] + 3][arow[i]] = ar[i].w;
            }
#pragma unroll
            for (int i = 0; i < 2; i++) {
                Bs[bcol[i] + 0][brow[i]] = br[i].x; Bs[bcol[i] + 1][brow[i]] = br[i].y;
                Bs[bcol[i] + 2][brow[i]] = br[i].z; Bs[bcol[i] + 3][brow[i]] = br[i].w;
            }
            __syncthreads();
        }
    }

    // epilogue: c0,c1 = (row, col..col+1), c2,c3 = (row+8, col..col+1)
#pragma unroll
    for (int mt = 0; mt < 2; mt++) {
        const int row = m0 + wm * 32 + mt * 16 + g;
#pragma unroll
        for (int nt = 0; nt < 4; nt++) {
            const int col = n0 + wn * 32 + nt * 8 + tig * 2;
            if (col < Nstore) {
                float v0 = acc[mt][nt][0], v1 = acc[mt][nt][1];
                float v2 = acc[mt][nt][2], v3 = acc[mt][nt][3];
                if (bias) {
                    const float b0 = bias[col], b1 = bias[col + 1];
                    v0 += b0; v1 += b1; v2 += b0; v3 += b1;
                }
                if (RELU) {
                    v0 = fmaxf(v0, 0.f); v1 = fmaxf(v1, 0.f);
                    v2 = fmaxf(v2, 0.f); v3 = fmaxf(v3, 0.f);
                }
                float2 w0 = make_float2(v0, v1);
                float2 w1 = make_float2(v2, v3);
                *(float2*)(C + (size_t)row * ldc + col) = w0;
                *(float2*)(C + (size_t)(row + 8) * ldc + col) = w1;
            }
        }
    }
}

// =============================================================================
// Bio head (unchanged): logits3 = h@W2^T + b2 ; log_softmax ; argmax (first max)
// =============================================================================
__global__ void __launch_bounds__(256) head_kernel(
    const float* __restrict__ Hb, const float* __restrict__ W2,
    const float* __restrict__ b2, float* __restrict__ out0,
    int* __restrict__ pred)
{
    __shared__ float w2s[3 * HD];
    __shared__ float b2s[3];
    const int tid = threadIdx.x;
    for (int i = tid; i < 3 * HD; i += 256) w2s[i] = W2[i];
    if (tid < 3) b2s[tid] = b2[tid];
    __syncthreads();

    const int warp = tid >> 5, lane = tid & 31;
    const int row = blockIdx.x * 8 + warp;
    const float* hr = Hb + (size_t)row * HD;
    float d0 = 0.f, d1 = 0.f, d2 = 0.f;
#pragma unroll
    for (int q = 0; q < 6; q++) {
        const int off = q * 128 + lane * 4;
        const float4 h  = *(const float4*)(hr + off);
        const float4 w0 = *(const float4*)(w2s + 0 * HD + off);
        const float4 w1 = *(const float4*)(w2s + 1 * HD + off);
        const float4 w2v = *(const float4*)(w2s + 2 * HD + off);
        d0 += h.x * w0.x + h.y * w0.y + h.z * w0.z + h.w * w0.w;
        d1 += h.x * w1.x + h.y * w1.y + h.z * w1.z + h.w * w1.w;
        d2 += h.x * w2v.x + h.y * w2v.y + h.z * w2v.z + h.w * w2v.w;
    }
#pragma unroll
    for (int o = 16; o >= 1; o >>= 1) {
        d0 += __shfl_xor_sync(0xffffffffu, d0, o);
        d1 += __shfl_xor_sync(0xffffffffu, d1, o);
        d2 += __shfl_xor_sync(0xffffffffu, d2, o);
    }
    if (lane == 0) {
        const float l0 = d0 + b2s[0], l1 = d1 + b2s[1], l2 = d2 + b2s[2];
        const float m = fmaxf(l0, fmaxf(l1, l2));
        const float s = __expf(l0 - m) + __expf(l1 - m) + __expf(l2 - m);
        const float lse = m + __logf(s);
        out0[row * 3 + 0] = l0 - lse;
        out0[row * 3 + 1] = l1 - lse;
        out0[row * 3 + 2] = l2 - lse;
        int p = 0; float bst = l0;
        if (l1 > bst) { bst = l1; p = 1; }
        if (l2 > bst) { p = 2; }
        pred[row] = p;
    }
}

// =============================================================================
// Segment scan: one block per batch; labels staged to smem, serial scan by t0.
// =============================================================================
__global__ void seg_scan(const int* __restrict__ lab,
                         unsigned int* __restrict__ segse, int* __restrict__ nseg)
{
    __shared__ int L[TB];
    const int b = blockIdx.x;
    for (int i = threadIdx.x; i < TB; i += blockDim.x) L[i] = lab[b * TB + i];
    __syncthreads();
    if (threadIdx.x == 0) {
        int ns = 0, start = 0, count = 0;
#pragma unroll 8
        for (int t = 0; t < TB; t++) {
            const int l = L[t];
            if (l == 1) {
                if (count > 0)
                    segse[b * TB + ns++] = (unsigned)start | ((unsigned)t << 16);
                start = t; count = 1;
            } else if (l != 0) {
                count++;
            }
        }
        if (count > 0)
            segse[b * TB + ns++] = (unsigned)start | ((unsigned)TB << 16);
        nseg[b] = ns;
    }
}

__global__ void seg_dest(const int* __restrict__ nseg, int* __restrict__ dest)
{
    if (threadIdx.x == 0) {
        int p = 0;
        for (int i = 0; i < NB; i++) dest[i] = (nseg[i] > 0) ? p++ : -1;
    }
}

// =============================================================================
// Pool phase 2 (unchanged): one block per (segment r, batch b)
// =============================================================================
__global__ void __launch_bounds__(256) pool_phase2(
    const float* __restrict__ hidden, const int* __restrict__ lab,
    const unsigned int* __restrict__ segse, const int* __restrict__ nseg,
    const int* __restrict__ dest, float* __restrict__ pooled,
    unsigned char* __restrict__ valid)
{
    const int b = blockIdx.y, r = blockIdx.x;
    if (r >= nseg[b]) return;
    const unsigned se = segse[b * TB + r];
    const int start = (int)(se & 0xffffu), end = (int)(se >> 16);
    const int tid = threadIdx.x;
    float a0 = 0.f, a1 = 0.f, a2 = 0.f;
    int cnt = 0;
    for (int t = start; t < end; t++) {
        const int l = lab[b * TB + t];
        if (l != 0) {
            const float* hp = hidden + (size_t)(b * TB + t) * HD;
            a0 += hp[tid]; a1 += hp[tid + 256]; a2 += hp[tid + 512];
            cnt++;
        }
    }
    const float c = (float)cnt;
    const int outr = dest[b] * TB + r;
    float* pp = pooled + (size_t)outr * HD;
    pp[tid] = a0 / c; pp[tid + 256] = a1 / c; pp[tid + 512] = a2 / c;
    if (tid == 0) valid[outr] = 1;
}

// =============================================================================
// Fused score + log_softmax, tensor cores, 2-pass over N (write output ONCE).
// Block = 64-row band. pm band resident in smem (k-major). pd streamed by
// 128x32 chunks. Pass 0: per-row online (max, sumexp). Pass 1: recompute
// (bitwise identical mma order) and store v - lse.
// warps: wm = warp&1 (rows wm*32), wn = warp>>1 (cols wn*32 of each 128 ntile).
// =============================================================================
#define SC_APM_F  (PPAD * 68)          // 21760 floats  Apm[PPAD][68]
#define SC_BS_F   (32 * 132)           // 4224          Bsc[32][132]
#define SC_SMEM_F (SC_APM_F + SC_BS_F + 256 + 256 + 64)
#define SC_SMEM_BYTES (SC_SMEM_F * 4)

__global__ void __launch_bounds__(256, 2) score_tc(
    const float* __restrict__ pm, const float* __restrict__ pd,
    const unsigned char* __restrict__ valid, float* __restrict__ out)
{
    extern __shared__ float sm[];
    float (*Apm)[68]  = (float(*)[68])sm;
    float (*Bsc)[132] = (float(*)[132])(sm + SC_APM_F);
    float* partM = sm + SC_APM_F + SC_BS_F;
    float* partS = partM + 256;
    float* lse   = partS + 256;
    __shared__ int s_any;

    const int tid = threadIdx.x;
    const int m0 = blockIdx.x * 64;
    if (tid == 0) s_any = 0;
    __syncthreads();
    if (tid < 64 && valid[m0 + tid]) s_any = 1;
    __syncthreads();

    float* orow = out + (size_t)m0 * NENT;
    if (!s_any) {
        const float C0 = -7.6246190f;   // -ln(2048)
        const float4 v = make_float4(C0, C0, C0, C0);
        float4* o4 = (float4*)orow;
        for (int i = tid; i < 64 * NENT / 4; i += 256) o4[i] = v;
        return;
    }

    // load pm band (64 x 320) into Apm[k][row]
    {
        const int row = tid >> 2, l4 = tid & 3;
        const float* src = pm + (size_t)(m0 + row) * PPAD;
        for (int c4 = l4; c4 < 80; c4 += 4) {
            const float4 v = *(const float4*)(src + c4 * 4);
            Apm[c4 * 4 + 0][row] = v.x; Apm[c4 * 4 + 1][row] = v.y;
            Apm[c4 * 4 + 2][row] = v.z; Apm[c4 * 4 + 3][row] = v.w;
        }
    }

    const int warp = tid >> 5, lane = tid & 31;
    const int wm = warp & 1;        // rows wm*32
    const int wn = warp >> 1;       // cols wn*32 (within 128 ntile)
    const int g = lane >> 2, tig = lane & 3;

    int prow[4], pcol4[4];
#pragma unroll
    for (int i = 0; i < 4; i++) {
        const int idx = tid + 256 * i;
        prow[i] = idx >> 3; pcol4[i] = (idx & 7) * 4;
    }

    float Mr[4] = { -3.0e38f, -3.0e38f, -3.0e38f, -3.0e38f };
    float Sr[4] = { 0.f, 0.f, 0.f, 0.f };
    float Ls[4] = { 0.f, 0.f, 0.f, 0.f };
    float acc[2][4][4];
    float4 st[4];

    for (int pass = 0; pass < 2; pass++) {
        // prime chunk 0
#pragma unroll
        for (int i = 0; i < 4; i++)
            st[i] = *(const float4*)(pd + (size_t)prow[i] * PPAD + pcol4[i]);
        __syncthreads();
#pragma unroll
        for (int i = 0; i < 4; i++) {
            Bsc[pcol4[i] + 0][prow[i]] = st[i].x; Bsc[pcol4[i] + 1][prow[i]] = st[i].y;
            Bsc[pcol4[i] + 2][prow[i]] = st[i].z; Bsc[pcol4[i] + 3][prow[i]] = st[i].w;
        }
        __syncthreads();

        for (int c = 0; c < 160; c++) {
            const int NT = c / 10, kc = c % 10;
            if (kc == 0) {
#pragma unroll
                for (int i = 0; i < 2; i++)
#pragma unroll
                    for (int j = 0; j < 4; j++)
#pragma unroll
                        for (int r = 0; r < 4; r++) acc[i][j][r] = 0.f;
            }
            if (c + 1 < 160) {
                const int NT2 = (c + 1) / 10, kc2 = (c + 1) % 10;
#pragma unroll
                for (int i = 0; i < 4; i++)
                    st[i] = *(const float4*)(pd + (size_t)(NT2 * 128 + prow[i]) * PPAD
                                             + kc2 * 32 + pcol4[i]);
            }
            // compute chunk: k in [kc*32, kc*32+32)
#pragma unroll
            for (int ks = 0; ks < 4; ks++) {
                const int ka = kc * 32 + ks * 8;   // Apm index
                const int kb = ks * 8;             // Bsc index
                unsigned ah[2][4];
#pragma unroll
                for (int mt = 0; mt < 2; mt++) {
                    const int r = wm * 32 + mt * 16 + g;
                    ah[mt][0] = f2t(Apm[ka + tig][r]);
                    ah[mt][1] = f2t(Apm[ka + tig][r + 8]);
                    ah[mt][2] = f2t(Apm[ka + tig + 4][r]);
                    ah[mt][3] = f2t(Apm[ka + tig + 4][r + 8]);
                }
#pragma unroll
                for (int nt = 0; nt < 4; nt++) {
                    const int cn = wn * 32 + nt * 8 + g;
                    unsigned bh[2] = { f2t(Bsc[kb + tig][cn]), f2t(Bsc[kb + tig + 4][cn]) };
#pragma unroll
                    for (int mt = 0; mt < 2; mt++) mma8(acc[mt][nt], ah[mt], bh);
                }
            }
            if (kc == 9) {
                const int n0 = NT * 128;
                if (pass == 0) {
                    // online (max, sumexp) per row-slot; slot s = mt*2 + h
#pragma unroll
                    for (int mt = 0; mt < 2; mt++)
#pragma unroll
                        for (int h = 0; h < 2; h++) {
                            const int s = mt * 2 + h;
                            float v[8];
#pragma unroll
                            for (int j = 0; j < 4; j++) {
                                v[j * 2 + 0] = acc[mt][j][h * 2 + 0];
                                v[j * 2 + 1] = acc[mt][j][h * 2 + 1];
                            }
                            float tm = v[0];
#pragma unroll
                            for (int j = 1; j < 8; j++) tm = fmaxf(tm, v[j]);
                            const float nm = fmaxf(Mr[s], tm);
                            float add = 0.f;
#pragma unroll
                            for (int j = 0; j < 8; j++) add += __expf(v[j] - nm);
                            Sr[s] = Sr[s] * __expf(Mr[s] - nm) + add;
                            Mr[s] = nm;
                        }
                } else {
                    // write out = v - lse
#pragma unroll
                    for (int mt = 0; mt < 2; mt++) {
                        const int row = m0 + wm * 32 + mt * 16 + g;
                        const float l0 = Ls[mt * 2 + 0], l1 = Ls[mt * 2 + 1];
#pragma unroll
                        for (int j = 0; j < 4; j++) {
                            const int col = n0 + wn * 32 + j * 8 + tig * 2;
                            float2 w0 = make_float2(acc[mt][j][0] - l0, acc[mt][j][1] - l0);
                            float2 w1 = make_float2(acc[mt][j][2] - l1, acc[mt][j][3] - l1);
                            *(float2*)(out + (size_t)row * NENT + col) = w0;
                            *(float2*)(out + (size_t)(row + 8) * NENT + col) = w1;
                        }
                    }
                }
            }
            if (c + 1 < 160) {
                __syncthreads();
#pragma unroll
                for (int i = 0; i < 4; i++) {
                    Bsc[pcol4[i] + 0][prow[i]] = st[i].x; Bsc[pcol4[i] + 1][prow[i]] = st[i].y;
                    Bsc[pcol4[i] + 2][prow[i]] = st[i].z; Bsc[pcol4[i] + 3][prow[i]] = st[i].w;
                }
                __syncthreads();
            }
        }

        if (pass == 0) {
            // merge across tig quad
#pragma unroll
            for (int s = 0; s < 4; s++) {
#pragma unroll
                for (int off = 1; off <= 2; off <<= 1) {
                    const float oM = __shfl_xor_sync(0xffffffffu, Mr[s], off);
                    const float oS = __shfl_xor_sync(0xffffffffu, Sr[s], off);
                    const float nm = fmaxf(Mr[s], oM);
                    Sr[s] = Sr[s] * __expf(Mr[s] - nm) + oS * __expf(oM - nm);
                    Mr[s] = nm;
                }
            }
            if (tig == 0) {
#pragma unroll
                for (int s = 0; s < 4; s++) {
                    const int r = wm * 32 + (s >> 1) * 16 + (s & 1) * 8 + g;
                    partM[wn * 64 + r] = Mr[s];
                    partS[wn * 64 + r] = Sr[s];
                }
            }
            __syncthreads();
            if (tid < 64) {
                float M = partM[tid];
#pragma unroll
                for (int w = 1; w < 4; w++) M = fmaxf(M, partM[w * 64 + tid]);
                float S = 0.f;
#pragma unroll
                for (int w = 0; w < 4; w++)
                    S += partS[w * 64 + tid] * __expf(partM[w * 64 + tid] - M);
                lse[tid] = M + __logf(S);
            }
            __syncthreads();
#pragma unroll
            for (int s = 0; s < 4; s++)
                Ls[s] = lse[wm * 32 + (s >> 1) * 16 + (s & 1) * 8 + g];
        }
    }
}

// =============================================================================
extern "C" void kernel_launch(void* const* d_in, const int* in_sizes, int n_in,
                              void* d_out, int out_size)
{
    (void)in_sizes; (void)n_in; (void)out_size;
    const int*   labels = (const int*)d_in[0];
    const float* hidden = (const float*)d_in[1];
    const float* ent    = (const float*)d_in[2];
    const float* W1     = (const float*)d_in[3];
    const float* b1     = (const float*)d_in[4];
    const float* W2     = (const float*)d_in[5];
    const float* b2     = (const float*)d_in[6];
    const float* Wm     = (const float*)d_in[7];
    const float* Wd     = (const float*)d_in[8];

    float* out0 = (float*)d_out;
    float* out1 = out0 + (size_t)MTOK * 3;
    float* out2 = out1 + (size_t)MTOK * NENT;

    float *pH, *pPooled, *pPm, *pPd;
    unsigned char *pV1, *pV2;
    int *pPred, *pNseg, *pDest;
    unsigned int *pSegse;
    cudaGetSymbolAddress((void**)&pH,      g_H);
    cudaGetSymbolAddress((void**)&pPooled, g_pooled);
    cudaGetSymbolAddress((void**)&pPm,     g_pm);
    cudaGetSymbolAddress((void**)&pPd,     g_pd);
    cudaGetSymbolAddress((void**)&pV1,     g_valid1);
    cudaGetSymbolAddress((void**)&pV2,     g_valid2);
    cudaGetSymbolAddress((void**)&pPred,   g_pred);
    cudaGetSymbolAddress((void**)&pNseg,   g_nseg);
    cudaGetSymbolAddress((void**)&pDest,   g_dest);
    cudaGetSymbolAddress((void**)&pSegse,  g_segse);

    cudaFuncSetAttribute(score_tc, cudaFuncAttributeMaxDynamicSharedMemorySize,
                         SC_SMEM_BYTES);

    // 1) h = relu(X@W1^T + b1)   (split tf32 => fp32-accurate for argmax)
    gemm_tc<1, 1><<<dim3(HD / 64, MTOK / 128), 256>>>(
        hidden, W1, pH, b1, nullptr, HD, HD, HD, HD, HD, HD);

    // 2) bio head
    head_kernel<<<MTOK / 8, 256>>>(pH, W2, b2, out0, pPred);

    // 3) pd = ent @ Wd^T (cols 300..319 = 0)
    gemm_tc<0, 0><<<dim3(PPAD / 64, NENT / 128), 256>>>(
        ent, Wd, pPd, nullptr, nullptr, PPAD, PDIM, HD, HD, HD, PPAD);

    // ---- pass 1: true labels ----
    cudaMemsetAsync(pPooled, 0, (size_t)MTOK * HD * sizeof(float));
    cudaMemsetAsync(pV1, 0, MTOK);
    seg_scan<<<NB, 128>>>(labels, pSegse, pNseg);
    seg_dest<<<1, 32>>>(pNseg, pDest);
    pool_phase2<<<dim3(TB, NB), 256>>>(hidden, labels, pSegse, pNseg, pDest,
                                       pPooled, pV1);
    gemm_tc<0, 0><<<dim3(PPAD / 64, MTOK / 128), 256>>>(
        pPooled, Wm, pPm, nullptr, pV1, PPAD, PDIM, HD, HD, HD, PPAD);
    score_tc<<<MTOK / 64, 256, SC_SMEM_BYTES>>>(pPm, pPd, pV1, out1);

    // ---- pass 2: predicted labels ----
    cudaMemsetAsync(pPooled, 0, (size_t)MTOK * HD * sizeof(float));
    cudaMemsetAsync(pV2, 0, MTOK);
    seg_scan<<<NB, 128>>>(pPred, pSegse, pNseg);
    seg_dest<<<1, 32>>>(pNseg, pDest);
    pool_phase2<<<dim3(TB, NB), 256>>>(hidden, pPred, pSegse, pNseg, pDest,
                                       pPooled, pV2);
    gemm_tc<0, 0><<<dim3(PPAD / 64, MTOK / 128), 256>>>(
        pPooled, Wm, pPm, nullptr, pV2, PPAD, PDIM, HD, HD, HD, PPAD);
    score_tc<<<MTOK / 64, 256, SC_SMEM_BYTES>>>(pPm, pPd, pV2, out2);
}

// round 8
// speedup vs baseline: 1.2041x; 1.0552x over previous
#include <cuda_runtime.h>
#include <cstdint>
#include <cstddef>

#define MTOK 32768      // B*T
#define HD   768
#define NENT 2048
#define PDIM 300
#define PPAD 320
#define TB   512
#define NB   64

// ---------------- scratch (static device globals; no allocations) ------------
__device__ float g_H[(size_t)MTOK * HD];
__device__ float g_pooled[(size_t)MTOK * HD];
__device__ float g_pm[(size_t)MTOK * PPAD];
__device__ float g_pd[(size_t)NENT * PPAD];
__device__ unsigned char g_valid1[MTOK];
__device__ unsigned char g_valid2[MTOK];
__device__ int g_pred[MTOK];
__device__ unsigned int g_segse[NB * TB];
__device__ int g_nseg[NB];
__device__ int g_dest[NB];

// ---------------------------------------------------------------------------
__device__ __forceinline__ unsigned f2t(float x) {
    unsigned r;
    asm("cvt.rna.tf32.f32 %0, %1;" : "=r"(r) : "f"(x));
    return r;
}
__device__ __forceinline__ float f2tf(float x) { return __uint_as_float(f2t(x)); }

__device__ __forceinline__ void mma8(float* c, const unsigned* a, const unsigned* b) {
    asm volatile(
        "mma.sync.aligned.m16n8k8.row.col.f32.tf32.tf32.f32 "
        "{%0,%1,%2,%3},{%4,%5,%6,%7},{%8,%9},{%0,%1,%2,%3};\n"
        : "+f"(c[0]), "+f"(c[1]), "+f"(c[2]), "+f"(c[3])
        : "r"(a[0]), "r"(a[1]), "r"(a[2]), "r"(a[3]), "r"(b[0]), "r"(b[1]));
}

// =============================================================================
// Tensor-core GEMM with FRAGMENT-LAYOUT smem.  C[m,n] = act(sum A[m,k]B[n,k]+bias)
// BM=128 BN=64 BK=32, 256 thr, warps 4(m)x2(n), warp tile 32x32.
// smem per buffer: A frags [4ks][8mi][32lane][4reg]  (16KB)
//                  B frags [4ks][8ni][32lane][2reg]  (8KB)
// SPLIT=1: hi/lo tf32 split tiles (3 mma per pair) => ~fp32 accuracy.
// valid!=null: skip fully-invalid 128-band; zero pm rows with !valid[row].
// =============================================================================
template<int SPLIT, int RELU>
__global__ void __launch_bounds__(256, 2) gemm_tc(
    const float* __restrict__ A, const float* __restrict__ B,
    float* __restrict__ C, const float* __restrict__ bias,
    const unsigned char* __restrict__ valid,
    int Nstore, int NloadB, int K, int lda, int ldb, int ldc)
{
    extern __shared__ float sm[];
    float* AH = sm;                          // [2][4096]
    float* BH = sm + 8192;                   // [2][2048]
    float* AL = sm + 12288;                  // [2][4096] (SPLIT only)
    float* BL = sm + 20480;                  // [2][2048] (SPLIT only)
    __shared__ int s_any;

    const int tid = threadIdx.x;
    const int m0 = blockIdx.y * 128;
    const int n0 = blockIdx.x * 64;

    if (valid != nullptr) {
        if (tid == 0) s_any = 0;
        __syncthreads();
        if (tid < 128 && valid[m0 + tid]) s_any = 1;
        __syncthreads();
        if (!s_any) return;
    }

    const int warp = tid >> 5, lane = tid & 31;
    const int wm = warp & 3;        // m offset wm*32
    const int wn = warp >> 2;       // n offset wn*32

    float acc[2][4][4];
#pragma unroll
    for (int i = 0; i < 2; i++)
#pragma unroll
        for (int j = 0; j < 4; j++)
#pragma unroll
            for (int r = 0; r < 4; r++) acc[i][j][r] = 0.f;

    // staging maps: A 128x32 -> 4 float4/thread, B 64x32 -> 2 float4/thread
    int aBase[4]; const float* Ap[4];
#pragma unroll
    for (int i = 0; i < 4; i++) {
        const int idx = tid + 256 * i;
        const int r = idx >> 3, c4 = idx & 7;
        const int ks = c4 >> 1, khi = c4 & 1, mi = r >> 4, rr = r & 15;
        aBase[i] = ((ks * 8 + mi) * 32 + (rr & 7) * 4) * 4 + (rr >> 3) + (khi << 1);
        Ap[i] = A + (size_t)(m0 + r) * lda + c4 * 4;
    }
    int bBase[2]; const float* Bp[2]; bool bok[2];
#pragma unroll
    for (int i = 0; i < 2; i++) {
        const int idx = tid + 256 * i;
        const int n = idx >> 3, c4 = idx & 7;
        const int ks = c4 >> 1, khi = c4 & 1;
        bBase[i] = ((ks * 8 + (n >> 3)) * 32 + (n & 7) * 4) * 2 + khi;
        bok[i] = (n0 + n) < NloadB;
        Bp[i] = B + (size_t)(n0 + n) * ldb + c4 * 4;
    }

    const float4 z4 = make_float4(0.f, 0.f, 0.f, 0.f);
    float4 ar[4], br[2];

    auto stage = [&](int buf) {
        const int ao = buf * 4096, bo = buf * 2048;
#pragma unroll
        for (int i = 0; i < 4; i++) {
            const float h0 = f2tf(ar[i].x), h1 = f2tf(ar[i].y);
            const float h2 = f2tf(ar[i].z), h3 = f2tf(ar[i].w);
            AH[ao + aBase[i] + 0]  = h0; AH[ao + aBase[i] + 4]  = h1;
            AH[ao + aBase[i] + 8]  = h2; AH[ao + aBase[i] + 12] = h3;
            if (SPLIT) {
                AL[ao + aBase[i] + 0]  = f2tf(ar[i].x - h0);
                AL[ao + aBase[i] + 4]  = f2tf(ar[i].y - h1);
                AL[ao + aBase[i] + 8]  = f2tf(ar[i].z - h2);
                AL[ao + aBase[i] + 12] = f2tf(ar[i].w - h3);
            }
        }
#pragma unroll
        for (int i = 0; i < 2; i++) {
            const float h0 = f2tf(br[i].x), h1 = f2tf(br[i].y);
            const float h2 = f2tf(br[i].z), h3 = f2tf(br[i].w);
            BH[bo + bBase[i] + 0] = h0; BH[bo + bBase[i] + 2] = h1;
            BH[bo + bBase[i] + 4] = h2; BH[bo + bBase[i] + 6] = h3;
            if (SPLIT) {
                BL[bo + bBase[i] + 0] = f2tf(br[i].x - h0);
                BL[bo + bBase[i] + 2] = f2tf(br[i].y - h1);
                BL[bo + bBase[i] + 4] = f2tf(br[i].z - h2);
                BL[bo + bBase[i] + 6] = f2tf(br[i].w - h3);
            }
        }
    };

    // prologue: tile 0
#pragma unroll
    for (int i = 0; i < 4; i++) ar[i] = *(const float4*)Ap[i];
#pragma unroll
    for (int i = 0; i < 2; i++) br[i] = bok[i] ? *(const float4*)Bp[i] : z4;
    stage(0);
    int cur = 0;

    const int nk = K / 32;
    for (int kt = 0; kt < nk; kt++) {
        if (kt + 1 < nk) {
            const int ko = (kt + 1) * 32;
#pragma unroll
            for (int i = 0; i < 4; i++) ar[i] = *(const float4*)(Ap[i] + ko);
#pragma unroll
            for (int i = 0; i < 2; i++) br[i] = bok[i] ? *(const float4*)(Bp[i] + ko) : z4;
        }
        __syncthreads();   // buf[cur] ready; all warps done with buf[cur^1]
        const int ao = cur * 4096, bo = cur * 2048;
#pragma unroll
        for (int ks = 0; ks < 4; ks++) {
            float4 ah[2], al[2];
#pragma unroll
            for (int mt = 0; mt < 2; mt++) {
                const int off = ((ks * 8 + wm * 2 + mt) * 32 + lane) * 4;
                ah[mt] = *(const float4*)&AH[ao + off];
                if (SPLIT) al[mt] = *(const float4*)&AL[ao + off];
            }
#pragma unroll
            for (int nt = 0; nt < 4; nt++) {
                const int off = ((ks * 8 + wn * 4 + nt) * 32 + lane) * 2;
                float2 bh = *(const float2*)&BH[bo + off];
#pragma unroll
                for (int mt = 0; mt < 2; mt++)
                    mma8(acc[mt][nt], (const unsigned*)&ah[mt], (const unsigned*)&bh);
                if (SPLIT) {
                    float2 bl = *(const float2*)&BL[bo + off];
#pragma unroll
                    for (int mt = 0; mt < 2; mt++) {
                        mma8(acc[mt][nt], (const unsigned*)&ah[mt], (const unsigned*)&bl);
                        mma8(acc[mt][nt], (const unsigned*)&al[mt], (const unsigned*)&bh);
                    }
                }
            }
        }
        if (kt + 1 < nk) { stage(cur ^ 1); cur ^= 1; }
    }

    // epilogue
    const int g = lane >> 2, tig = lane & 3;
#pragma unroll
    for (int mt = 0; mt < 2; mt++) {
        const int row = m0 + wm * 32 + mt * 16 + g;
        bool v0 = true, v1 = true;
        if (valid != nullptr) { v0 = valid[row] != 0; v1 = valid[row + 8] != 0; }
#pragma unroll
        for (int nt = 0; nt < 4; nt++) {
            const int col = n0 + wn * 32 + nt * 8 + tig * 2;
            if (col < Nstore) {
                float a0 = acc[mt][nt][0], a1 = acc[mt][nt][1];
                float a2 = acc[mt][nt][2], a3 = acc[mt][nt][3];
                if (bias) {
                    const float b0 = bias[col], b1 = bias[col + 1];
                    a0 += b0; a1 += b1; a2 += b0; a3 += b1;
                }
                if (RELU) {
                    a0 = fmaxf(a0, 0.f); a1 = fmaxf(a1, 0.f);
                    a2 = fmaxf(a2, 0.f); a3 = fmaxf(a3, 0.f);
                }
                if (!v0) { a0 = 0.f; a1 = 0.f; }
                if (!v1) { a2 = 0.f; a3 = 0.f; }
                *(float2*)(C + (size_t)row * ldc + col) = make_float2(a0, a1);
                *(float2*)(C + (size_t)(row + 8) * ldc + col) = make_float2(a2, a3);
            }
        }
    }
}

// =============================================================================
// Bio head: logits3 = h@W2^T + b2 ; log_softmax ; argmax (first max)
// =============================================================================
__global__ void __launch_bounds__(256) head_kernel(
    const float* __restrict__ Hb, const float* __restrict__ W2,
    const float* __restrict__ b2, float* __restrict__ out0,
    int* __restrict__ pred)
{
    __shared__ float w2s[3 * HD];
    __shared__ float b2s[3];
    const int tid = threadIdx.x;
    for (int i = tid; i < 3 * HD; i += 256) w2s[i] = W2[i];
    if (tid < 3) b2s[tid] = b2[tid];
    __syncthreads();

    const int warp = tid >> 5, lane = tid & 31;
    const int row = blockIdx.x * 8 + warp;
    const float* hr = Hb + (size_t)row * HD;
    float d0 = 0.f, d1 = 0.f, d2 = 0.f;
#pragma unroll
    for (int q = 0; q < 6; q++) {
        const int off = q * 128 + lane * 4;
        const float4 h  = *(const float4*)(hr + off);
        const float4 w0 = *(const float4*)(w2s + 0 * HD + off);
        const float4 w1 = *(const float4*)(w2s + 1 * HD + off);
        const float4 w2v = *(const float4*)(w2s + 2 * HD + off);
        d0 += h.x * w0.x + h.y * w0.y + h.z * w0.z + h.w * w0.w;
        d1 += h.x * w1.x + h.y * w1.y + h.z * w1.z + h.w * w1.w;
        d2 += h.x * w2v.x + h.y * w2v.y + h.z * w2v.z + h.w * w2v.w;
    }
#pragma unroll
    for (int o = 16; o >= 1; o >>= 1) {
        d0 += __shfl_xor_sync(0xffffffffu, d0, o);
        d1 += __shfl_xor_sync(0xffffffffu, d1, o);
        d2 += __shfl_xor_sync(0xffffffffu, d2, o);
    }
    if (lane == 0) {
        const float l0 = d0 + b2s[0], l1 = d1 + b2s[1], l2 = d2 + b2s[2];
        const float m = fmaxf(l0, fmaxf(l1, l2));
        const float s = __expf(l0 - m) + __expf(l1 - m) + __expf(l2 - m);
        const float lse = m + __logf(s);
        out0[row * 3 + 0] = l0 - lse;
        out0[row * 3 + 1] = l1 - lse;
        out0[row * 3 + 2] = l2 - lse;
        int p = 0; float bst = l0;
        if (l1 > bst) { bst = l1; p = 1; }
        if (l2 > bst) { p = 2; }
        pred[row] = p;
    }
}

// =============================================================================
// Segment scan: one block per batch, smem-staged serial scan.
// =============================================================================
__global__ void seg_scan(const int* __restrict__ lab,
                         unsigned int* __restrict__ segse, int* __restrict__ nseg)
{
    __shared__ int L[TB];
    const int b = blockIdx.x;
    for (int i = threadIdx.x; i < TB; i += blockDim.x) L[i] = lab[b * TB + i];
    __syncthreads();
    if (threadIdx.x == 0) {
        int ns = 0, start = 0, count = 0;
#pragma unroll 8
        for (int t = 0; t < TB; t++) {
            const int l = L[t];
            if (l == 1) {
                if (count > 0)
                    segse[b * TB + ns++] = (unsigned)start | ((unsigned)t << 16);
                start = t; count = 1;
            } else if (l != 0) {
                count++;
            }
        }
        if (count > 0)
            segse[b * TB + ns++] = (unsigned)start | ((unsigned)TB << 16);
        nseg[b] = ns;
    }
}

__global__ void seg_dest(const int* __restrict__ nseg, int* __restrict__ dest)
{
    if (threadIdx.x == 0) {
        int p = 0;
        for (int i = 0; i < NB; i++) dest[i] = (nseg[i] > 0) ? p++ : -1;
    }
}

// =============================================================================
// Pool phase 2: one block per (segment r, batch b)
// =============================================================================
__global__ void __launch_bounds__(256) pool_phase2(
    const float* __restrict__ hidden, const int* __restrict__ lab,
    const unsigned int* __restrict__ segse, const int* __restrict__ nseg,
    const int* __restrict__ dest, float* __restrict__ pooled,
    unsigned char* __restrict__ valid)
{
    const int b = blockIdx.y, r = blockIdx.x;
    if (r >= nseg[b]) return;
    const unsigned se = segse[b * TB + r];
    const int start = (int)(se & 0xffffu), end = (int)(se >> 16);
    const int tid = threadIdx.x;
    float a0 = 0.f, a1 = 0.f, a2 = 0.f;
    int cnt = 0;
    for (int t = start; t < end; t++) {
        const int l = lab[b * TB + t];
        if (l != 0) {
            const float* hp = hidden + (size_t)(b * TB + t) * HD;
            a0 += hp[tid]; a1 += hp[tid + 256]; a2 += hp[tid + 512];
            cnt++;
        }
    }
    const float c = (float)cnt;
    const int outr = dest[b] * TB + r;
    float* pp = pooled + (size_t)outr * HD;
    pp[tid] = a0 / c; pp[tid + 256] = a1 / c; pp[tid + 512] = a2 / c;
    if (tid == 0) valid[outr] = 1;
}

// =============================================================================
// Fused score + log_softmax, fragment-layout smem, 2-pass over N.
// Apm frags persistent: [40ks][4mi][32][4] = 80KB (tf32 pre-converted).
// Bsc frags per 128-col chunk: [4ks][16ni][32][2] = 16KB, reg-prefetched.
// =============================================================================
#define SC_APM_F  20480
#define SC_B_F    4096
#define SC_SMEM_F (SC_APM_F + SC_B_F + 256 + 256 + 64)
#define SC_SMEM_BYTES (SC_SMEM_F * 4)

__global__ void __launch_bounds__(256, 2) score_tc(
    const float* __restrict__ pm, const float* __restrict__ pd,
    const unsigned char* __restrict__ valid, float* __restrict__ out)
{
    extern __shared__ float sm[];
    float* Apm = sm;
    float* Bsc = sm + SC_APM_F;
    float* partM = sm + SC_APM_F + SC_B_F;
    float* partS = partM + 256;
    float* lse   = partS + 256;
    __shared__ int s_any;

    const int tid = threadIdx.x;
    const int m0 = blockIdx.x * 64;
    if (tid == 0) s_any = 0;
    __syncthreads();
    if (tid < 64 && valid[m0 + tid]) s_any = 1;
    __syncthreads();

    float* orow = out + (size_t)m0 * NENT;
    if (!s_any) {
        const float C0 = -7.6246190f;   // -ln(2048)
        const float4 v = make_float4(C0, C0, C0, C0);
        float4* o4 = (float4*)orow;
        for (int i = tid; i < 64 * NENT / 4; i += 256) o4[i] = v;
        return;
    }

    // stage pm band (64x320) into Apm fragments, tf32-converted
    {
        const int row = tid >> 2, l4 = tid & 3;
        const float* src = pm + (size_t)(m0 + row) * PPAD;
        const int mi = row >> 4, rr = row & 15;
        const int lpart = (rr & 7) * 4, rpart = rr >> 3;
        for (int c4 = l4; c4 < 80; c4 += 4) {
            const float4 v = *(const float4*)(src + c4 * 4);
            const int ks = c4 >> 1, khi = c4 & 1;
            const int base = ((ks * 4 + mi) * 32 + lpart) * 4 + rpart + (khi << 1);
            Apm[base + 0]  = f2tf(v.x);
            Apm[base + 4]  = f2tf(v.y);
            Apm[base + 8]  = f2tf(v.z);
            Apm[base + 12] = f2tf(v.w);
        }
    }

    const int warp = tid >> 5, lane = tid & 31;
    const int wm = warp & 1;        // rows wm*32
    const int wn = warp >> 1;       // cols wn*32 (within 128 ntile)
    const int g = lane >> 2, tig = lane & 3;

    // B staging map: 128x32 chunk -> 4 float4/thread
    int prow[4], pcol4[4], bBase[4];
#pragma unroll
    for (int i = 0; i < 4; i++) {
        const int idx = tid + 256 * i;
        const int n = idx >> 3, c4 = idx & 7;
        prow[i] = n; pcol4[i] = c4 * 4;
        const int ks = c4 >> 1, khi = c4 & 1;
        bBase[i] = ((ks * 16 + (n >> 3)) * 32 + (n & 7) * 4) * 2 + khi;
    }

    float Mr[4] = { -3.0e38f, -3.0e38f, -3.0e38f, -3.0e38f };
    float Sr[4] = { 0.f, 0.f, 0.f, 0.f };
    float Ls[4] = { 0.f, 0.f, 0.f, 0.f };
    float acc[2][4][4];
    float4 st[4];

    for (int pass = 0; pass < 2; pass++) {
        // prime chunk 0
#pragma unroll
        for (int i = 0; i < 4; i++)
            st[i] = *(const float4*)(pd + (size_t)prow[i] * PPAD + pcol4[i]);

        for (int c = 0; c < 160; c++) {
            const int NT = c / 10, kc = c % 10;
            __syncthreads();    // all warps done reading previous Bsc
#pragma unroll
            for (int i = 0; i < 4; i++) {
                Bsc[bBase[i] + 0] = f2tf(st[i].x);
                Bsc[bBase[i] + 2] = f2tf(st[i].y);
                Bsc[bBase[i] + 4] = f2tf(st[i].z);
                Bsc[bBase[i] + 6] = f2tf(st[i].w);
            }
            __syncthreads();    // Bsc (and on c==0 Apm) visible
            if (c + 1 < 160) {
                const int NT2 = (c + 1) / 10, kc2 = (c + 1) % 10;
#pragma unroll
                for (int i = 0; i < 4; i++)
                    st[i] = *(const float4*)(pd + (size_t)(NT2 * 128 + prow[i]) * PPAD
                                             + kc2 * 32 + pcol4[i]);
            }
            if (kc == 0) {
#pragma unroll
                for (int i = 0; i < 2; i++)
#pragma unroll
                    for (int j = 0; j < 4; j++)
#pragma unroll
                        for (int r = 0; r < 4; r++) acc[i][j][r] = 0.f;
            }
#pragma unroll
            for (int ks = 0; ks < 4; ks++) {
                float4 ah[2];
#pragma unroll
                for (int mt = 0; mt < 2; mt++)
                    ah[mt] = *(const float4*)&Apm[(((kc * 4 + ks) * 4 + wm * 2 + mt) * 32 + lane) * 4];
#pragma unroll
                for (int nt = 0; nt < 4; nt++) {
                    float2 bh = *(const float2*)&Bsc[((ks * 16 + wn * 4 + nt) * 32 + lane) * 2];
#pragma unroll
                    for (int mt = 0; mt < 2; mt++)
                        mma8(acc[mt][nt], (const unsigned*)&ah[mt], (const unsigned*)&bh);
                }
            }
            if (kc == 9) {
                const int n0 = NT * 128;
                if (pass == 0) {
#pragma unroll
                    for (int mt = 0; mt < 2; mt++)
#pragma unroll
                        for (int h = 0; h < 2; h++) {
                            const int s = mt * 2 + h;
                            float v[8];
#pragma unroll
                            for (int j = 0; j < 4; j++) {
                                v[j * 2 + 0] = acc[mt][j][h * 2 + 0];
                                v[j * 2 + 1] = acc[mt][j][h * 2 + 1];
                            }
                            float tm = v[0];
#pragma unroll
                            for (int j = 1; j < 8; j++) tm = fmaxf(tm, v[j]);
                            const float nm = fmaxf(Mr[s], tm);
                            float add = 0.f;
#pragma unroll
                            for (int j = 0; j < 8; j++) add += __expf(v[j] - nm);
                            Sr[s] = Sr[s] * __expf(Mr[s] - nm) + add;
                            Mr[s] = nm;
                        }
                } else {
#pragma unroll
                    for (int mt = 0; mt < 2; mt++) {
                        const int row = m0 + wm * 32 + mt * 16 + g;
                        const float l0 = Ls[mt * 2 + 0], l1 = Ls[mt * 2 + 1];
#pragma unroll
                        for (int j = 0; j < 4; j++) {
                            const int col = n0 + wn * 32 + j * 8 + tig * 2;
                            *(float2*)(out + (size_t)row * NENT + col) =
                                make_float2(acc[mt][j][0] - l0, acc[mt][j][1] - l0);
                            *(float2*)(out + (size_t)(row + 8) * NENT + col) =
                                make_float2(acc[mt][j][2] - l1, acc[mt][j][3] - l1);
                        }
                    }
                }
            }
        }

        if (pass == 0) {
            // merge across quad (tig)
#pragma unroll
            for (int s = 0; s < 4; s++) {
#pragma unroll
                for (int off = 1; off <= 2; off <<= 1) {
                    const float oM = __shfl_xor_sync(0xffffffffu, Mr[s], off);
                    const float oS = __shfl_xor_sync(0xffffffffu, Sr[s], off);
                    const float nm = fmaxf(Mr[s], oM);
                    Sr[s] = Sr[s] * __expf(Mr[s] - nm) + oS * __expf(oM - nm);
                    Mr[s] = nm;
                }
            }
            __syncthreads();
            if (tig == 0) {
#pragma unroll
                for (int s = 0; s < 4; s++) {
                    const int r = wm * 32 + (s >> 1) * 16 + (s & 1) * 8 + g;
                    partM[wn * 64 + r] = Mr[s];
                    partS[wn * 64 + r] = Sr[s];
                }
            }
            __syncthreads();
            if (tid < 64) {
                float M = partM[tid];
#pragma unroll
                for (int w = 1; w < 4; w++) M = fmaxf(M, partM[w * 64 + tid]);
                float S = 0.f;
#pragma unroll
                for (int w = 0; w < 4; w++)
                    S += partS[w * 64 + tid] * __expf(partM[w * 64 + tid] - M);
                lse[tid] = M + __logf(S);
            }
            __syncthreads();
#pragma unroll
            for (int s = 0; s < 4; s++)
                Ls[s] = lse[wm * 32 + (s >> 1) * 16 + (s & 1) * 8 + g];
        }
    }
}

// =============================================================================
extern "C" void kernel_launch(void* const* d_in, const int* in_sizes, int n_in,
                              void* d_out, int out_size)
{
    (void)in_sizes; (void)n_in; (void)out_size;
    const int*   labels = (const int*)d_in[0];
    const float* hidden = (const float*)d_in[1];
    const float* ent    = (const float*)d_in[2];
    const float* W1     = (const float*)d_in[3];
    const float* b1     = (const float*)d_in[4];
    const float* W2     = (const float*)d_in[5];
    const float* b2     = (const float*)d_in[6];
    const float* Wm     = (const float*)d_in[7];
    const float* Wd     = (const float*)d_in[8];

    float* out0 = (float*)d_out;
    float* out1 = out0 + (size_t)MTOK * 3;
    float* out2 = out1 + (size_t)MTOK * NENT;

    float *pH, *pPooled, *pPm, *pPd;
    unsigned char *pV1, *pV2;
    int *pPred, *pNseg, *pDest;
    unsigned int *pSegse;
    cudaGetSymbolAddress((void**)&pH,      g_H);
    cudaGetSymbolAddress((void**)&pPooled, g_pooled);
    cudaGetSymbolAddress((void**)&pPm,     g_pm);
    cudaGetSymbolAddress((void**)&pPd,     g_pd);
    cudaGetSymbolAddress((void**)&pV1,     g_valid1);
    cudaGetSymbolAddress((void**)&pV2,     g_valid2);
    cudaGetSymbolAddress((void**)&pPred,   g_pred);
    cudaGetSymbolAddress((void**)&pNseg,   g_nseg);
    cudaGetSymbolAddress((void**)&pDest,   g_dest);
    cudaGetSymbolAddress((void**)&pSegse,  g_segse);

    const int SMEM_SPLIT = 24576 * 4;   // 96KB
    const int SMEM_NS    = 12288 * 4;   // 48KB
    cudaFuncSetAttribute(gemm_tc<1, 1>, cudaFuncAttributeMaxDynamicSharedMemorySize, SMEM_SPLIT);
    cudaFuncSetAttribute(gemm_tc<0, 0>, cudaFuncAttributeMaxDynamicSharedMemorySize, SMEM_NS);
    cudaFuncSetAttribute(score_tc, cudaFuncAttributeMaxDynamicSharedMemorySize, SC_SMEM_BYTES);

    // 1) h = relu(X@W1^T + b1)   (split tf32 => fp32-accurate for argmax)
    gemm_tc<1, 1><<<dim3(HD / 64, MTOK / 128), 256, SMEM_SPLIT>>>(
        hidden, W1, pH, b1, nullptr, HD, HD, HD, HD, HD, HD);

    // 2) bio head
    head_kernel<<<MTOK / 8, 256>>>(pH, W2, b2, out0, pPred);

    // 3) pd = ent @ Wd^T (cols 300..319 = 0)
    gemm_tc<0, 0><<<dim3(PPAD / 64, NENT / 128), 256, SMEM_NS>>>(
        ent, Wd, pPd, nullptr, nullptr, PPAD, PDIM, HD, HD, HD, PPAD);

    // ---- pass 1: true labels ----
    cudaMemsetAsync(pV1, 0, MTOK);
    seg_scan<<<NB, 128>>>(labels, pSegse, pNseg);
    seg_dest<<<1, 32>>>(pNseg, pDest);
    pool_phase2<<<dim3(TB, NB), 256>>>(hidden, labels, pSegse, pNseg, pDest,
                                       pPooled, pV1);
    gemm_tc<0, 0><<<dim3(PPAD / 64, MTOK / 128), 256, SMEM_NS>>>(
        pPooled, Wm, pPm, nullptr, pV1, PPAD, PDIM, HD, HD, HD, PPAD);
    score_tc<<<MTOK / 64, 256, SC_SMEM_BYTES>>>(pPm, pPd, pV1, out1);

    // ---- pass 2: predicted labels ----
    cudaMemsetAsync(pV2, 0, MTOK);
    seg_scan<<<NB, 128>>>(pPred, pSegse, pNseg);
    seg_dest<<<1, 32>>>(pNseg, pDest);
    pool_phase2<<<dim3(TB, NB), 256>>>(hidden, pPred, pSegse, pNseg, pDest,
                                       pPooled, pV2);
    gemm_tc<0, 0><<<dim3(PPAD / 64, MTOK / 128), 256, SMEM_NS>>>(
        pPooled, Wm, pPm, nullptr, pV2, PPAD, PDIM, HD, HD, HD, PPAD);
    score_tc<<<MTOK / 64, 256, SC_SMEM_BYTES>>>(pPm, pPd, pV2, out2);
}

// round 9
// speedup vs baseline: 1.7878x; 1.4847x over previous
#include <cuda_runtime.h>
#include <cstdint>
#include <cstddef>

#define MTOK 32768      // B*T
#define HD   768
#define NENT 2048
#define PDIM 300
#define PPAD 320
#define TB   512
#define NB   64
#define MAXFIX 4096
#define GAP_THRESH 0.004f

// ---------------- scratch (static device globals; no allocations) ------------
__device__ float g_H[(size_t)MTOK * HD];
__device__ float g_pooled[(size_t)MTOK * HD];
__device__ float g_pm[(size_t)MTOK * PPAD];
__device__ float g_pd[(size_t)NENT * PPAD];
__device__ float g_fixX[(size_t)MAXFIX * HD];
__device__ float g_fixH[(size_t)MAXFIX * HD];
__device__ unsigned char g_valid1[MTOK];
__device__ unsigned char g_valid2[MTOK];
__device__ unsigned char g_fixvalid[MAXFIX];
__device__ int g_fixrows[MAXFIX];
__device__ int g_nfix;
__device__ int g_pred[MTOK];
__device__ unsigned int g_segse[NB * TB];
__device__ int g_nseg[NB];
__device__ int g_dest[NB];

// ---------------------------------------------------------------------------
__device__ __forceinline__ unsigned f2t(float x) {
    unsigned r;
    asm("cvt.rna.tf32.f32 %0, %1;" : "=r"(r) : "f"(x));
    return r;
}
__device__ __forceinline__ float f2tf(float x) { return __uint_as_float(f2t(x)); }

__device__ __forceinline__ void mma8(float* c, const unsigned* a, const unsigned* b) {
    asm volatile(
        "mma.sync.aligned.m16n8k8.row.col.f32.tf32.tf32.f32 "
        "{%0,%1,%2,%3},{%4,%5,%6,%7},{%8,%9},{%0,%1,%2,%3};\n"
        : "+f"(c[0]), "+f"(c[1]), "+f"(c[2]), "+f"(c[3])
        : "r"(a[0]), "r"(a[1]), "r"(a[2]), "r"(a[3]), "r"(b[0]), "r"(b[1]));
}

// =============================================================================
// Tensor-core GEMM, fragment-layout smem.  C[m,n] = act(sum A[m,k]B[n,k]+bias)
// BM=128 BN=64 BK=32, 256 thr, warps 4(m)x2(n).
// SPLIT=1: hi/lo tf32 split (3 mma/pair) => ~fp32 accuracy.
// valid!=null: skip fully-invalid 128-band; zero C rows with !valid[row].
// =============================================================================
template<int SPLIT, int RELU>
__global__ void __launch_bounds__(256, 2) gemm_tc(
    const float* __restrict__ A, const float* __restrict__ B,
    float* __restrict__ C, const float* __restrict__ bias,
    const unsigned char* __restrict__ valid,
    int Nstore, int NloadB, int K, int lda, int ldb, int ldc)
{
    extern __shared__ float sm[];
    float* AH = sm;                          // [2][4096]
    float* BH = sm + 8192;                   // [2][2048]
    float* AL = sm + 12288;                  // [2][4096] (SPLIT only)
    float* BL = sm + 20480;                  // [2][2048] (SPLIT only)
    __shared__ int s_any;

    const int tid = threadIdx.x;
    const int m0 = blockIdx.y * 128;
    const int n0 = blockIdx.x * 64;

    if (valid != nullptr) {
        if (tid == 0) s_any = 0;
        __syncthreads();
        if (tid < 128 && valid[m0 + tid]) s_any = 1;
        __syncthreads();
        if (!s_any) return;
    }

    const int warp = tid >> 5, lane = tid & 31;
    const int wm = warp & 3;
    const int wn = warp >> 2;

    float acc[2][4][4];
#pragma unroll
    for (int i = 0; i < 2; i++)
#pragma unroll
        for (int j = 0; j < 4; j++)
#pragma unroll
            for (int r = 0; r < 4; r++) acc[i][j][r] = 0.f;

    int aBase[4]; const float* Ap[4];
#pragma unroll
    for (int i = 0; i < 4; i++) {
        const int idx = tid + 256 * i;
        const int r = idx >> 3, c4 = idx & 7;
        const int ks = c4 >> 1, khi = c4 & 1, mi = r >> 4, rr = r & 15;
        aBase[i] = ((ks * 8 + mi) * 32 + (rr & 7) * 4) * 4 + (rr >> 3) + (khi << 1);
        Ap[i] = A + (size_t)(m0 + r) * lda + c4 * 4;
    }
    int bBase[2]; const float* Bp[2]; bool bok[2];
#pragma unroll
    for (int i = 0; i < 2; i++) {
        const int idx = tid + 256 * i;
        const int n = idx >> 3, c4 = idx & 7;
        const int ks = c4 >> 1, khi = c4 & 1;
        bBase[i] = ((ks * 8 + (n >> 3)) * 32 + (n & 7) * 4) * 2 + khi;
        bok[i] = (n0 + n) < NloadB;
        Bp[i] = B + (size_t)(n0 + n) * ldb + c4 * 4;
    }

    const float4 z4 = make_float4(0.f, 0.f, 0.f, 0.f);
    float4 ar[4], br[2];

    auto stage = [&](int buf) {
        const int ao = buf * 4096, bo = buf * 2048;
#pragma unroll
        for (int i = 0; i < 4; i++) {
            const float h0 = f2tf(ar[i].x), h1 = f2tf(ar[i].y);
            const float h2 = f2tf(ar[i].z), h3 = f2tf(ar[i].w);
            AH[ao + aBase[i] + 0]  = h0; AH[ao + aBase[i] + 4]  = h1;
            AH[ao + aBase[i] + 8]  = h2; AH[ao + aBase[i] + 12] = h3;
            if (SPLIT) {
                AL[ao + aBase[i] + 0]  = f2tf(ar[i].x - h0);
                AL[ao + aBase[i] + 4]  = f2tf(ar[i].y - h1);
                AL[ao + aBase[i] + 8]  = f2tf(ar[i].z - h2);
                AL[ao + aBase[i] + 12] = f2tf(ar[i].w - h3);
            }
        }
#pragma unroll
        for (int i = 0; i < 2; i++) {
            const float h0 = f2tf(br[i].x), h1 = f2tf(br[i].y);
            const float h2 = f2tf(br[i].z), h3 = f2tf(br[i].w);
            BH[bo + bBase[i] + 0] = h0; BH[bo + bBase[i] + 2] = h1;
            BH[bo + bBase[i] + 4] = h2; BH[bo + bBase[i] + 6] = h3;
            if (SPLIT) {
                BL[bo + bBase[i] + 0] = f2tf(br[i].x - h0);
                BL[bo + bBase[i] + 2] = f2tf(br[i].y - h1);
                BL[bo + bBase[i] + 4] = f2tf(br[i].z - h2);
                BL[bo + bBase[i] + 6] = f2tf(br[i].w - h3);
            }
        }
    };

#pragma unroll
    for (int i = 0; i < 4; i++) ar[i] = *(const float4*)Ap[i];
#pragma unroll
    for (int i = 0; i < 2; i++) br[i] = bok[i] ? *(const float4*)Bp[i] : z4;
    stage(0);
    int cur = 0;

    const int nk = K / 32;
    for (int kt = 0; kt < nk; kt++) {
        if (kt + 1 < nk) {
            const int ko = (kt + 1) * 32;
#pragma unroll
            for (int i = 0; i < 4; i++) ar[i] = *(const float4*)(Ap[i] + ko);
#pragma unroll
            for (int i = 0; i < 2; i++) br[i] = bok[i] ? *(const float4*)(Bp[i] + ko) : z4;
        }
        __syncthreads();
        const int ao = cur * 4096, bo = cur * 2048;
#pragma unroll
        for (int ks = 0; ks < 4; ks++) {
            float4 ah[2], al[2];
#pragma unroll
            for (int mt = 0; mt < 2; mt++) {
                const int off = ((ks * 8 + wm * 2 + mt) * 32 + lane) * 4;
                ah[mt] = *(const float4*)&AH[ao + off];
                if (SPLIT) al[mt] = *(const float4*)&AL[ao + off];
            }
#pragma unroll
            for (int nt = 0; nt < 4; nt++) {
                const int off = ((ks * 8 + wn * 4 + nt) * 32 + lane) * 2;
                float2 bh = *(const float2*)&BH[bo + off];
#pragma unroll
                for (int mt = 0; mt < 2; mt++)
                    mma8(acc[mt][nt], (const unsigned*)&ah[mt], (const unsigned*)&bh);
                if (SPLIT) {
                    float2 bl = *(const float2*)&BL[bo + off];
#pragma unroll
                    for (int mt = 0; mt < 2; mt++) {
                        mma8(acc[mt][nt], (const unsigned*)&ah[mt], (const unsigned*)&bl);
                        mma8(acc[mt][nt], (const unsigned*)&al[mt], (const unsigned*)&bh);
                    }
                }
            }
        }
        if (kt + 1 < nk) { stage(cur ^ 1); cur ^= 1; }
    }

    const int g = lane >> 2, tig = lane & 3;
#pragma unroll
    for (int mt = 0; mt < 2; mt++) {
        const int row = m0 + wm * 32 + mt * 16 + g;
        bool v0 = true, v1 = true;
        if (valid != nullptr) { v0 = valid[row] != 0; v1 = valid[row + 8] != 0; }
#pragma unroll
        for (int nt = 0; nt < 4; nt++) {
            const int col = n0 + wn * 32 + nt * 8 + tig * 2;
            if (col < Nstore) {
                float a0 = acc[mt][nt][0], a1 = acc[mt][nt][1];
                float a2 = acc[mt][nt][2], a3 = acc[mt][nt][3];
                if (bias) {
                    const float b0 = bias[col], b1 = bias[col + 1];
                    a0 += b0; a1 += b1; a2 += b0; a3 += b1;
                }
                if (RELU) {
                    a0 = fmaxf(a0, 0.f); a1 = fmaxf(a1, 0.f);
                    a2 = fmaxf(a2, 0.f); a3 = fmaxf(a3, 0.f);
                }
                if (!v0) { a0 = 0.f; a1 = 0.f; }
                if (!v1) { a2 = 0.f; a3 = 0.f; }
                *(float2*)(C + (size_t)row * ldc + col) = make_float2(a0, a1);
                *(float2*)(C + (size_t)(row + 8) * ldc + col) = make_float2(a2, a3);
            }
        }
    }
}

// =============================================================================
// Bio head: logits3 ; log_softmax ; argmax (first max); flag ambiguous rows.
// =============================================================================
__global__ void __launch_bounds__(256) head_kernel(
    const float* __restrict__ Hb, const float* __restrict__ W2,
    const float* __restrict__ b2, float* __restrict__ out0,
    int* __restrict__ pred, int* __restrict__ fixrows, int* __restrict__ nfix)
{
    __shared__ float w2s[3 * HD];
    __shared__ float b2s[3];
    const int tid = threadIdx.x;
    for (int i = tid; i < 3 * HD; i += 256) w2s[i] = W2[i];
    if (tid < 3) b2s[tid] = b2[tid];
    __syncthreads();

    const int warp = tid >> 5, lane = tid & 31;
    const int row = blockIdx.x * 8 + warp;
    const float* hr = Hb + (size_t)row * HD;
    float d0 = 0.f, d1 = 0.f, d2 = 0.f;
#pragma unroll
    for (int q = 0; q < 6; q++) {
        const int off = q * 128 + lane * 4;
        const float4 h  = *(const float4*)(hr + off);
        const float4 w0 = *(const float4*)(w2s + 0 * HD + off);
        const float4 w1 = *(const float4*)(w2s + 1 * HD + off);
        const float4 w2v = *(const float4*)(w2s + 2 * HD + off);
        d0 += h.x * w0.x + h.y * w0.y + h.z * w0.z + h.w * w0.w;
        d1 += h.x * w1.x + h.y * w1.y + h.z * w1.z + h.w * w1.w;
        d2 += h.x * w2v.x + h.y * w2v.y + h.z * w2v.z + h.w * w2v.w;
    }
#pragma unroll
    for (int o = 16; o >= 1; o >>= 1) {
        d0 += __shfl_xor_sync(0xffffffffu, d0, o);
        d1 += __shfl_xor_sync(0xffffffffu, d1, o);
        d2 += __shfl_xor_sync(0xffffffffu, d2, o);
    }
    if (lane == 0) {
        const float l0 = d0 + b2s[0], l1 = d1 + b2s[1], l2 = d2 + b2s[2];
        const float m = fmaxf(l0, fmaxf(l1, l2));
        const float s = __expf(l0 - m) + __expf(l1 - m) + __expf(l2 - m);
        const float lse = m + __logf(s);
        out0[row * 3 + 0] = l0 - lse;
        out0[row * 3 + 1] = l1 - lse;
        out0[row * 3 + 2] = l2 - lse;
        int p = 0; float bst = l0, sec;
        if (l1 > bst) { sec = bst; bst = l1; p = 1; } else sec = l1;
        if (l2 > bst) { sec = bst; bst = l2; p = 2; }
        else if (l2 > sec) sec = l2;
        pred[row] = p;
        if (bst - sec < GAP_THRESH) {
            const int ix = atomicAdd(nfix, 1);
            if (ix < MAXFIX) fixrows[ix] = row;
        }
    }
}

// gather flagged hidden rows into compact matrix
__global__ void gather_fix(const float* __restrict__ hidden,
                           const int* __restrict__ fixrows,
                           const int* __restrict__ nfix,
                           float* __restrict__ fixX,
                           unsigned char* __restrict__ fixvalid)
{
    const int b = blockIdx.x;
    int n = *nfix; if (n > MAXFIX) n = MAXFIX;
    if (b >= n) return;
    const int row = fixrows[b];
    const float4* src = (const float4*)(hidden + (size_t)row * HD);
    float4* dst = (float4*)(fixX + (size_t)b * HD);
    if (threadIdx.x < 192) dst[threadIdx.x] = src[threadIdx.x];
    if (threadIdx.x == 0) fixvalid[b] = 1;
}

// exact fp32 head on recomputed (split-tf32 ~ fp32) h rows; overwrite out0/pred
__global__ void __launch_bounds__(256) head_fix(
    const float* __restrict__ Hf, const float* __restrict__ W2,
    const float* __restrict__ b2, const int* __restrict__ fixrows,
    const int* __restrict__ nfix, float* __restrict__ out0,
    int* __restrict__ pred)
{
    __shared__ float w2s[3 * HD];
    __shared__ float b2s[3];
    const int tid = threadIdx.x;
    int n = *nfix; if (n > MAXFIX) n = MAXFIX;
    if (blockIdx.x * 8 >= n) return;
    for (int i = tid; i < 3 * HD; i += 256) w2s[i] = W2[i];
    if (tid < 3) b2s[tid] = b2[tid];
    __syncthreads();

    const int warp = tid >> 5, lane = tid & 31;
    const int slot = blockIdx.x * 8 + warp;
    if (slot >= n) return;
    const int row = fixrows[slot];
    const float* hr = Hf + (size_t)slot * HD;
    float d0 = 0.f, d1 = 0.f, d2 = 0.f;
#pragma unroll
    for (int q = 0; q < 6; q++) {
        const int off = q * 128 + lane * 4;
        const float4 h  = *(const float4*)(hr + off);
        const float4 w0 = *(const float4*)(w2s + 0 * HD + off);
        const float4 w1 = *(const float4*)(w2s + 1 * HD + off);
        const float4 w2v = *(const float4*)(w2s + 2 * HD + off);
        d0 += h.x * w0.x + h.y * w0.y + h.z * w0.z + h.w * w0.w;
        d1 += h.x * w1.x + h.y * w1.y + h.z * w1.z + h.w * w1.w;
        d2 += h.x * w2v.x + h.y * w2v.y + h.z * w2v.z + h.w * w2v.w;
    }
#pragma unroll
    for (int o = 16; o >= 1; o >>= 1) {
        d0 += __shfl_xor_sync(0xffffffffu, d0, o);
        d1 += __shfl_xor_sync(0xffffffffu, d1, o);
        d2 += __shfl_xor_sync(0xffffffffu, d2, o);
    }
    if (lane == 0) {
        const float l0 = d0 + b2s[0], l1 = d1 + b2s[1], l2 = d2 + b2s[2];
        const float m = fmaxf(l0, fmaxf(l1, l2));
        const float s = __expf(l0 - m) + __expf(l1 - m) + __expf(l2 - m);
        const float lse = m + __logf(s);
        out0[row * 3 + 0] = l0 - lse;
        out0[row * 3 + 1] = l1 - lse;
        out0[row * 3 + 2] = l2 - lse;
        int p = 0; float bst = l0;
        if (l1 > bst) { bst = l1; p = 1; }
        if (l2 > bst) { p = 2; }
        pred[row] = p;
    }
}

// =============================================================================
// Segment scan + dest
// =============================================================================
__global__ void seg_scan(const int* __restrict__ lab,
                         unsigned int* __restrict__ segse, int* __restrict__ nseg)
{
    __shared__ int L[TB];
    const int b = blockIdx.x;
    for (int i = threadIdx.x; i < TB; i += blockDim.x) L[i] = lab[b * TB + i];
    __syncthreads();
    if (threadIdx.x == 0) {
        int ns = 0, start = 0, count = 0;
#pragma unroll 8
        for (int t = 0; t < TB; t++) {
            const int l = L[t];
            if (l == 1) {
                if (count > 0)
                    segse[b * TB + ns++] = (unsigned)start | ((unsigned)t << 16);
                start = t; count = 1;
            } else if (l != 0) {
                count++;
            }
        }
        if (count > 0)
            segse[b * TB + ns++] = (unsigned)start | ((unsigned)TB << 16);
        nseg[b] = ns;
    }
}

__global__ void seg_dest(const int* __restrict__ nseg, int* __restrict__ dest)
{
    if (threadIdx.x == 0) {
        int p = 0;
        for (int i = 0; i < NB; i++) dest[i] = (nseg[i] > 0) ? p++ : -1;
    }
}

// =============================================================================
// Pool phase 2
// =============================================================================
__global__ void __launch_bounds__(256) pool_phase2(
    const float* __restrict__ hidden, const int* __restrict__ lab,
    const unsigned int* __restrict__ segse, const int* __restrict__ nseg,
    const int* __restrict__ dest, float* __restrict__ pooled,
    unsigned char* __restrict__ valid)
{
    const int b = blockIdx.y, r = blockIdx.x;
    if (r >= nseg[b]) return;
    const unsigned se = segse[b * TB + r];
    const int start = (int)(se & 0xffffu), end = (int)(se >> 16);
    const int tid = threadIdx.x;
    float a0 = 0.f, a1 = 0.f, a2 = 0.f;
    int cnt = 0;
    for (int t = start; t < end; t++) {
        const int l = lab[b * TB + t];
        if (l != 0) {
            const float* hp = hidden + (size_t)(b * TB + t) * HD;
            a0 += hp[tid]; a1 += hp[tid + 256]; a2 += hp[tid + 512];
            cnt++;
        }
    }
    const float c = (float)cnt;
    const int outr = dest[b] * TB + r;
    float* pp = pooled + (size_t)outr * HD;
    pp[tid] = a0 / c; pp[tid + 256] = a1 / c; pp[tid + 512] = a2 / c;
    if (tid == 0) valid[outr] = 1;
}

// =============================================================================
// Fused score + log_softmax: SINGLE mma pass. Writes raw scores while
// accumulating online (max, sumexp); then in-place fixup subtracts lse.
// Apm frags persistent (80KB tf32), Bsc per 128-col chunk (16KB).
// =============================================================================
#define SC_APM_F  20480
#define SC_B_F    4096
#define SC_SMEM_F (SC_APM_F + SC_B_F + 256 + 256 + 64)
#define SC_SMEM_BYTES (SC_SMEM_F * 4)

__global__ void __launch_bounds__(256, 2) score_tc(
    const float* __restrict__ pm, const float* __restrict__ pd,
    const unsigned char* __restrict__ valid, float* __restrict__ out)
{
    extern __shared__ float sm[];
    float* Apm = sm;
    float* Bsc = sm + SC_APM_F;
    float* partM = sm + SC_APM_F + SC_B_F;
    float* partS = partM + 256;
    float* lse   = partS + 256;
    __shared__ int s_any;

    const int tid = threadIdx.x;
    const int m0 = blockIdx.x * 64;
    if (tid == 0) s_any = 0;
    __syncthreads();
    if (tid < 64 && valid[m0 + tid]) s_any = 1;
    __syncthreads();

    float* orow = out + (size_t)m0 * NENT;
    if (!s_any) {
        const float C0 = -7.6246190f;   // -ln(2048)
        const float4 v = make_float4(C0, C0, C0, C0);
        float4* o4 = (float4*)orow;
        for (int i = tid; i < 64 * NENT / 4; i += 256) o4[i] = v;
        return;
    }

    // stage pm band (64x320) into Apm fragments, tf32-converted
    {
        const int row = tid >> 2, l4 = tid & 3;
        const float* src = pm + (size_t)(m0 + row) * PPAD;
        const int mi = row >> 4, rr = row & 15;
        const int lpart = (rr & 7) * 4, rpart = rr >> 3;
        for (int c4 = l4; c4 < 80; c4 += 4) {
            const float4 v = *(const float4*)(src + c4 * 4);
            const int ks = c4 >> 1, khi = c4 & 1;
            const int base = ((ks * 4 + mi) * 32 + lpart) * 4 + rpart + (khi << 1);
            Apm[base + 0]  = f2tf(v.x);
            Apm[base + 4]  = f2tf(v.y);
            Apm[base + 8]  = f2tf(v.z);
            Apm[base + 12] = f2tf(v.w);
        }
    }

    const int warp = tid >> 5, lane = tid & 31;
    const int wm = warp & 1;
    const int wn = warp >> 1;
    const int g = lane >> 2, tig = lane & 3;

    int prow[4], pcol4[4], bBase[4];
#pragma unroll
    for (int i = 0; i < 4; i++) {
        const int idx = tid + 256 * i;
        const int n = idx >> 3, c4 = idx & 7;
        prow[i] = n; pcol4[i] = c4 * 4;
        const int ks = c4 >> 1, khi = c4 & 1;
        bBase[i] = ((ks * 16 + (n >> 3)) * 32 + (n & 7) * 4) * 2 + khi;
    }

    float Mr[4] = { -3.0e38f, -3.0e38f, -3.0e38f, -3.0e38f };
    float Sr[4] = { 0.f, 0.f, 0.f, 0.f };
    float acc[2][4][4];
    float4 st[4];

    // prime chunk 0
#pragma unroll
    for (int i = 0; i < 4; i++)
        st[i] = *(const float4*)(pd + (size_t)prow[i] * PPAD + pcol4[i]);

    for (int c = 0; c < 160; c++) {
        const int NT = c / 10, kc = c % 10;
        __syncthreads();
#pragma unroll
        for (int i = 0; i < 4; i++) {
            Bsc[bBase[i] + 0] = f2tf(st[i].x);
            Bsc[bBase[i] + 2] = f2tf(st[i].y);
            Bsc[bBase[i] + 4] = f2tf(st[i].z);
            Bsc[bBase[i] + 6] = f2tf(st[i].w);
        }
        __syncthreads();
        if (c + 1 < 160) {
            const int NT2 = (c + 1) / 10, kc2 = (c + 1) % 10;
#pragma unroll
            for (int i = 0; i < 4; i++)
                st[i] = *(const float4*)(pd + (size_t)(NT2 * 128 + prow[i]) * PPAD
                                         + kc2 * 32 + pcol4[i]);
        }
        if (kc == 0) {
#pragma unroll
            for (int i = 0; i < 2; i++)
#pragma unroll
                for (int j = 0; j < 4; j++)
#pragma unroll
                    for (int r = 0; r < 4; r++) acc[i][j][r] = 0.f;
        }
#pragma unroll
        for (int ks = 0; ks < 4; ks++) {
            float4 ah[2];
#pragma unroll
            for (int mt = 0; mt < 2; mt++)
                ah[mt] = *(const float4*)&Apm[(((kc * 4 + ks) * 4 + wm * 2 + mt) * 32 + lane) * 4];
#pragma unroll
            for (int nt = 0; nt < 4; nt++) {
                float2 bh = *(const float2*)&Bsc[((ks * 16 + wn * 4 + nt) * 32 + lane) * 2];
#pragma unroll
                for (int mt = 0; mt < 2; mt++)
                    mma8(acc[mt][nt], (const unsigned*)&ah[mt], (const unsigned*)&bh);
            }
        }
        if (kc == 9) {
            const int n0 = NT * 128;
            // online stats
#pragma unroll
            for (int mt = 0; mt < 2; mt++)
#pragma unroll
                for (int h = 0; h < 2; h++) {
                    const int s = mt * 2 + h;
                    float v[8];
#pragma unroll
                    for (int j = 0; j < 4; j++) {
                        v[j * 2 + 0] = acc[mt][j][h * 2 + 0];
                        v[j * 2 + 1] = acc[mt][j][h * 2 + 1];
                    }
                    float tm = v[0];
#pragma unroll
                    for (int j = 1; j < 8; j++) tm = fmaxf(tm, v[j]);
                    const float nm = fmaxf(Mr[s], tm);
                    float add = 0.f;
#pragma unroll
                    for (int j = 0; j < 8; j++) add += __expf(v[j] - nm);
                    Sr[s] = Sr[s] * __expf(Mr[s] - nm) + add;
                    Mr[s] = nm;
                }
            // raw store
#pragma unroll
            for (int mt = 0; mt < 2; mt++) {
                const int row = m0 + wm * 32 + mt * 16 + g;
#pragma unroll
                for (int j = 0; j < 4; j++) {
                    const int col = n0 + wn * 32 + j * 8 + tig * 2;
                    *(float2*)(out + (size_t)row * NENT + col) =
                        make_float2(acc[mt][j][0], acc[mt][j][1]);
                    *(float2*)(out + (size_t)(row + 8) * NENT + col) =
                        make_float2(acc[mt][j][2], acc[mt][j][3]);
                }
            }
        }
    }

    // reduce lse across quad + warps
#pragma unroll
    for (int s = 0; s < 4; s++) {
#pragma unroll
        for (int off = 1; off <= 2; off <<= 1) {
            const float oM = __shfl_xor_sync(0xffffffffu, Mr[s], off);
            const float oS = __shfl_xor_sync(0xffffffffu, Sr[s], off);
            const float nm = fmaxf(Mr[s], oM);
            Sr[s] = Sr[s] * __expf(Mr[s] - nm) + oS * __expf(oM - nm);
            Mr[s] = nm;
        }
    }
    __syncthreads();
    if (tig == 0) {
#pragma unroll
        for (int s = 0; s < 4; s++) {
            const int r = wm * 32 + (s >> 1) * 16 + (s & 1) * 8 + g;
            partM[wn * 64 + r] = Mr[s];
            partS[wn * 64 + r] = Sr[s];
        }
    }
    __syncthreads();
    if (tid < 64) {
        float M = partM[tid];
#pragma unroll
        for (int w = 1; w < 4; w++) M = fmaxf(M, partM[w * 64 + tid]);
        float S = 0.f;
#pragma unroll
        for (int w = 0; w < 4; w++)
            S += partS[w * 64 + tid] * __expf(partM[w * 64 + tid] - M);
        lse[tid] = M + __logf(S);
    }
    __syncthreads();   // lse ready; raw global writes visible block-wide

    // in-place fixup: out -= lse[row]
    float4* o4 = (float4*)orow;
    for (int i = tid; i < 64 * NENT / 4; i += 256) {
        const int r = i >> 9;           // 512 float4 per row
        const float cc = lse[r];
        float4 v = o4[i];
        v.x -= cc; v.y -= cc; v.z -= cc; v.w -= cc;
        o4[i] = v;
    }
}

// =============================================================================
extern "C" void kernel_launch(void* const* d_in, const int* in_sizes, int n_in,
                              void* d_out, int out_size)
{
    (void)in_sizes; (void)n_in; (void)out_size;
    const int*   labels = (const int*)d_in[0];
    const float* hidden = (const float*)d_in[1];
    const float* ent    = (const float*)d_in[2];
    const float* W1     = (const float*)d_in[3];
    const float* b1     = (const float*)d_in[4];
    const float* W2     = (const float*)d_in[5];
    const float* b2     = (const float*)d_in[6];
    const float* Wm     = (const float*)d_in[7];
    const float* Wd     = (const float*)d_in[8];

    float* out0 = (float*)d_out;
    float* out1 = out0 + (size_t)MTOK * 3;
    float* out2 = out1 + (size_t)MTOK * NENT;

    float *pH, *pPooled, *pPm, *pPd, *pFixX, *pFixH;
    unsigned char *pV1, *pV2, *pFixV;
    int *pPred, *pNseg, *pDest, *pFixRows, *pNfix;
    unsigned int *pSegse;
    cudaGetSymbolAddress((void**)&pH,      g_H);
    cudaGetSymbolAddress((void**)&pPooled, g_pooled);
    cudaGetSymbolAddress((void**)&pPm,     g_pm);
    cudaGetSymbolAddress((void**)&pPd,     g_pd);
    cudaGetSymbolAddress((void**)&pFixX,   g_fixX);
    cudaGetSymbolAddress((void**)&pFixH,   g_fixH);
    cudaGetSymbolAddress((void**)&pV1,     g_valid1);
    cudaGetSymbolAddress((void**)&pV2,     g_valid2);
    cudaGetSymbolAddress((void**)&pFixV,   g_fixvalid);
    cudaGetSymbolAddress((void**)&pPred,   g_pred);
    cudaGetSymbolAddress((void**)&pNseg,   g_nseg);
    cudaGetSymbolAddress((void**)&pDest,   g_dest);
    cudaGetSymbolAddress((void**)&pFixRows,g_fixrows);
    cudaGetSymbolAddress((void**)&pNfix,   g_nfix);
    cudaGetSymbolAddress((void**)&pSegse,  g_segse);

    const int SMEM_SPLIT = 24576 * 4;   // 96KB
    const int SMEM_NS    = 12288 * 4;   // 48KB
    cudaFuncSetAttribute(gemm_tc<1, 1>, cudaFuncAttributeMaxDynamicSharedMemorySize, SMEM_SPLIT);
    cudaFuncSetAttribute(gemm_tc<0, 1>, cudaFuncAttributeMaxDynamicSharedMemorySize, SMEM_NS);
    cudaFuncSetAttribute(gemm_tc<0, 0>, cudaFuncAttributeMaxDynamicSharedMemorySize, SMEM_NS);
    cudaFuncSetAttribute(score_tc, cudaFuncAttributeMaxDynamicSharedMemorySize, SC_SMEM_BYTES);

    cudaMemsetAsync(pNfix, 0, sizeof(int));
    cudaMemsetAsync(pFixV, 0, MAXFIX);
    cudaMemsetAsync(pV1, 0, MTOK);
    cudaMemsetAsync(pV2, 0, MTOK);

    // 1) h = relu(X@W1^T + b1)  SINGLE tf32 (fast); ambiguous rows fixed below
    gemm_tc<0, 1><<<dim3(HD / 64, MTOK / 128), 256, SMEM_NS>>>(
        hidden, W1, pH, b1, nullptr, HD, HD, HD, HD, HD, HD);

    // 2) bio head + ambiguity flags
    head_kernel<<<MTOK / 8, 256>>>(pH, W2, b2, out0, pPred, pFixRows, pNfix);

    // 2b) exact recompute of flagged rows (split tf32 ~ fp32)
    gather_fix<<<MAXFIX, 192>>>(hidden, pFixRows, pNfix, pFixX, pFixV);
    gemm_tc<1, 1><<<dim3(HD / 64, MAXFIX / 128), 256, SMEM_SPLIT>>>(
        pFixX, W1, pFixH, b1, pFixV, HD, HD, HD, HD, HD, HD);
    head_fix<<<MAXFIX / 8, 256>>>(pFixH, W2, b2, pFixRows, pNfix, out0, pPred);

    // 3) pd = ent @ Wd^T (cols 300..319 = 0)
    gemm_tc<0, 0><<<dim3(PPAD / 64, NENT / 128), 256, SMEM_NS>>>(
        ent, Wd, pPd, nullptr, nullptr, PPAD, PDIM, HD, HD, HD, PPAD);

    // ---- pass 1: true labels ----
    seg_scan<<<NB, 128>>>(labels, pSegse, pNseg);
    seg_dest<<<1, 32>>>(pNseg, pDest);
    pool_phase2<<<dim3(TB, NB), 256>>>(hidden, labels, pSegse, pNseg, pDest,
                                       pPooled, pV1);
    gemm_tc<0, 0><<<dim3(PPAD / 64, MTOK / 128), 256, SMEM_NS>>>(
        pPooled, Wm, pPm, nullptr, pV1, PPAD, PDIM, HD, HD, HD, PPAD);
    score_tc<<<MTOK / 64, 256, SC_SMEM_BYTES>>>(pPm, pPd, pV1, out1);

    // ---- pass 2: predicted labels ----
    seg_scan<<<NB, 128>>>(pPred, pSegse, pNseg);
    seg_dest<<<1, 32>>>(pNseg, pDest);
    pool_phase2<<<dim3(TB, NB), 256>>>(hidden, pPred, pSegse, pNseg, pDest,
                                       pPooled, pV2);
    gemm_tc<0, 0><<<dim3(PPAD / 64, MTOK / 128), 256, SMEM_NS>>>(
        pPooled, Wm, pPm, nullptr, pV2, PPAD, PDIM, HD, HD, HD, PPAD);
    score_tc<<<MTOK / 64, 256, SC_SMEM_BYTES>>>(pPm, pPd, pV2, out2);
}

// round 10
// speedup vs baseline: 2.8651x; 1.6026x over previous
#include <cuda_runtime.h>
#include <cuda_fp16.h>
#include <cstdint>
#include <cstddef>

#define MTOK 32768      // B*T
#define HD   768
#define NENT 2048
#define PDIM 300
#define PPAD 320
#define TB   512
#define NB   64
#define MAXFIX 4096
#define GAP_THRESH 0.004f

// ---------------- scratch (static device globals; no allocations) ------------
__device__ float g_H[(size_t)MTOK * HD];
__device__ float g_pooled[(size_t)MTOK * HD];
__device__ float g_pm[(size_t)MTOK * PPAD];
__device__ float g_pd[(size_t)NENT * PPAD];
__device__ float g_fixX[(size_t)MAXFIX * HD];
__device__ float g_fixH[(size_t)MAXFIX * HD];
__device__ unsigned char g_valid1[MTOK];
__device__ unsigned char g_valid2[MTOK];
__device__ unsigned char g_fixvalid[MAXFIX];
__device__ int g_fixrows[MAXFIX];
__device__ int g_nfix;
__device__ int g_pred[MTOK];
__device__ unsigned int g_segse[NB * TB];
__device__ int g_nseg[NB];
__device__ int g_dest[NB];

// ---------------------------------------------------------------------------
__device__ __forceinline__ unsigned f2t(float x) {
    unsigned r;
    asm("cvt.rna.tf32.f32 %0, %1;" : "=r"(r) : "f"(x));
    return r;
}
__device__ __forceinline__ float f2tf(float x) { return __uint_as_float(f2t(x)); }

__device__ __forceinline__ unsigned pkh2(float x, float y) {
    __half2 h = __floats2half2_rn(x, y);   // x -> low half (even k)
    return *reinterpret_cast<unsigned*>(&h);
}

__device__ __forceinline__ void mma8(float* c, const unsigned* a, const unsigned* b) {
    asm volatile(
        "mma.sync.aligned.m16n8k8.row.col.f32.tf32.tf32.f32 "
        "{%0,%1,%2,%3},{%4,%5,%6,%7},{%8,%9},{%0,%1,%2,%3};\n"
        : "+f"(c[0]), "+f"(c[1]), "+f"(c[2]), "+f"(c[3])
        : "r"(a[0]), "r"(a[1]), "r"(a[2]), "r"(a[3]), "r"(b[0]), "r"(b[1]));
}

__device__ __forceinline__ void mma16(float* c, const unsigned* a, const unsigned* b) {
    asm volatile(
        "mma.sync.aligned.m16n8k16.row.col.f32.f16.f16.f32 "
        "{%0,%1,%2,%3},{%4,%5,%6,%7},{%8,%9},{%0,%1,%2,%3};\n"
        : "+f"(c[0]), "+f"(c[1]), "+f"(c[2]), "+f"(c[3])
        : "r"(a[0]), "r"(a[1]), "r"(a[2]), "r"(a[3]), "r"(b[0]), "r"(b[1]));
}

// =============================================================================
// FP16 tensor-core GEMM, fragment-layout smem.
// C[m,n] = act(sum A[m,k]B[n,k] + bias).  BM=128 BN=64 BK=32, 256 thr.
// m16n8k16: per 16-k step A frag = uint4, B frag = uint2 (C layout == k8 tf32).
// valid!=null: skip fully-invalid 128-band; zero C rows with !valid[row].
// =============================================================================
template<int RELU>
__global__ void __launch_bounds__(256, 2) gemm_hc(
    const float* __restrict__ A, const float* __restrict__ B,
    float* __restrict__ C, const float* __restrict__ bias,
    const unsigned char* __restrict__ valid,
    int Nstore, int NloadB, int K, int lda, int ldb, int ldc)
{
    extern __shared__ unsigned smu[];
    unsigned* AH = smu;          // [2][2048]  [ks16][mi8][lane][4]
    unsigned* BH = smu + 4096;   // [2][1024]  [ks16][ni8][lane][2]
    __shared__ int s_any;

    const int tid = threadIdx.x;
    const int m0 = blockIdx.y * 128;
    const int n0 = blockIdx.x * 64;

    if (valid != nullptr) {
        if (tid == 0) s_any = 0;
        __syncthreads();
        if (tid < 128 && valid[m0 + tid]) s_any = 1;
        __syncthreads();
        if (!s_any) return;
    }

    const int warp = tid >> 5, lane = tid & 31;
    const int wm = warp & 3;
    const int wn = warp >> 2;

    float acc[2][4][4];
#pragma unroll
    for (int i = 0; i < 2; i++)
#pragma unroll
        for (int j = 0; j < 4; j++)
#pragma unroll
            for (int r = 0; r < 4; r++) acc[i][j][r] = 0.f;

    // A staging: 128x32 tile, 4 float4/thread
    int aAddr[4]; const float* Ap[4];
#pragma unroll
    for (int i = 0; i < 4; i++) {
        const int idx = tid + 256 * i;
        const int r = idx >> 3, c4 = idx & 7;
        const int ks16 = c4 >> 2, kk = (c4 & 3) * 4;
        const int mi = r >> 4, rr = r & 15, g = rr & 7, rh = rr >> 3;
        const int tig0 = (kk & 7) >> 1, reg = rh + 2 * (kk >> 3);
        aAddr[i] = ((ks16 * 8 + mi) * 32 + g * 4 + tig0) * 4 + reg;
        Ap[i] = A + (size_t)(m0 + r) * lda + c4 * 4;
    }
    // B staging: 64x32 tile, 2 float4/thread
    int bAddr[2]; const float* Bp[2]; bool bok[2];
#pragma unroll
    for (int i = 0; i < 2; i++) {
        const int idx = tid + 256 * i;
        const int n = idx >> 3, c4 = idx & 7;
        const int ks16 = c4 >> 2, kk = (c4 & 3) * 4;
        const int ni = n >> 3, g = n & 7;
        const int p0 = kk >> 1, tig0 = p0 & 3, regb = p0 >> 2;
        bAddr[i] = ((ks16 * 8 + ni) * 32 + g * 4 + tig0) * 2 + regb;
        bok[i] = (n0 + n) < NloadB;
        Bp[i] = B + (size_t)(n0 + n) * ldb + c4 * 4;
    }

    const float4 z4 = make_float4(0.f, 0.f, 0.f, 0.f);
    float4 ar[4], br[2];

    auto stage = [&](int buf) {
        const int ao = buf * 2048, bo = buf * 1024;
#pragma unroll
        for (int i = 0; i < 4; i++) {
            AH[ao + aAddr[i] + 0] = pkh2(ar[i].x, ar[i].y);
            AH[ao + aAddr[i] + 4] = pkh2(ar[i].z, ar[i].w);
        }
#pragma unroll
        for (int i = 0; i < 2; i++) {
            BH[bo + bAddr[i] + 0] = pkh2(br[i].x, br[i].y);
            BH[bo + bAddr[i] + 2] = pkh2(br[i].z, br[i].w);
        }
    };

#pragma unroll
    for (int i = 0; i < 4; i++) ar[i] = *(const float4*)Ap[i];
#pragma unroll
    for (int i = 0; i < 2; i++) br[i] = bok[i] ? *(const float4*)Bp[i] : z4;
    stage(0);
    int cur = 0;

    const int nk = K / 32;
    for (int kt = 0; kt < nk; kt++) {
        if (kt + 1 < nk) {
            const int ko = (kt + 1) * 32;
#pragma unroll
            for (int i = 0; i < 4; i++) ar[i] = *(const float4*)(Ap[i] + ko);
#pragma unroll
            for (int i = 0; i < 2; i++) br[i] = bok[i] ? *(const float4*)(Bp[i] + ko) : z4;
        }
        __syncthreads();
        const int ao = cur * 2048, bo = cur * 1024;
#pragma unroll
        for (int ks = 0; ks < 2; ks++) {
            uint4 a[2];
#pragma unroll
            for (int mt = 0; mt < 2; mt++)
                a[mt] = *(const uint4*)&AH[ao + ((ks * 8 + wm * 2 + mt) * 32 + lane) * 4];
#pragma unroll
            for (int nt = 0; nt < 4; nt++) {
                uint2 b = *(const uint2*)&BH[bo + ((ks * 8 + wn * 4 + nt) * 32 + lane) * 2];
#pragma unroll
                for (int mt = 0; mt < 2; mt++)
                    mma16(acc[mt][nt], (const unsigned*)&a[mt], (const unsigned*)&b);
            }
        }
        if (kt + 1 < nk) { stage(cur ^ 1); cur ^= 1; }
    }

    const int g = lane >> 2, tig = lane & 3;
#pragma unroll
    for (int mt = 0; mt < 2; mt++) {
        const int row = m0 + wm * 32 + mt * 16 + g;
        bool v0 = true, v1 = true;
        if (valid != nullptr) { v0 = valid[row] != 0; v1 = valid[row + 8] != 0; }
#pragma unroll
        for (int nt = 0; nt < 4; nt++) {
            const int col = n0 + wn * 32 + nt * 8 + tig * 2;
            if (col < Nstore) {
                float a0 = acc[mt][nt][0], a1 = acc[mt][nt][1];
                float a2 = acc[mt][nt][2], a3 = acc[mt][nt][3];
                if (bias) {
                    const float b0 = bias[col], b1 = bias[col + 1];
                    a0 += b0; a1 += b1; a2 += b0; a3 += b1;
                }
                if (RELU) {
                    a0 = fmaxf(a0, 0.f); a1 = fmaxf(a1, 0.f);
                    a2 = fmaxf(a2, 0.f); a3 = fmaxf(a3, 0.f);
                }
                if (!v0) { a0 = 0.f; a1 = 0.f; }
                if (!v1) { a2 = 0.f; a3 = 0.f; }
                *(float2*)(C + (size_t)row * ldc + col) = make_float2(a0, a1);
                *(float2*)(C + (size_t)(row + 8) * ldc + col) = make_float2(a2, a3);
            }
        }
    }
}

// =============================================================================
// Split-tf32 GEMM (exact path for flagged rows).  Same as R9 gemm_tc SPLIT=1.
// =============================================================================
__global__ void __launch_bounds__(256, 2) gemm_split(
    const float* __restrict__ A, const float* __restrict__ B,
    float* __restrict__ C, const float* __restrict__ bias,
    const unsigned char* __restrict__ valid,
    int Nstore, int NloadB, int K, int lda, int ldb, int ldc)
{
    extern __shared__ float sm[];
    float* AH = sm;                          // [2][4096]
    float* BH = sm + 8192;                   // [2][2048]
    float* AL = sm + 12288;                  // [2][4096]
    float* BL = sm + 20480;                  // [2][2048]
    __shared__ int s_any;

    const int tid = threadIdx.x;
    const int m0 = blockIdx.y * 128;
    const int n0 = blockIdx.x * 64;

    if (valid != nullptr) {
        if (tid == 0) s_any = 0;
        __syncthreads();
        if (tid < 128 && valid[m0 + tid]) s_any = 1;
        __syncthreads();
        if (!s_any) return;
    }

    const int warp = tid >> 5, lane = tid & 31;
    const int wm = warp & 3;
    const int wn = warp >> 2;

    float acc[2][4][4];
#pragma unroll
    for (int i = 0; i < 2; i++)
#pragma unroll
        for (int j = 0; j < 4; j++)
#pragma unroll
            for (int r = 0; r < 4; r++) acc[i][j][r] = 0.f;

    int aBase[4]; const float* Ap[4];
#pragma unroll
    for (int i = 0; i < 4; i++) {
        const int idx = tid + 256 * i;
        const int r = idx >> 3, c4 = idx & 7;
        const int ks = c4 >> 1, khi = c4 & 1, mi = r >> 4, rr = r & 15;
        aBase[i] = ((ks * 8 + mi) * 32 + (rr & 7) * 4) * 4 + (rr >> 3) + (khi << 1);
        Ap[i] = A + (size_t)(m0 + r) * lda + c4 * 4;
    }
    int bBase[2]; const float* Bp[2]; bool bok[2];
#pragma unroll
    for (int i = 0; i < 2; i++) {
        const int idx = tid + 256 * i;
        const int n = idx >> 3, c4 = idx & 7;
        const int ks = c4 >> 1, khi = c4 & 1;
        bBase[i] = ((ks * 8 + (n >> 3)) * 32 + (n & 7) * 4) * 2 + khi;
        bok[i] = (n0 + n) < NloadB;
        Bp[i] = B + (size_t)(n0 + n) * ldb + c4 * 4;
    }

    const float4 z4 = make_float4(0.f, 0.f, 0.f, 0.f);
    float4 ar[4], br[2];

    auto stage = [&](int buf) {
        const int ao = buf * 4096, bo = buf * 2048;
#pragma unroll
        for (int i = 0; i < 4; i++) {
            const float h0 = f2tf(ar[i].x), h1 = f2tf(ar[i].y);
            const float h2 = f2tf(ar[i].z), h3 = f2tf(ar[i].w);
            AH[ao + aBase[i] + 0]  = h0; AH[ao + aBase[i] + 4]  = h1;
            AH[ao + aBase[i] + 8]  = h2; AH[ao + aBase[i] + 12] = h3;
            AL[ao + aBase[i] + 0]  = f2tf(ar[i].x - h0);
            AL[ao + aBase[i] + 4]  = f2tf(ar[i].y - h1);
            AL[ao + aBase[i] + 8]  = f2tf(ar[i].z - h2);
            AL[ao + aBase[i] + 12] = f2tf(ar[i].w - h3);
        }
#pragma unroll
        for (int i = 0; i < 2; i++) {
            const float h0 = f2tf(br[i].x), h1 = f2tf(br[i].y);
            const float h2 = f2tf(br[i].z), h3 = f2tf(br[i].w);
            BH[bo + bBase[i] + 0] = h0; BH[bo + bBase[i] + 2] = h1;
            BH[bo + bBase[i] + 4] = h2; BH[bo + bBase[i] + 6] = h3;
            BL[bo + bBase[i] + 0] = f2tf(br[i].x - h0);
            BL[bo + bBase[i] + 2] = f2tf(br[i].y - h1);
            BL[bo + bBase[i] + 4] = f2tf(br[i].z - h2);
            BL[bo + bBase[i] + 6] = f2tf(br[i].w - h3);
        }
    };

#pragma unroll
    for (int i = 0; i < 4; i++) ar[i] = *(const float4*)Ap[i];
#pragma unroll
    for (int i = 0; i < 2; i++) br[i] = bok[i] ? *(const float4*)Bp[i] : z4;
    stage(0);
    int cur = 0;

    const int nk = K / 32;
    for (int kt = 0; kt < nk; kt++) {
        if (kt + 1 < nk) {
            const int ko = (kt + 1) * 32;
#pragma unroll
            for (int i = 0; i < 4; i++) ar[i] = *(const float4*)(Ap[i] + ko);
#pragma unroll
            for (int i = 0; i < 2; i++) br[i] = bok[i] ? *(const float4*)(Bp[i] + ko) : z4;
        }
        __syncthreads();
        const int ao = cur * 4096, bo = cur * 2048;
#pragma unroll
        for (int ks = 0; ks < 4; ks++) {
            float4 ah[2], al[2];
#pragma unroll
            for (int mt = 0; mt < 2; mt++) {
                const int off = ((ks * 8 + wm * 2 + mt) * 32 + lane) * 4;
                ah[mt] = *(const float4*)&AH[ao + off];
                al[mt] = *(const float4*)&AL[ao + off];
            }
#pragma unroll
            for (int nt = 0; nt < 4; nt++) {
                const int off = ((ks * 8 + wn * 4 + nt) * 32 + lane) * 2;
                float2 bh = *(const float2*)&BH[bo + off];
                float2 bl = *(const float2*)&BL[bo + off];
#pragma unroll
                for (int mt = 0; mt < 2; mt++) {
                    mma8(acc[mt][nt], (const unsigned*)&ah[mt], (const unsigned*)&bh);
                    mma8(acc[mt][nt], (const unsigned*)&ah[mt], (const unsigned*)&bl);
                    mma8(acc[mt][nt], (const unsigned*)&al[mt], (const unsigned*)&bh);
                }
            }
        }
        if (kt + 1 < nk) { stage(cur ^ 1); cur ^= 1; }
    }

    const int g = lane >> 2, tig = lane & 3;
#pragma unroll
    for (int mt = 0; mt < 2; mt++) {
        const int row = m0 + wm * 32 + mt * 16 + g;
        bool v0 = true, v1 = true;
        if (valid != nullptr) { v0 = valid[row] != 0; v1 = valid[row + 8] != 0; }
#pragma unroll
        for (int nt = 0; nt < 4; nt++) {
            const int col = n0 + wn * 32 + nt * 8 + tig * 2;
            if (col < Nstore) {
                float a0 = acc[mt][nt][0], a1 = acc[mt][nt][1];
                float a2 = acc[mt][nt][2], a3 = acc[mt][nt][3];
                if (bias) {
                    const float b0 = bias[col], b1 = bias[col + 1];
                    a0 += b0; a1 += b1; a2 += b0; a3 += b1;
                }
                a0 = fmaxf(a0, 0.f); a1 = fmaxf(a1, 0.f);
                a2 = fmaxf(a2, 0.f); a3 = fmaxf(a3, 0.f);
                if (!v0) { a0 = 0.f; a1 = 0.f; }
                if (!v1) { a2 = 0.f; a3 = 0.f; }
                *(float2*)(C + (size_t)row * ldc + col) = make_float2(a0, a1);
                *(float2*)(C + (size_t)(row + 8) * ldc + col) = make_float2(a2, a3);
            }
        }
    }
}

// =============================================================================
// Bio head: logits3 ; log_softmax ; argmax (first max); flag ambiguous rows.
// =============================================================================
__global__ void __launch_bounds__(256) head_kernel(
    const float* __restrict__ Hb, const float* __restrict__ W2,
    const float* __restrict__ b2, float* __restrict__ out0,
    int* __restrict__ pred, int* __restrict__ fixrows, int* __restrict__ nfix)
{
    __shared__ float w2s[3 * HD];
    __shared__ float b2s[3];
    const int tid = threadIdx.x;
    for (int i = tid; i < 3 * HD; i += 256) w2s[i] = W2[i];
    if (tid < 3) b2s[tid] = b2[tid];
    __syncthreads();

    const int warp = tid >> 5, lane = tid & 31;
    const int row = blockIdx.x * 8 + warp;
    const float* hr = Hb + (size_t)row * HD;
    float d0 = 0.f, d1 = 0.f, d2 = 0.f;
#pragma unroll
    for (int q = 0; q < 6; q++) {
        const int off = q * 128 + lane * 4;
        const float4 h  = *(const float4*)(hr + off);
        const float4 w0 = *(const float4*)(w2s + 0 * HD + off);
        const float4 w1 = *(const float4*)(w2s + 1 * HD + off);
        const float4 w2v = *(const float4*)(w2s + 2 * HD + off);
        d0 += h.x * w0.x + h.y * w0.y + h.z * w0.z + h.w * w0.w;
        d1 += h.x * w1.x + h.y * w1.y + h.z * w1.z + h.w * w1.w;
        d2 += h.x * w2v.x + h.y * w2v.y + h.z * w2v.z + h.w * w2v.w;
    }
#pragma unroll
    for (int o = 16; o >= 1; o >>= 1) {
        d0 += __shfl_xor_sync(0xffffffffu, d0, o);
        d1 += __shfl_xor_sync(0xffffffffu, d1, o);
        d2 += __shfl_xor_sync(0xffffffffu, d2, o);
    }
    if (lane == 0) {
        const float l0 = d0 + b2s[0], l1 = d1 + b2s[1], l2 = d2 + b2s[2];
        const float m = fmaxf(l0, fmaxf(l1, l2));
        const float s = __expf(l0 - m) + __expf(l1 - m) + __expf(l2 - m);
        const float lse = m + __logf(s);
        out0[row * 3 + 0] = l0 - lse;
        out0[row * 3 + 1] = l1 - lse;
        out0[row * 3 + 2] = l2 - lse;
        int p = 0; float bst = l0, sec;
        if (l1 > bst) { sec = bst; bst = l1; p = 1; } else sec = l1;
        if (l2 > bst) { sec = bst; bst = l2; p = 2; }
        else if (l2 > sec) sec = l2;
        pred[row] = p;
        if (bst - sec < GAP_THRESH) {
            const int ix = atomicAdd(nfix, 1);
            if (ix < MAXFIX) fixrows[ix] = row;
        }
    }
}

__global__ void gather_fix(const float* __restrict__ hidden,
                           const int* __restrict__ fixrows,
                           const int* __restrict__ nfix,
                           float* __restrict__ fixX,
                           unsigned char* __restrict__ fixvalid)
{
    const int b = blockIdx.x;
    int n = *nfix; if (n > MAXFIX) n = MAXFIX;
    if (b >= n) return;
    const int row = fixrows[b];
    const float4* src = (const float4*)(hidden + (size_t)row * HD);
    float4* dst = (float4*)(fixX + (size_t)b * HD);
    if (threadIdx.x < 192) dst[threadIdx.x] = src[threadIdx.x];
    if (threadIdx.x == 0) fixvalid[b] = 1;
}

__global__ void __launch_bounds__(256) head_fix(
    const float* __restrict__ Hf, const float* __restrict__ W2,
    const float* __restrict__ b2, const int* __restrict__ fixrows,
    const int* __restrict__ nfix, float* __restrict__ out0,
    int* __restrict__ pred)
{
    __shared__ float w2s[3 * HD];
    __shared__ float b2s[3];
    const int tid = threadIdx.x;
    int n = *nfix; if (n > MAXFIX) n = MAXFIX;
    if (blockIdx.x * 8 >= n) return;
    for (int i = tid; i < 3 * HD; i += 256) w2s[i] = W2[i];
    if (tid < 3) b2s[tid] = b2[tid];
    __syncthreads();

    const int warp = tid >> 5, lane = tid & 31;
    const int slot = blockIdx.x * 8 + warp;
    if (slot >= n) return;
    const int row = fixrows[slot];
    const float* hr = Hf + (size_t)slot * HD;
    float d0 = 0.f, d1 = 0.f, d2 = 0.f;
#pragma unroll
    for (int q = 0; q < 6; q++) {
        const int off = q * 128 + lane * 4;
        const float4 h  = *(const float4*)(hr + off);
        const float4 w0 = *(const float4*)(w2s + 0 * HD + off);
        const float4 w1 = *(const float4*)(w2s + 1 * HD + off);
        const float4 w2v = *(const float4*)(w2s + 2 * HD + off);
        d0 += h.x * w0.x + h.y * w0.y + h.z * w0.z + h.w * w0.w;
        d1 += h.x * w1.x + h.y * w1.y + h.z * w1.z + h.w * w1.w;
        d2 += h.x * w2v.x + h.y * w2v.y + h.z * w2v.z + h.w * w2v.w;
    }
#pragma unroll
    for (int o = 16; o >= 1; o >>= 1) {
        d0 += __shfl_xor_sync(0xffffffffu, d0, o);
        d1 += __shfl_xor_sync(0xffffffffu, d1, o);
        d2 += __shfl_xor_sync(0xffffffffu, d2, o);
    }
    if (lane == 0) {
        const float l0 = d0 + b2s[0], l1 = d1 + b2s[1], l2 = d2 + b2s[2];
        const float m = fmaxf(l0, fmaxf(l1, l2));
        const float s = __expf(l0 - m) + __expf(l1 - m) + __expf(l2 - m);
        const float lse = m + __logf(s);
        out0[row * 3 + 0] = l0 - lse;
        out0[row * 3 + 1] = l1 - lse;
        out0[row * 3 + 2] = l2 - lse;
        int p = 0; float bst = l0;
        if (l1 > bst) { bst = l1; p = 1; }
        if (l2 > bst) { p = 2; }
        pred[row] = p;
    }
}

// =============================================================================
// Segment scan + dest
// =============================================================================
__global__ void seg_scan(const int* __restrict__ lab,
                         unsigned int* __restrict__ segse, int* __restrict__ nseg)
{
    __shared__ int L[TB];
    const int b = blockIdx.x;
    for (int i = threadIdx.x; i < TB; i += blockDim.x) L[i] = lab[b * TB + i];
    __syncthreads();
    if (threadIdx.x == 0) {
        int ns = 0, start = 0, count = 0;
#pragma unroll 8
        for (int t = 0; t < TB; t++) {
            const int l = L[t];
            if (l == 1) {
                if (count > 0)
                    segse[b * TB + ns++] = (unsigned)start | ((unsigned)t << 16);
                start = t; count = 1;
            } else if (l != 0) {
                count++;
            }
        }
        if (count > 0)
            segse[b * TB + ns++] = (unsigned)start | ((unsigned)TB << 16);
        nseg[b] = ns;
    }
}

__global__ void seg_dest(const int* __restrict__ nseg, int* __restrict__ dest)
{
    if (threadIdx.x == 0) {
        int p = 0;
        for (int i = 0; i < NB; i++) dest[i] = (nseg[i] > 0) ? p++ : -1;
    }
}

// =============================================================================
// Pool phase 2: one block (192 thr, float4) per (segment r, batch b)
// =============================================================================
__global__ void __launch_bounds__(192) pool_phase2(
    const float* __restrict__ hidden, const int* __restrict__ lab,
    const unsigned int* __restrict__ segse, const int* __restrict__ nseg,
    const int* __restrict__ dest, float* __restrict__ pooled,
    unsigned char* __restrict__ valid)
{
    const int b = blockIdx.y, r = blockIdx.x;
    if (r >= nseg[b]) return;
    const unsigned se = segse[b * TB + r];
    const int start = (int)(se & 0xffffu), end = (int)(se >> 16);
    const int tid = threadIdx.x;
    float4 a = make_float4(0.f, 0.f, 0.f, 0.f);
    int cnt = 0;
    for (int t = start; t < end; t++) {
        const int l = lab[b * TB + t];
        if (l != 0) {
            const float4 v = ((const float4*)(hidden + (size_t)(b * TB + t) * HD))[tid];
            a.x += v.x; a.y += v.y; a.z += v.z; a.w += v.w;
            cnt++;
        }
    }
    const float c = (float)cnt;
    const int outr = dest[b] * TB + r;
    float4* pp = (float4*)(pooled + (size_t)outr * HD);
    pp[tid] = make_float4(a.x / c, a.y / c, a.z / c, a.w / c);
    if (tid == 0) valid[outr] = 1;
}

// =============================================================================
// Fused score + log_softmax (fp16 mma): single pass, raw store, lse fixup.
// Apm frags persistent: [20ks16][4mi][32][4] u32 = 40KB.
// Bsc per 128x32 chunk:  [2ks16][16ni][32][2] u32 = 8KB.
// =============================================================================
#define SC_APM_W 10240
#define SC_B_W   2048
#define SC_SMEM_BYTES ((SC_APM_W + SC_B_W) * 4 + (256 + 256 + 64) * 4)

__global__ void __launch_bounds__(256, 2) score_hc(
    const float* __restrict__ pm, const float* __restrict__ pd,
    const unsigned char* __restrict__ valid, float* __restrict__ out)
{
    extern __shared__ unsigned smu[];
    unsigned* Apm = smu;
    unsigned* Bsc = smu + SC_APM_W;
    float* partM = (float*)(smu + SC_APM_W + SC_B_W);
    float* partS = partM + 256;
    float* lse   = partS + 256;
    __shared__ int s_any;

    const int tid = threadIdx.x;
    const int m0 = blockIdx.x * 64;
    if (tid == 0) s_any = 0;
    __syncthreads();
    if (tid < 64 && valid[m0 + tid]) s_any = 1;
    __syncthreads();

    float* orow = out + (size_t)m0 * NENT;
    if (!s_any) {
        const float C0 = -7.6246190f;   // -ln(2048)
        const float4 v = make_float4(C0, C0, C0, C0);
        float4* o4 = (float4*)orow;
        for (int i = tid; i < 64 * NENT / 4; i += 256) o4[i] = v;
        return;
    }

    // stage pm band (64 x 320) into fp16 fragments
    {
        const int row = tid >> 2, l4 = tid & 3;
        const float* src = pm + (size_t)(m0 + row) * PPAD;
        const int mi = row >> 4, rr = row & 15, g = rr & 7, rh = rr >> 3;
        for (int c4 = l4; c4 < 80; c4 += 4) {
            const float4 v = *(const float4*)(src + c4 * 4);
            const int ks16 = c4 >> 2, kk = (c4 & 3) * 4;
            const int tig0 = (kk & 7) >> 1, reg = rh + 2 * (kk >> 3);
            const int addr = ((ks16 * 4 + mi) * 32 + g * 4 + tig0) * 4 + reg;
            Apm[addr + 0] = pkh2(v.x, v.y);
            Apm[addr + 4] = pkh2(v.z, v.w);
        }
    }

    const int warp = tid >> 5, lane = tid & 31;
    const int wm = warp & 1;
    const int wn = warp >> 1;
    const int g = lane >> 2, tig = lane & 3;

    int prow[4], pcol4[4], bAddr[4];
#pragma unroll
    for (int i = 0; i < 4; i++) {
        const int idx = tid + 256 * i;
        const int n = idx >> 3, c4 = idx & 7;
        prow[i] = n; pcol4[i] = c4 * 4;
        const int ks16 = c4 >> 2, kk = (c4 & 3) * 4;
        const int p0 = kk >> 1, tig0 = p0 & 3, regb = p0 >> 2;
        bAddr[i] = ((ks16 * 16 + (n >> 3)) * 32 + (n & 7) * 4 + tig0) * 2 + regb;
    }

    float Mr[4] = { -3.0e38f, -3.0e38f, -3.0e38f, -3.0e38f };
    float Sr[4] = { 0.f, 0.f, 0.f, 0.f };
    float acc[2][4][4];
    float4 st[4];

#pragma unroll
    for (int i = 0; i < 4; i++)
        st[i] = *(const float4*)(pd + (size_t)prow[i] * PPAD + pcol4[i]);

    for (int c = 0; c < 160; c++) {
        const int NT = c / 10, kc = c % 10;
        __syncthreads();
#pragma unroll
        for (int i = 0; i < 4; i++) {
            Bsc[bAddr[i] + 0] = pkh2(st[i].x, st[i].y);
            Bsc[bAddr[i] + 2] = pkh2(st[i].z, st[i].w);
        }
        __syncthreads();
        if (c + 1 < 160) {
            const int NT2 = (c + 1) / 10, kc2 = (c + 1) % 10;
#pragma unroll
            for (int i = 0; i < 4; i++)
                st[i] = *(const float4*)(pd + (size_t)(NT2 * 128 + prow[i]) * PPAD
                                         + kc2 * 32 + pcol4[i]);
        }
        if (kc == 0) {
#pragma unroll
            for (int i = 0; i < 2; i++)
#pragma unroll
                for (int j = 0; j < 4; j++)
#pragma unroll
                    for (int r = 0; r < 4; r++) acc[i][j][r] = 0.f;
        }
#pragma unroll
        for (int ks = 0; ks < 2; ks++) {
            const int ksg = kc * 2 + ks;
            uint4 a[2];
#pragma unroll
            for (int mt = 0; mt < 2; mt++)
                a[mt] = *(const uint4*)&Apm[((ksg * 4 + wm * 2 + mt) * 32 + lane) * 4];
#pragma unroll
            for (int nt = 0; nt < 4; nt++) {
                uint2 b = *(const uint2*)&Bsc[((ks * 16 + wn * 4 + nt) * 32 + lane) * 2];
#pragma unroll
                for (int mt = 0; mt < 2; mt++)
                    mma16(acc[mt][nt], (const unsigned*)&a[mt], (const unsigned*)&b);
            }
        }
        if (kc == 9) {
            const int n0 = NT * 128;
#pragma unroll
            for (int mt = 0; mt < 2; mt++)
#pragma unroll
                for (int h = 0; h < 2; h++) {
                    const int s = mt * 2 + h;
                    float v[8];
#pragma unroll
                    for (int j = 0; j < 4; j++) {
                        v[j * 2 + 0] = acc[mt][j][h * 2 + 0];
                        v[j * 2 + 1] = acc[mt][j][h * 2 + 1];
                    }
                    float tm = v[0];
#pragma unroll
                    for (int j = 1; j < 8; j++) tm = fmaxf(tm, v[j]);
                    const float nm = fmaxf(Mr[s], tm);
                    float add = 0.f;
#pragma unroll
                    for (int j = 0; j < 8; j++) add += __expf(v[j] - nm);
                    Sr[s] = Sr[s] * __expf(Mr[s] - nm) + add;
                    Mr[s] = nm;
                }
#pragma unroll
            for (int mt = 0; mt < 2; mt++) {
                const int row = m0 + wm * 32 + mt * 16 + g;
#pragma unroll
                for (int j = 0; j < 4; j++) {
                    const int col = n0 + wn * 32 + j * 8 + tig * 2;
                    *(float2*)(out + (size_t)row * NENT + col) =
                        make_float2(acc[mt][j][0], acc[mt][j][1]);
                    *(float2*)(out + (size_t)(row + 8) * NENT + col) =
                        make_float2(acc[mt][j][2], acc[mt][j][3]);
                }
            }
        }
    }

#pragma unroll
    for (int s = 0; s < 4; s++) {
#pragma unroll
        for (int off = 1; off <= 2; off <<= 1) {
            const float oM = __shfl_xor_sync(0xffffffffu, Mr[s], off);
            const float oS = __shfl_xor_sync(0xffffffffu, Sr[s], off);
            const float nm = fmaxf(Mr[s], oM);
            Sr[s] = Sr[s] * __expf(Mr[s] - nm) + oS * __expf(oM - nm);
            Mr[s] = nm;
        }
    }
    __syncthreads();
    if (tig == 0) {
#pragma unroll
        for (int s = 0; s < 4; s++) {
            const int r = wm * 32 + (s >> 1) * 16 + (s & 1) * 8 + g;
            partM[wn * 64 + r] = Mr[s];
            partS[wn * 64 + r] = Sr[s];
        }
    }
    __syncthreads();
    if (tid < 64) {
        float M = partM[tid];
#pragma unroll
        for (int w = 1; w < 4; w++) M = fmaxf(M, partM[w * 64 + tid]);
        float S = 0.f;
#pragma unroll
        for (int w = 0; w < 4; w++)
            S += partS[w * 64 + tid] * __expf(partM[w * 64 + tid] - M);
        lse[tid] = M + __logf(S);
    }
    __syncthreads();

    float4* o4 = (float4*)orow;
    for (int i = tid; i < 64 * NENT / 4; i += 256) {
        const int r = i >> 9;
        const float cc = lse[r];
        float4 v = o4[i];
        v.x -= cc; v.y -= cc; v.z -= cc; v.w -= cc;
        o4[i] = v;
    }
}

// =============================================================================
extern "C" void kernel_launch(void* const* d_in, const int* in_sizes, int n_in,
                              void* d_out, int out_size)
{
    (void)in_sizes; (void)n_in; (void)out_size;
    const int*   labels = (const int*)d_in[0];
    const float* hidden = (const float*)d_in[1];
    const float* ent    = (const float*)d_in[2];
    const float* W1     = (const float*)d_in[3];
    const float* b1     = (const float*)d_in[4];
    const float* W2     = (const float*)d_in[5];
    const float* b2     = (const float*)d_in[6];
    const float* Wm     = (const float*)d_in[7];
    const float* Wd     = (const float*)d_in[8];

    float* out0 = (float*)d_out;
    float* out1 = out0 + (size_t)MTOK * 3;
    float* out2 = out1 + (size_t)MTOK * NENT;

    float *pH, *pPooled, *pPm, *pPd, *pFixX, *pFixH;
    unsigned char *pV1, *pV2, *pFixV;
    int *pPred, *pNseg, *pDest, *pFixRows, *pNfix;
    unsigned int *pSegse;
    cudaGetSymbolAddress((void**)&pH,      g_H);
    cudaGetSymbolAddress((void**)&pPooled, g_pooled);
    cudaGetSymbolAddress((void**)&pPm,     g_pm);
    cudaGetSymbolAddress((void**)&pPd,     g_pd);
    cudaGetSymbolAddress((void**)&pFixX,   g_fixX);
    cudaGetSymbolAddress((void**)&pFixH,   g_fixH);
    cudaGetSymbolAddress((void**)&pV1,     g_valid1);
    cudaGetSymbolAddress((void**)&pV2,     g_valid2);
    cudaGetSymbolAddress((void**)&pFixV,   g_fixvalid);
    cudaGetSymbolAddress((void**)&pPred,   g_pred);
    cudaGetSymbolAddress((void**)&pNseg,   g_nseg);
    cudaGetSymbolAddress((void**)&pDest,   g_dest);
    cudaGetSymbolAddress((void**)&pFixRows,g_fixrows);
    cudaGetSymbolAddress((void**)&pNfix,   g_nfix);
    cudaGetSymbolAddress((void**)&pSegse,  g_segse);

    const int SMEM_HC    = 6144 * 4;    // 24KB
    const int SMEM_SPLIT = 24576 * 4;   // 96KB
    cudaFuncSetAttribute(gemm_hc<1>, cudaFuncAttributeMaxDynamicSharedMemorySize, SMEM_HC);
    cudaFuncSetAttribute(gemm_hc<0>, cudaFuncAttributeMaxDynamicSharedMemorySize, SMEM_HC);
    cudaFuncSetAttribute(gemm_split, cudaFuncAttributeMaxDynamicSharedMemorySize, SMEM_SPLIT);
    cudaFuncSetAttribute(score_hc, cudaFuncAttributeMaxDynamicSharedMemorySize, SC_SMEM_BYTES);

    cudaMemsetAsync(pNfix, 0, sizeof(int));
    cudaMemsetAsync(pFixV, 0, MAXFIX);
    cudaMemsetAsync(pV1, 0, MTOK);
    cudaMemsetAsync(pV2, 0, MTOK);

    // 1) h = relu(X@W1^T + b1)  fp16 mma (tf32-equivalent mantissa)
    gemm_hc<1><<<dim3(HD / 64, MTOK / 128), 256, SMEM_HC>>>(
        hidden, W1, pH, b1, nullptr, HD, HD, HD, HD, HD, HD);

    // 2) bio head + ambiguity flags
    head_kernel<<<MTOK / 8, 256>>>(pH, W2, b2, out0, pPred, pFixRows, pNfix);

    // 2b) exact recompute of flagged rows (split tf32 ~ fp32)
    gather_fix<<<MAXFIX, 192>>>(hidden, pFixRows, pNfix, pFixX, pFixV);
    gemm_split<<<dim3(HD / 64, MAXFIX / 128), 256, SMEM_SPLIT>>>(
        pFixX, W1, pFixH, b1, pFixV, HD, HD, HD, HD, HD, HD);
    head_fix<<<MAXFIX / 8, 256>>>(pFixH, W2, b2, pFixRows, pNfix, out0, pPred);

    // 3) pd = ent @ Wd^T (cols 300..319 = 0)
    gemm_hc<0><<<dim3(PPAD / 64, NENT / 128), 256, SMEM_HC>>>(
        ent, Wd, pPd, nullptr, nullptr, PPAD, PDIM, HD, HD, HD, PPAD);

    // ---- pass 1: true labels ----
    seg_scan<<<NB, 128>>>(labels, pSegse, pNseg);
    seg_dest<<<1, 32>>>(pNseg, pDest);
    pool_phase2<<<dim3(TB, NB), 192>>>(hidden, labels, pSegse, pNseg, pDest,
                                       pPooled, pV1);
    gemm_hc<0><<<dim3(PPAD / 64, MTOK / 128), 256, SMEM_HC>>>(
        pPooled, Wm, pPm, nullptr, pV1, PPAD, PDIM, HD, HD, HD, PPAD);
    score_hc<<<MTOK / 64, 256, SC_SMEM_BYTES>>>(pPm, pPd, pV1, out1);

    // ---- pass 2: predicted labels ----
    seg_scan<<<NB, 128>>>(pPred, pSegse, pNseg);
    seg_dest<<<1, 32>>>(pNseg, pDest);
    pool_phase2<<<dim3(TB, NB), 192>>>(hidden, pPred, pSegse, pNseg, pDest,
                                       pPooled, pV2);
    gemm_hc<0><<<dim3(PPAD / 64, MTOK / 128), 256, SMEM_HC>>>(
        pPooled, Wm, pPm, nullptr, pV2, PPAD, PDIM, HD, HD, HD, PPAD);
    score_hc<<<MTOK / 64, 256, SC_SMEM_BYTES>>>(pPm, pPd, pV2, out2);
}

// round 14
// speedup vs baseline: 3.3384x; 1.1652x over previous
#include <cuda_runtime.h>
#include <cuda_fp16.h>
#include <cstdint>
#include <cstddef>

#define MTOK 32768      // B*T
#define HD   768
#define NENT 2048
#define PDIM 300
#define PPAD 320
#define PPADB 384       // B-side row padding for pm/pd (3 x 128)
#define TB   512
#define NB   64
#define MAXFIX 4096
#define GAP_THRESH 0.004f

// ---------------- scratch (static device globals; no allocations) ------------
__device__ float g_H[(size_t)MTOK * HD];
__device__ __half g_Xh[(size_t)MTOK * HD];
__device__ __half g_pooledh[(size_t)MTOK * HD];
__device__ __half g_W1h[(size_t)HD * HD];
__device__ __half g_enth[(size_t)NENT * HD];
__device__ __half g_Wmh[(size_t)PPADB * HD];
__device__ __half g_Wdh[(size_t)PPADB * HD];
__device__ float g_pm[(size_t)MTOK * PPAD];
__device__ float g_pd[(size_t)NENT * PPAD];
__device__ float g_fixX[(size_t)MAXFIX * HD];
__device__ float g_fixH[(size_t)MAXFIX * HD];
__device__ unsigned char g_valid1[MTOK];
__device__ unsigned char g_valid2[MTOK];
__device__ unsigned char g_fixvalid[MAXFIX];
__device__ int g_fixrows[MAXFIX];
__device__ int g_nfix;
__device__ int g_pred[MTOK];
__device__ unsigned int g_segse[NB * TB];
__device__ int g_nseg[NB];
__device__ int g_dest[NB];

// ---------------------------------------------------------------------------
__device__ __forceinline__ unsigned f2t(float x) {
    unsigned r;
    asm("cvt.rna.tf32.f32 %0, %1;" : "=r"(r) : "f"(x));
    return r;
}
__device__ __forceinline__ float f2tf(float x) { return __uint_as_float(f2t(x)); }

__device__ __forceinline__ unsigned pkh2(float x, float y) {
    __half2 h = __floats2half2_rn(x, y);   // x -> low half (even k)
    return *reinterpret_cast<unsigned*>(&h);
}

__device__ __forceinline__ void mma8(float* c, const unsigned* a, const unsigned* b) {
    asm volatile(
        "mma.sync.aligned.m16n8k8.row.col.f32.tf32.tf32.f32 "
        "{%0,%1,%2,%3},{%4,%5,%6,%7},{%8,%9},{%0,%1,%2,%3};\n"
        : "+f"(c[0]), "+f"(c[1]), "+f"(c[2]), "+f"(c[3])
        : "r"(a[0]), "r"(a[1]), "r"(a[2]), "r"(a[3]), "r"(b[0]), "r"(b[1]));
}

__device__ __forceinline__ void mma16(float* c, const unsigned* a, const unsigned* b) {
    asm volatile(
        "mma.sync.aligned.m16n8k16.row.col.f32.f16.f16.f32 "
        "{%0,%1,%2,%3},{%4,%5,%6,%7},{%8,%9},{%0,%1,%2,%3};\n"
        : "+f"(c[0]), "+f"(c[1]), "+f"(c[2]), "+f"(c[3])
        : "r"(a[0]), "r"(a[1]), "r"(a[2]), "r"(a[3]), "r"(b[0]), "r"(b[1]));
}

__device__ __forceinline__ uint32_t s2u(const void* p) {
    uint32_t a;
    asm("{ .reg .u64 t; cvta.to.shared.u64 t, %1; cvt.u32.u64 %0, t; }"
        : "=r"(a) : "l"(p));
    return a;
}

#define SWZ128(x) ((x) ^ (((x) >> 3) & 0x70))

__device__ __forceinline__ void ldsm4(uint32_t* r, uint32_t addr) {
    asm volatile(
        "ldmatrix.sync.aligned.m8n8.x4.shared.b16 {%0,%1,%2,%3}, [%4];"
        : "=r"(r[0]), "=r"(r[1]), "=r"(r[2]), "=r"(r[3]) : "r"(addr));
}
__device__ __forceinline__ void cpa16(uint32_t dst, const void* src) {
    asm volatile("cp.async.cg.shared.global [%0], [%1], 16;"
                 :: "r"(dst), "l"(src) : "memory");
}
__device__ __forceinline__ void cpa_commit() {
    asm volatile("cp.async.commit_group;" ::: "memory");
}

// =============================================================================
// cp.async + ldmatrix fp16 GEMM:  C[m,n] = act(sum_k A[m,k]*B[n,k] + bias)
// A,B fp16 row-major (ld = HD), K = HD fixed (12 stages of 64).
// BM=128 BN=128 BK=64, 256 threads, warps 4m x 2n, warp tile 32x64.
// 3-stage cp.async ring, SW128-swizzled 128B rows.
// HASVALID: skip fully-invalid 128-row band; zero C rows with !valid[row].
// =============================================================================
#define GL_ASTG 16384
#define GL_SMEM (3 * 2 * 16384)   // 96KB

template<int RELU, int HASVALID>
__global__ void __launch_bounds__(256) gemm_ld(
    const __half* __restrict__ A, const __half* __restrict__ B,
    float* __restrict__ C, const float* __restrict__ bias,
    const unsigned char* __restrict__ valid, int Nstore, int ldc)
{
    extern __shared__ char smc[];
    const uint32_t sb = s2u(smc);
    __shared__ int s_any;
    const int tid = threadIdx.x;
    const int m0 = blockIdx.y * 128, n0 = blockIdx.x * 128;

    if (HASVALID) {
        if (tid == 0) s_any = 0;
        __syncthreads();
        if (tid < 128 && valid[m0 + tid]) s_any = 1;
        __syncthreads();
        if (!s_any) return;
    }

    const int warp = tid >> 5, lane = tid & 31;
    const int wm = warp & 3;        // m offset wm*32
    const int wn = warp >> 2;       // n offset wn*64

    float acc[2][8][4];
#pragma unroll
    for (int i = 0; i < 2; i++)
#pragma unroll
        for (int j = 0; j < 8; j++)
#pragma unroll
            for (int r = 0; r < 4; r++) acc[i][j][r] = 0.f;

    // cp.async maps: each thread copies 4 A chunks + 4 B chunks (16B each)
    const int crow = tid >> 3, cch = tid & 7;
    const __half* Asrc = A + (size_t)(m0 + crow) * HD + cch * 8;
    const __half* Bsrc = B + (size_t)(n0 + crow) * HD + cch * 8;
    const uint32_t dOff = SWZ128(crow * 128 + cch * 16);

    auto issue = [&](int s) {
        const int buf = s % 3;
        const uint32_t ab = sb + buf * GL_ASTG;
        const uint32_t bb = sb + 49152 + buf * GL_ASTG;
        const __half* as = Asrc + s * 64;
        const __half* bs = Bsrc + s * 64;
#pragma unroll
        for (int i = 0; i < 4; i++)
            cpa16(ab + dOff + i * 4096, as + (size_t)i * 32 * HD);
#pragma unroll
        for (int i = 0; i < 4; i++)
            cpa16(bb + dOff + i * 4096, bs + (size_t)i * 32 * HD);
        cpa_commit();
    };

    issue(0); issue(1);

    const int arow = wm * 32 + (lane & 15);
    const int ach  = (lane >> 4) << 4;
    const int brow = wn * 64 + ((lane >> 4) << 3) + (lane & 7);
    const int bch  = ((lane >> 3) & 1) << 4;

    for (int s = 0; s < 12; s++) {
        if (s < 10) asm volatile("cp.async.wait_group 1;" ::: "memory");
        else        asm volatile("cp.async.wait_group 0;" ::: "memory");
        __syncthreads();
        if (s + 2 < 12) issue(s + 2);
        const int buf = s % 3;
        const uint32_t ab = sb + buf * GL_ASTG;
        const uint32_t bb = sb + 49152 + buf * GL_ASTG;
#pragma unroll
        for (int ks = 0; ks < 4; ks++) {
            uint32_t af[2][4];
#pragma unroll
            for (int mt = 0; mt < 2; mt++)
                ldsm4(af[mt], ab + SWZ128((arow + mt * 16) * 128 + ks * 32 + ach));
            uint32_t bf[4][4];
#pragma unroll
            for (int np = 0; np < 4; np++)
                ldsm4(bf[np], bb + SWZ128((brow + np * 16) * 128 + ks * 32 + bch));
#pragma unroll
            for (int nt = 0; nt < 8; nt++) {
                const unsigned* bp = &bf[nt >> 1][(nt & 1) * 2];
#pragma unroll
                for (int mt = 0; mt < 2; mt++)
                    mma16(acc[mt][nt], af[mt], bp);
            }
        }
    }

    // epilogue
    const int g = lane >> 2, tig = lane & 3;
#pragma unroll
    for (int mt = 0; mt < 2; mt++) {
        const int row = m0 + wm * 32 + mt * 16 + g;
        bool v0 = true, v1 = true;
        if (HASVALID) { v0 = valid[row] != 0; v1 = valid[row + 8] != 0; }
#pragma unroll
        for (int nt = 0; nt < 8; nt++) {
            const int col = n0 + wn * 64 + nt * 8 + tig * 2;
            if (col < Nstore) {
                float a0 = acc[mt][nt][0], a1 = acc[mt][nt][1];
                float a2 = acc[mt][nt][2], a3 = acc[mt][nt][3];
                if (bias) {
                    const float b0 = bias[col], b1 = bias[col + 1];
                    a0 += b0; a1 += b1; a2 += b0; a3 += b1;
                }
                if (RELU) {
                    a0 = fmaxf(a0, 0.f); a1 = fmaxf(a1, 0.f);
                    a2 = fmaxf(a2, 0.f); a3 = fmaxf(a3, 0.f);
                }
                if (HASVALID) {
                    if (!v0) { a0 = 0.f; a1 = 0.f; }
                    if (!v1) { a2 = 0.f; a3 = 0.f; }
                }
                *(float2*)(C + (size_t)row * ldc + col) = make_float2(a0, a1);
                *(float2*)(C + (size_t)(row + 8) * ldc + col) = make_float2(a2, a3);
            }
        }
    }
}

// =============================================================================
// fp32 -> fp16 conversion kernels
// =============================================================================
__global__ void cvt_half_k(const float* __restrict__ s, __half* __restrict__ d, int n8)
{
    for (int i = blockIdx.x * blockDim.x + threadIdx.x; i < n8;
         i += gridDim.x * blockDim.x) {
        const float4 a = ((const float4*)s)[i * 2];
        const float4 b = ((const float4*)s)[i * 2 + 1];
        ((uint4*)d)[i] = make_uint4(pkh2(a.x, a.y), pkh2(a.z, a.w),
                                    pkh2(b.x, b.y), pkh2(b.z, b.w));
    }
}

// Wm/Wd [300][768] -> [384][768] fp16, rows 300..383 zero
__global__ void cvt_pad_k(const float* __restrict__ s, __half* __restrict__ d)
{
    const int i = blockIdx.x * blockDim.x + threadIdx.x;
    if (i >= PPADB * HD / 8) return;
    const int row = (i * 8) / HD;
    uint4 v = make_uint4(0u, 0u, 0u, 0u);
    if (row < PDIM) {
        const float4 a = ((const float4*)s)[i * 2];
        const float4 b = ((const float4*)s)[i * 2 + 1];
        v = make_uint4(pkh2(a.x, a.y), pkh2(a.z, a.w),
                       pkh2(b.x, b.y), pkh2(b.z, b.w));
    }
    ((uint4*)d)[i] = v;
}

// =============================================================================
// Split-tf32 GEMM (exact path for flagged rows) — unchanged
// =============================================================================
__global__ void __launch_bounds__(256, 2) gemm_split(
    const float* __restrict__ A, const float* __restrict__ B,
    float* __restrict__ C, const float* __restrict__ bias,
    const unsigned char* __restrict__ valid,
    int Nstore, int NloadB, int K, int lda, int ldb, int ldc)
{
    extern __shared__ float sm[];
    float* AH = sm;
    float* BH = sm + 8192;
    float* AL = sm + 12288;
    float* BL = sm + 20480;
    __shared__ int s_any;

    const int tid = threadIdx.x;
    const int m0 = blockIdx.y * 128;
    const int n0 = blockIdx.x * 64;

    if (valid != nullptr) {
        if (tid == 0) s_any = 0;
        __syncthreads();
        if (tid < 128 && valid[m0 + tid]) s_any = 1;
        __syncthreads();
        if (!s_any) return;
    }

    const int warp = tid >> 5, lane = tid & 31;
    const int wm = warp & 3;
    const int wn = warp >> 2;

    float acc[2][4][4];
#pragma unroll
    for (int i = 0; i < 2; i++)
#pragma unroll
        for (int j = 0; j < 4; j++)
#pragma unroll
            for (int r = 0; r < 4; r++) acc[i][j][r] = 0.f;

    int aBase[4]; const float* Ap[4];
#pragma unroll
    for (int i = 0; i < 4; i++) {
        const int idx = tid + 256 * i;
        const int r = idx >> 3, c4 = idx & 7;
        const int ks = c4 >> 1, khi = c4 & 1, mi = r >> 4, rr = r & 15;
        aBase[i] = ((ks * 8 + mi) * 32 + (rr & 7) * 4) * 4 + (rr >> 3) + (khi << 1);
        Ap[i] = A + (size_t)(m0 + r) * lda + c4 * 4;
    }
    int bBase[2]; const float* Bp[2]; bool bok[2];
#pragma unroll
    for (int i = 0; i < 2; i++) {
        const int idx = tid + 256 * i;
        const int n = idx >> 3, c4 = idx & 7;
        const int ks = c4 >> 1, khi = c4 & 1;
        bBase[i] = ((ks * 8 + (n >> 3)) * 32 + (n & 7) * 4) * 2 + khi;
        bok[i] = (n0 + n) < NloadB;
        Bp[i] = B + (size_t)(n0 + n) * ldb + c4 * 4;
    }

    const float4 z4 = make_float4(0.f, 0.f, 0.f, 0.f);
    float4 ar[4], br[2];

    auto stage = [&](int buf) {
        const int ao = buf * 4096, bo = buf * 2048;
#pragma unroll
        for (int i = 0; i < 4; i++) {
            const float h0 = f2tf(ar[i].x), h1 = f2tf(ar[i].y);
            const float h2 = f2tf(ar[i].z), h3 = f2tf(ar[i].w);
            AH[ao + aBase[i] + 0]  = h0; AH[ao + aBase[i] + 4]  = h1;
            AH[ao + aBase[i] + 8]  = h2; AH[ao + aBase[i] + 12] = h3;
            AL[ao + aBase[i] + 0]  = f2tf(ar[i].x - h0);
            AL[ao + aBase[i] + 4]  = f2tf(ar[i].y - h1);
            AL[ao + aBase[i] + 8]  = f2tf(ar[i].z - h2);
            AL[ao + aBase[i] + 12] = f2tf(ar[i].w - h3);
        }
#pragma unroll
        for (int i = 0; i < 2; i++) {
            const float h0 = f2tf(br[i].x), h1 = f2tf(br[i].y);
            const float h2 = f2tf(br[i].z), h3 = f2tf(br[i].w);
            BH[bo + bBase[i] + 0] = h0; BH[bo + bBase[i] + 2] = h1;
            BH[bo + bBase[i] + 4] = h2; BH[bo + bBase[i] + 6] = h3;
            BL[bo + bBase[i] + 0] = f2tf(br[i].x - h0);
            BL[bo + bBase[i] + 2] = f2tf(br[i].y - h1);
            BL[bo + bBase[i] + 4] = f2tf(br[i].z - h2);
            BL[bo + bBase[i] + 6] = f2tf(br[i].w - h3);
        }
    };

#pragma unroll
    for (int i = 0; i < 4; i++) ar[i] = *(const float4*)Ap[i];
#pragma unroll
    for (int i = 0; i < 2; i++) br[i] = bok[i] ? *(const float4*)Bp[i] : z4;
    stage(0);
    int cur = 0;

    const int nk = K / 32;
    for (int kt = 0; kt < nk; kt++) {
        if (kt + 1 < nk) {
            const int ko = (kt + 1) * 32;
#pragma unroll
            for (int i = 0; i < 4; i++) ar[i] = *(const float4*)(Ap[i] + ko);
#pragma unroll
            for (int i = 0; i < 2; i++) br[i] = bok[i] ? *(const float4*)(Bp[i] + ko) : z4;
        }
        __syncthreads();
        const int ao = cur * 4096, bo = cur * 2048;
#pragma unroll
        for (int ks = 0; ks < 4; ks++) {
            float4 ah[2], al[2];
#pragma unroll
            for (int mt = 0; mt < 2; mt++) {
                const int off = ((ks * 8 + wm * 2 + mt) * 32 + lane) * 4;
                ah[mt] = *(const float4*)&AH[ao + off];
                al[mt] = *(const float4*)&AL[ao + off];
            }
#pragma unroll
            for (int nt = 0; nt < 4; nt++) {
                const int off = ((ks * 8 + wn * 4 + nt) * 32 + lane) * 2;
                float2 bh = *(const float2*)&BH[bo + off];
                float2 bl = *(const float2*)&BL[bo + off];
#pragma unroll
                for (int mt = 0; mt < 2; mt++) {
                    mma8(acc[mt][nt], (const unsigned*)&ah[mt], (const unsigned*)&bh);
                    mma8(acc[mt][nt], (const unsigned*)&ah[mt], (const unsigned*)&bl);
                    mma8(acc[mt][nt], (const unsigned*)&al[mt], (const unsigned*)&bh);
                }
            }
        }
        if (kt + 1 < nk) { stage(cur ^ 1); cur ^= 1; }
    }

    const int g = lane >> 2, tig = lane & 3;
#pragma unroll
    for (int mt = 0; mt < 2; mt++) {
        const int row = m0 + wm * 32 + mt * 16 + g;
        bool v0 = true, v1 = true;
        if (valid != nullptr) { v0 = valid[row] != 0; v1 = valid[row + 8] != 0; }
#pragma unroll
        for (int nt = 0; nt < 4; nt++) {
            const int col = n0 + wn * 32 + nt * 8 + tig * 2;
            if (col < Nstore) {
                float a0 = acc[mt][nt][0], a1 = acc[mt][nt][1];
                float a2 = acc[mt][nt][2], a3 = acc[mt][nt][3];
                if (bias) {
                    const float b0 = bias[col], b1 = bias[col + 1];
                    a0 += b0; a1 += b1; a2 += b0; a3 += b1;
                }
                a0 = fmaxf(a0, 0.f); a1 = fmaxf(a1, 0.f);
                a2 = fmaxf(a2, 0.f); a3 = fmaxf(a3, 0.f);
                if (!v0) { a0 = 0.f; a1 = 0.f; }
                if (!v1) { a2 = 0.f; a3 = 0.f; }
                *(float2*)(C + (size_t)row * ldc + col) = make_float2(a0, a1);
                *(float2*)(C + (size_t)(row + 8) * ldc + col) = make_float2(a2, a3);
            }
        }
    }
}

// =============================================================================
// Bio head + ambiguity flags
// =============================================================================
__global__ void __launch_bounds__(256) head_kernel(
    const float* __restrict__ Hb, const float* __restrict__ W2,
    const float* __restrict__ b2, float* __restrict__ out0,
    int* __restrict__ pred, int* __restrict__ fixrows, int* __restrict__ nfix)
{
    __shared__ float w2s[3 * HD];
    __shared__ float b2s[3];
    const int tid = threadIdx.x;
    for (int i = tid; i < 3 * HD; i += 256) w2s[i] = W2[i];
    if (tid < 3) b2s[tid] = b2[tid];
    __syncthreads();

    const int warp = tid >> 5, lane = tid & 31;
    const int row = blockIdx.x * 8 + warp;
    const float* hr = Hb + (size_t)row * HD;
    float d0 = 0.f, d1 = 0.f, d2 = 0.f;
#pragma unroll
    for (int q = 0; q < 6; q++) {
        const int off = q * 128 + lane * 4;
        const float4 h  = *(const float4*)(hr + off);
        const float4 w0 = *(const float4*)(w2s + 0 * HD + off);
        const float4 w1 = *(const float4*)(w2s + 1 * HD + off);
        const float4 w2v = *(const float4*)(w2s + 2 * HD + off);
        d0 += h.x * w0.x + h.y * w0.y + h.z * w0.z + h.w * w0.w;
        d1 += h.x * w1.x + h.y * w1.y + h.z * w1.z + h.w * w1.w;
        d2 += h.x * w2v.x + h.y * w2v.y + h.z * w2v.z + h.w * w2v.w;
    }
#pragma unroll
    for (int o = 16; o >= 1; o >>= 1) {
        d0 += __shfl_xor_sync(0xffffffffu, d0, o);
        d1 += __shfl_xor_sync(0xffffffffu, d1, o);
        d2 += __shfl_xor_sync(0xffffffffu, d2, o);
    }
    if (lane == 0) {
        const float l0 = d0 + b2s[0], l1 = d1 + b2s[1], l2 = d2 + b2s[2];
        const float m = fmaxf(l0, fmaxf(l1, l2));
        const float s = __expf(l0 - m) + __expf(l1 - m) + __expf(l2 - m);
        const float lse = m + __logf(s);
        out0[row * 3 + 0] = l0 - lse;
        out0[row * 3 + 1] = l1 - lse;
        out0[row * 3 + 2] = l2 - lse;
        int p = 0; float bst = l0, sec;
        if (l1 > bst) { sec = bst; bst = l1; p = 1; } else sec = l1;
        if (l2 > bst) { sec = bst; bst = l2; p = 2; }
        else if (l2 > sec) sec = l2;
        pred[row] = p;
        if (bst - sec < GAP_THRESH) {
            const int ix = atomicAdd(nfix, 1);
            if (ix < MAXFIX) fixrows[ix] = row;
        }
    }
}

__global__ void gather_fix(const float* __restrict__ hidden,
                           const int* __restrict__ fixrows,
                           const int* __restrict__ nfix,
                           float* __restrict__ fixX,
                           unsigned char* __restrict__ fixvalid)
{
    const int b = blockIdx.x;
    int n = *nfix; if (n > MAXFIX) n = MAXFIX;
    if (b >= n) return;
    const int row = fixrows[b];
    const float4* src = (const float4*)(hidden + (size_t)row * HD);
    float4* dst = (float4*)(fixX + (size_t)b * HD);
    if (threadIdx.x < 192) dst[threadIdx.x] = src[threadIdx.x];
    if (threadIdx.x == 0) fixvalid[b] = 1;
}

__global__ void __launch_bounds__(256) head_fix(
    const float* __restrict__ Hf, const float* __restrict__ W2,
    const float* __restrict__ b2, const int* __restrict__ fixrows,
    const int* __restrict__ nfix, float* __restrict__ out0,
    int* __restrict__ pred)
{
    __shared__ float w2s[3 * HD];
    __shared__ float b2s[3];
    const int tid = threadIdx.x;
    int n = *nfix; if (n > MAXFIX) n = MAXFIX;
    if (blockIdx.x * 8 >= n) return;
    for (int i = tid; i < 3 * HD; i += 256) w2s[i] = W2[i];
    if (tid < 3) b2s[tid] = b2[tid];
    __syncthreads();

    const int warp = tid >> 5, lane = tid & 31;
    const int slot = blockIdx.x * 8 + warp;
    if (slot >= n) return;
    const int row = fixrows[slot];
    const float* hr = Hf + (size_t)slot * HD;
    float d0 = 0.f, d1 = 0.f, d2 = 0.f;
#pragma unroll
    for (int q = 0; q < 6; q++) {
        const int off = q * 128 + lane * 4;
        const float4 h  = *(const float4*)(hr + off);
        const float4 w0 = *(const float4*)(w2s + 0 * HD + off);
        const float4 w1 = *(const float4*)(w2s + 1 * HD + off);
        const float4 w2v = *(const float4*)(w2s + 2 * HD + off);
        d0 += h.x * w0.x + h.y * w0.y + h.z * w0.z + h.w * w0.w;
        d1 += h.x * w1.x + h.y * w1.y + h.z * w1.z + h.w * w1.w;
        d2 += h.x * w2v.x + h.y * w2v.y + h.z * w2v.z + h.w * w2v.w;
    }
#pragma unroll
    for (int o = 16; o >= 1; o >>= 1) {
        d0 += __shfl_xor_sync(0xffffffffu, d0, o);
        d1 += __shfl_xor_sync(0xffffffffu, d1, o);
        d2 += __shfl_xor_sync(0xffffffffu, d2, o);
    }
    if (lane == 0) {
        const float l0 = d0 + b2s[0], l1 = d1 + b2s[1], l2 = d2 + b2s[2];
        const float m = fmaxf(l0, fmaxf(l1, l2));
        const float s = __expf(l0 - m) + __expf(l1 - m) + __expf(l2 - m);
        const float lse = m + __logf(s);
        out0[row * 3 + 0] = l0 - lse;
        out0[row * 3 + 1] = l1 - lse;
        out0[row * 3 + 2] = l2 - lse;
        int p = 0; float bst = l0;
        if (l1 > bst) { bst = l1; p = 1; }
        if (l2 > bst) { p = 2; }
        pred[row] = p;
    }
}

// =============================================================================
// Segment scan + dest + pool (pool writes fp16 directly)
// =============================================================================
__global__ void seg_scan(const int* __restrict__ lab,
                         unsigned int* __restrict__ segse, int* __restrict__ nseg)
{
    __shared__ int L[TB];
    const int b = blockIdx.x;
    for (int i = threadIdx.x; i < TB; i += blockDim.x) L[i] = lab[b * TB + i];
    __syncthreads();
    if (threadIdx.x == 0) {
        int ns = 0, start = 0, count = 0;
#pragma unroll 8
        for (int t = 0; t < TB; t++) {
            const int l = L[t];
            if (l == 1) {
                if (count > 0)
                    segse[b * TB + ns++] = (unsigned)start | ((unsigned)t << 16);
                start = t; count = 1;
            } else if (l != 0) {
                count++;
            }
        }
        if (count > 0)
            segse[b * TB + ns++] = (unsigned)start | ((unsigned)TB << 16);
        nseg[b] = ns;
    }
}

__global__ void seg_dest(const int* __restrict__ nseg, int* __restrict__ dest)
{
    if (threadIdx.x == 0) {
        int p = 0;
        for (int i = 0; i < NB; i++) dest[i] = (nseg[i] > 0) ? p++ : -1;
    }
}

__global__ void __launch_bounds__(192) pool_phase2(
    const float* __restrict__ hidden, const int* __restrict__ lab,
    const unsigned int* __restrict__ segse, const int* __restrict__ nseg,
    const int* __restrict__ dest, __half* __restrict__ pooledh,
    unsigned char* __restrict__ valid)
{
    const int b = blockIdx.y, r = blockIdx.x;
    if (r >= nseg[b]) return;
    const unsigned se = segse[b * TB + r];
    const int start = (int)(se & 0xffffu), end = (int)(se >> 16);
    const int tid = threadIdx.x;
    float4 a = make_float4(0.f, 0.f, 0.f, 0.f);
    int cnt = 0;
    for (int t = start; t < end; t++) {
        const int l = lab[b * TB + t];
        if (l != 0) {
            const float4 v = ((const float4*)(hidden + (size_t)(b * TB + t) * HD))[tid];
            a.x += v.x; a.y += v.y; a.z += v.z; a.w += v.w;
            cnt++;
        }
    }
    const float c = (float)cnt;
    const int outr = dest[b] * TB + r;
    uint2 w = make_uint2(pkh2(a.x / c, a.y / c), pkh2(a.z / c, a.w / c));
    ((uint2*)(pooledh + (size_t)outr * HD))[tid] = w;
    if (tid == 0) valid[outr] = 1;
}

// =============================================================================
// Fused score + log_softmax (fp16 mma): single pass, raw store, lse fixup.
// (unchanged from R10)
// =============================================================================
#define SC_APM_W 10240
#define SC_B_W   2048
#define SC_SMEM_BYTES ((SC_APM_W + SC_B_W) * 4 + (256 + 256 + 64) * 4)

__global__ void __launch_bounds__(256, 2) score_hc(
    const float* __restrict__ pm, const float* __restrict__ pd,
    const unsigned char* __restrict__ valid, float* __restrict__ out)
{
    extern __shared__ unsigned smu[];
    unsigned* Apm = smu;
    unsigned* Bsc = smu + SC_APM_W;
    float* partM = (float*)(smu + SC_APM_W + SC_B_W);
    float* partS = partM + 256;
    float* lse   = partS + 256;
    __shared__ int s_any;

    const int tid = threadIdx.x;
    const int m0 = blockIdx.x * 64;
    if (tid == 0) s_any = 0;
    __syncthreads();
    if (tid < 64 && valid[m0 + tid]) s_any = 1;
    __syncthreads();

    float* orow = out + (size_t)m0 * NENT;
    if (!s_any) {
        const float C0 = -7.6246190f;   // -ln(2048)
        const float4 v = make_float4(C0, C0, C0, C0);
        float4* o4 = (float4*)orow;
        for (int i = tid; i < 64 * NENT / 4; i += 256) o4[i] = v;
        return;
    }

    {
        const int row = tid >> 2, l4 = tid & 3;
        const float* src = pm + (size_t)(m0 + row) * PPAD;
        const int mi = row >> 4, rr = row & 15, g = rr & 7, rh = rr >> 3;
        for (int c4 = l4; c4 < 80; c4 += 4) {
            const float4 v = *(const float4*)(src + c4 * 4);
            const int ks16 = c4 >> 2, kk = (c4 & 3) * 4;
            const int tig0 = (kk & 7) >> 1, reg = rh + 2 * (kk >> 3);
            const int addr = ((ks16 * 4 + mi) * 32 + g * 4 + tig0) * 4 + reg;
            Apm[addr + 0] = pkh2(v.x, v.y);
            Apm[addr + 4] = pkh2(v.z, v.w);
        }
    }

    const int warp = tid >> 5, lane = tid & 31;
    const int wm = warp & 1;
    const int wn = warp >> 1;
    const int g = lane >> 2, tig = lane & 3;

    int prow[4], pcol4[4], bAddr[4];
#pragma unroll
    for (int i = 0; i < 4; i++) {
        const int idx = tid + 256 * i;
        const int n = idx >> 3, c4 = idx & 7;
        prow[i] = n; pcol4[i] = c4 * 4;
        const int ks16 = c4 >> 2, kk = (c4 & 3) * 4;
        const int p0 = kk >> 1, tig0 = p0 & 3, regb = p0 >> 2;
        bAddr[i] = ((ks16 * 16 + (n >> 3)) * 32 + (n & 7) * 4 + tig0) * 2 + regb;
    }

    float Mr[4] = { -3.0e38f, -3.0e38f, -3.0e38f, -3.0e38f };
    float Sr[4] = { 0.f, 0.f, 0.f, 0.f };
    float acc[2][4][4];
    float4 st[4];

#pragma unroll
    for (int i = 0; i < 4; i++)
        st[i] = *(const float4*)(pd + (size_t)prow[i] * PPAD + pcol4[i]);

    for (int c = 0; c < 160; c++) {
        const int NT = c / 10, kc = c % 10;
        __syncthreads();
#pragma unroll
        for (int i = 0; i < 4; i++) {
            Bsc[bAddr[i] + 0] = pkh2(st[i].x, st[i].y);
            Bsc[bAddr[i] + 2] = pkh2(st[i].z, st[i].w);
        }
        __syncthreads();
        if (c + 1 < 160) {
            const int NT2 = (c + 1) / 10, kc2 = (c + 1) % 10;
#pragma unroll
            for (int i = 0; i < 4; i++)
                st[i] = *(const float4*)(pd + (size_t)(NT2 * 128 + prow[i]) * PPAD
                                         + kc2 * 32 + pcol4[i]);
        }
        if (kc == 0) {
#pragma unroll
            for (int i = 0; i < 2; i++)
#pragma unroll
                for (int j = 0; j < 4; j++)
#pragma unroll
                    for (int r = 0; r < 4; r++) acc[i][j][r] = 0.f;
        }
#pragma unroll
        for (int ks = 0; ks < 2; ks++) {
            const int ksg = kc * 2 + ks;
            uint4 a[2];
#pragma unroll
            for (int mt = 0; mt < 2; mt++)
                a[mt] = *(const uint4*)&Apm[((ksg * 4 + wm * 2 + mt) * 32 + lane) * 4];
#pragma unroll
            for (int nt = 0; nt < 4; nt++) {
                uint2 b = *(const uint2*)&Bsc[((ks * 16 + wn * 4 + nt) * 32 + lane) * 2];
#pragma unroll
                for (int mt = 0; mt < 2; mt++)
                    mma16(acc[mt][nt], (const unsigned*)&a[mt], (const unsigned*)&b);
            }
        }
        if (kc == 9) {
            const int n0 = NT * 128;
#pragma unroll
            for (int mt = 0; mt < 2; mt++)
#pragma unroll
                for (int h = 0; h < 2; h++) {
                    const int s = mt * 2 + h;
                    float v[8];
#pragma unroll
                    for (int j = 0; j < 4; j++) {
                        v[j * 2 + 0] = acc[mt][j][h * 2 + 0];
                        v[j * 2 + 1] = acc[mt][j][h * 2 + 1];
                    }
                    float tm = v[0];
#pragma unroll
                    for (int j = 1; j < 8; j++) tm = fmaxf(tm, v[j]);
                    const float nm = fmaxf(Mr[s], tm);
                    float add = 0.f;
#pragma unroll
                    for (int j = 0; j < 8; j++) add += __expf(v[j] - nm);
                    Sr[s] = Sr[s] * __expf(Mr[s] - nm) + add;
                    Mr[s] = nm;
                }
#pragma unroll
            for (int mt = 0; mt < 2; mt++) {
                const int row = m0 + wm * 32 + mt * 16 + g;
#pragma unroll
                for (int j = 0; j < 4; j++) {
                    const int col = n0 + wn * 32 + j * 8 + tig * 2;
                    *(float2*)(out + (size_t)row * NENT + col) =
                        make_float2(acc[mt][j][0], acc[mt][j][1]);
                    *(float2*)(out + (size_t)(row + 8) * NENT + col) =
                        make_float2(acc[mt][j][2], acc[mt][j][3]);
                }
            }
        }
    }

#pragma unroll
    for (int s = 0; s < 4; s++) {
#pragma unroll
        for (int off = 1; off <= 2; off <<= 1) {
            const float oM = __shfl_xor_sync(0xffffffffu, Mr[s], off);
            const float oS = __shfl_xor_sync(0xffffffffu, Sr[s], off);
            const float nm = fmaxf(Mr[s], oM);
            Sr[s] = Sr[s] * __expf(Mr[s] - nm) + oS * __expf(oM - nm);
            Mr[s] = nm;
        }
    }
    __syncthreads();
    if (tig == 0) {
#pragma unroll
        for (int s = 0; s < 4; s++) {
            const int r = wm * 32 + (s >> 1) * 16 + (s & 1) * 8 + g;
            partM[wn * 64 + r] = Mr[s];
            partS[wn * 64 + r] = Sr[s];
        }
    }
    __syncthreads();
    if (tid < 64) {
        float M = partM[tid];
#pragma unroll
        for (int w = 1; w < 4; w++) M = fmaxf(M, partM[w * 64 + tid]);
        float S = 0.f;
#pragma unroll
        for (int w = 0; w < 4; w++)
            S += partS[w * 64 + tid] * __expf(partM[w * 64 + tid] - M);
        lse[tid] = M + __logf(S);
    }
    __syncthreads();

    float4* o4 = (float4*)orow;
    for (int i = tid; i < 64 * NENT / 4; i += 256) {
        const int r = i >> 9;
        const float cc = lse[r];
        float4 v = o4[i];
        v.x -= cc; v.y -= cc; v.z -= cc; v.w -= cc;
        o4[i] = v;
    }
}

// =============================================================================
extern "C" void kernel_launch(void* const* d_in, const int* in_sizes, int n_in,
                              void* d_out, int out_size)
{
    (void)in_sizes; (void)n_in; (void)out_size;
    const int*   labels = (const int*)d_in[0];
    const float* hidden = (const float*)d_in[1];
    const float* ent    = (const float*)d_in[2];
    const float* W1     = (const float*)d_in[3];
    const float* b1     = (const float*)d_in[4];
    const float* W2     = (const float*)d_in[5];
    const float* b2     = (const float*)d_in[6];
    const float* Wm     = (const float*)d_in[7];
    const float* Wd     = (const float*)d_in[8];

    float* out0 = (float*)d_out;
    float* out1 = out0 + (size_t)MTOK * 3;
    float* out2 = out1 + (size_t)MTOK * NENT;

    float *pH, *pPm, *pPd, *pFixX, *pFixH;
    __half *pXh, *pPooledh, *pW1h, *pEnth, *pWmh, *pWdh;
    unsigned char *pV1, *pV2, *pFixV;
    int *pPred, *pNseg, *pDest, *pFixRows, *pNfix;
    unsigned int *pSegse;
    cudaGetSymbolAddress((void**)&pH,      g_H);
    cudaGetSymbolAddress((void**)&pXh,     g_Xh);
    cudaGetSymbolAddress((void**)&pPooledh,g_pooledh);
    cudaGetSymbolAddress((void**)&pW1h,    g_W1h);
    cudaGetSymbolAddress((void**)&pEnth,   g_enth);
    cudaGetSymbolAddress((void**)&pWmh,    g_Wmh);
    cudaGetSymbolAddress((void**)&pWdh,    g_Wdh);
    cudaGetSymbolAddress((void**)&pPm,     g_pm);
    cudaGetSymbolAddress((void**)&pPd,     g_pd);
    cudaGetSymbolAddress((void**)&pFixX,   g_fixX);
    cudaGetSymbolAddress((void**)&pFixH,   g_fixH);
    cudaGetSymbolAddress((void**)&pV1,     g_valid1);
    cudaGetSymbolAddress((void**)&pV2,     g_valid2);
    cudaGetSymbolAddress((void**)&pFixV,   g_fixvalid);
    cudaGetSymbolAddress((void**)&pPred,   g_pred);
    cudaGetSymbolAddress((void**)&pNseg,   g_nseg);
    cudaGetSymbolAddress((void**)&pDest,   g_dest);
    cudaGetSymbolAddress((void**)&pFixRows,g_fixrows);
    cudaGetSymbolAddress((void**)&pNfix,   g_nfix);
    cudaGetSymbolAddress((void**)&pSegse,  g_segse);

    const int SMEM_SPLIT = 24576 * 4;   // 96KB
    cudaFuncSetAttribute(gemm_ld<1, 0>, cudaFuncAttributeMaxDynamicSharedMemorySize, GL_SMEM);
    cudaFuncSetAttribute(gemm_ld<0, 0>, cudaFuncAttributeMaxDynamicSharedMemorySize, GL_SMEM);
    cudaFuncSetAttribute(gemm_ld<0, 1>, cudaFuncAttributeMaxDynamicSharedMemorySize, GL_SMEM);
    cudaFuncSetAttribute(gemm_split, cudaFuncAttributeMaxDynamicSharedMemorySize, SMEM_SPLIT);
    cudaFuncSetAttribute(score_hc, cudaFuncAttributeMaxDynamicSharedMemorySize, SC_SMEM_BYTES);

    cudaMemsetAsync(pNfix, 0, sizeof(int));
    cudaMemsetAsync(pFixV, 0, MAXFIX);
    cudaMemsetAsync(pV1, 0, MTOK);
    cudaMemsetAsync(pV2, 0, MTOK);

    // 0) fp32 -> fp16 conversions (once)
    cvt_half_k<<<3072, 256>>>(hidden, pXh, MTOK * HD / 8);
    cvt_half_k<<<288, 256>>>(W1, pW1h, HD * HD / 8);
    cvt_half_k<<<768, 256>>>(ent, pEnth, NENT * HD / 8);
    cvt_pad_k<<<(PPADB * HD / 8 + 255) / 256, 256>>>(Wm, pWmh);
    cvt_pad_k<<<(PPADB * HD / 8 + 255) / 256, 256>>>(Wd, pWdh);

    // 1) h = relu(X@W1^T + b1) — cp.async + ldmatrix fp16 pipeline
    gemm_ld<1, 0><<<dim3(HD / 128, MTOK / 128), 256, GL_SMEM>>>(
        pXh, pW1h, pH, b1, nullptr, HD, HD);

    // 2) bio head + ambiguity flags
    head_kernel<<<MTOK / 8, 256>>>(pH, W2, b2, out0, pPred, pFixRows, pNfix);

    // 2b) exact recompute of flagged rows (split tf32 ~ fp32)
    gather_fix<<<MAXFIX, 192>>>(hidden, pFixRows, pNfix, pFixX, pFixV);
    gemm_split<<<dim3(HD / 64, MAXFIX / 128), 256, SMEM_SPLIT>>>(
        pFixX, W1, pFixH, b1, pFixV, HD, HD, HD, HD, HD, HD);
    head_fix<<<MAXFIX / 8, 256>>>(pFixH, W2, b2, pFixRows, pNfix, out0, pPred);

    // 3) pd = ent @ Wd^T (Wdh rows 300..383 zero -> pd cols 300..319 zero)
    gemm_ld<0, 0><<<dim3(PPADB / 128, NENT / 128), 256, GL_SMEM>>>(
        pEnth, pWdh, pPd, nullptr, nullptr, PPAD, PPAD);

    // ---- pass 1: true labels ----
    seg_scan<<<NB, 128>>>(labels, pSegse, pNseg);
    seg_dest<<<1, 32>>>(pNseg, pDest);
    pool_phase2<<<dim3(TB, NB), 192>>>(hidden, labels, pSegse, pNseg, pDest,
                                       pPooledh, pV1);
    gemm_ld<0, 1><<<dim3(PPADB / 128, MTOK / 128), 256, GL_SMEM>>>(
        pPooledh, pWmh, pPm, nullptr, pV1, PPAD, PPAD);
    score_hc<<<MTOK / 64, 256, SC_SMEM_BYTES>>>(pPm, pPd, pV1, out1);

    // ---- pass 2: predicted labels ----
    seg_scan<<<NB, 128>>>(pPred, pSegse, pNseg);
    seg_dest<<<1, 32>>>(pNseg, pDest);
    pool_phase2<<<dim3(TB, NB), 192>>>(hidden, pPred, pSegse, pNseg, pDest,
                                       pPooledh, pV2);
    gemm_ld<0, 1><<<dim3(PPADB / 128, MTOK / 128), 256, GL_SMEM>>>(
        pPooledh, pWmh, pPm, nullptr, pV2, PPAD, PPAD);
    score_hc<<<MTOK / 64, 256, SC_SMEM_BYTES>>>(pPm, pPd, pV2, out2);
}

// round 15
// speedup vs baseline: 3.6586x; 1.0959x over previous
#include <cuda_runtime.h>
#include <cuda_fp16.h>
#include <cstdint>
#include <cstddef>

#define MTOK 32768      // B*T
#define HD   768
#define NENT 2048
#define PDIM 300
#define PPAD 320
#define PPADB 384       // padded P for fp16 buffers (3 x 128)
#define TB   512
#define NB   64
#define MAXFIX 4096
#define GAP_THRESH 0.0015f

// ---------------- scratch (static device globals; no allocations) ------------
__device__ float g_H[(size_t)MTOK * HD];
__device__ __half g_Xh[(size_t)MTOK * HD];
__device__ __half g_pooledh[(size_t)MTOK * HD];
__device__ __half g_W1h[(size_t)HD * HD];
__device__ __half g_enth[(size_t)NENT * HD];
__device__ __half g_Wmh[(size_t)PPADB * HD];
__device__ __half g_Wdh[(size_t)PPADB * HD];
__device__ __half g_pmh[(size_t)MTOK * PPADB];
__device__ __half g_pdh[(size_t)NENT * PPADB];
__device__ float g_fixX[(size_t)MAXFIX * HD];
__device__ float g_fixH[(size_t)MAXFIX * HD];
__device__ unsigned char g_valid1[MTOK];
__device__ unsigned char g_valid2[MTOK];
__device__ unsigned char g_fixvalid[MAXFIX];
__device__ int g_fixrows[MAXFIX];
__device__ int g_nfix;
__device__ int g_pred[MTOK];
__device__ unsigned int g_segse[NB * TB];
__device__ int g_nseg[NB];
__device__ int g_dest[NB];

// ---------------------------------------------------------------------------
__device__ __forceinline__ unsigned f2t(float x) {
    unsigned r;
    asm("cvt.rna.tf32.f32 %0, %1;" : "=r"(r) : "f"(x));
    return r;
}
__device__ __forceinline__ float f2tf(float x) { return __uint_as_float(f2t(x)); }

__device__ __forceinline__ unsigned pkh2(float x, float y) {
    __half2 h = __floats2half2_rn(x, y);   // x -> low half
    return *reinterpret_cast<unsigned*>(&h);
}

__device__ __forceinline__ void mma8(float* c, const unsigned* a, const unsigned* b) {
    asm volatile(
        "mma.sync.aligned.m16n8k8.row.col.f32.tf32.tf32.f32 "
        "{%0,%1,%2,%3},{%4,%5,%6,%7},{%8,%9},{%0,%1,%2,%3};\n"
        : "+f"(c[0]), "+f"(c[1]), "+f"(c[2]), "+f"(c[3])
        : "r"(a[0]), "r"(a[1]), "r"(a[2]), "r"(a[3]), "r"(b[0]), "r"(b[1]));
}

__device__ __forceinline__ void mma16(float* c, const unsigned* a, const unsigned* b) {
    asm volatile(
        "mma.sync.aligned.m16n8k16.row.col.f32.f16.f16.f32 "
        "{%0,%1,%2,%3},{%4,%5,%6,%7},{%8,%9},{%0,%1,%2,%3};\n"
        : "+f"(c[0]), "+f"(c[1]), "+f"(c[2]), "+f"(c[3])
        : "r"(a[0]), "r"(a[1]), "r"(a[2]), "r"(a[3]), "r"(b[0]), "r"(b[1]));
}

__device__ __forceinline__ uint32_t s2u(const void* p) {
    uint32_t a;
    asm("{ .reg .u64 t; cvta.to.shared.u64 t, %1; cvt.u32.u64 %0, t; }"
        : "=r"(a) : "l"(p));
    return a;
}

#define SWZ128(x) ((x) ^ (((x) >> 3) & 0x70))

__device__ __forceinline__ void ldsm4(uint32_t* r, uint32_t addr) {
    asm volatile(
        "ldmatrix.sync.aligned.m8n8.x4.shared.b16 {%0,%1,%2,%3}, [%4];"
        : "=r"(r[0]), "=r"(r[1]), "=r"(r[2]), "=r"(r[3]) : "r"(addr));
}
__device__ __forceinline__ void cpa16(uint32_t dst, const void* src) {
    asm volatile("cp.async.cg.shared.global [%0], [%1], 16;"
                 :: "r"(dst), "l"(src) : "memory");
}
__device__ __forceinline__ void cpa_commit() {
    asm volatile("cp.async.commit_group;" ::: "memory");
}

// =============================================================================
// cp.async + ldmatrix fp16 GEMM:  C[m,n] = act(sum_k A[m,k]*B[n,k] + bias)
// A,B fp16 row-major (ld = HD), K = HD (12 stages of 64).
// BM=128 BN=128 BK=64, 256 threads, warps 4m x 2n, warp tile 32x64.
// OUTH: write __half2 to C (cast); else float2.
// =============================================================================
#define GL_ASTG 16384
#define GL_SMEM (3 * 2 * 16384)   // 96KB

template<int RELU, int HASVALID, int OUTH>
__global__ void __launch_bounds__(256) gemm_ld(
    const __half* __restrict__ A, const __half* __restrict__ B,
    float* __restrict__ C, const float* __restrict__ bias,
    const unsigned char* __restrict__ valid, int Nstore, int ldc)
{
    extern __shared__ char smc[];
    const uint32_t sb = s2u(smc);
    __shared__ int s_any;
    const int tid = threadIdx.x;
    const int m0 = blockIdx.y * 128, n0 = blockIdx.x * 128;

    if (HASVALID) {
        if (tid == 0) s_any = 0;
        __syncthreads();
        if (tid < 128 && valid[m0 + tid]) s_any = 1;
        __syncthreads();
        if (!s_any) return;
    }

    const int warp = tid >> 5, lane = tid & 31;
    const int wm = warp & 3;
    const int wn = warp >> 2;

    float acc[2][8][4];
#pragma unroll
    for (int i = 0; i < 2; i++)
#pragma unroll
        for (int j = 0; j < 8; j++)
#pragma unroll
            for (int r = 0; r < 4; r++) acc[i][j][r] = 0.f;

    const int crow = tid >> 3, cch = tid & 7;
    const __half* Asrc = A + (size_t)(m0 + crow) * HD + cch * 8;
    const __half* Bsrc = B + (size_t)(n0 + crow) * HD + cch * 8;
    const uint32_t dOff = SWZ128(crow * 128 + cch * 16);

    auto issue = [&](int s) {
        const int buf = s % 3;
        const uint32_t ab = sb + buf * GL_ASTG;
        const uint32_t bb = sb + 49152 + buf * GL_ASTG;
        const __half* as = Asrc + s * 64;
        const __half* bs = Bsrc + s * 64;
#pragma unroll
        for (int i = 0; i < 4; i++)
            cpa16(ab + dOff + i * 4096, as + (size_t)i * 32 * HD);
#pragma unroll
        for (int i = 0; i < 4; i++)
            cpa16(bb + dOff + i * 4096, bs + (size_t)i * 32 * HD);
        cpa_commit();
    };

    issue(0); issue(1);

    const int arow = wm * 32 + (lane & 15);
    const int ach  = (lane >> 4) << 4;
    const int brow = wn * 64 + ((lane >> 4) << 3) + (lane & 7);
    const int bch  = ((lane >> 3) & 1) << 4;

    for (int s = 0; s < 12; s++) {
        if (s < 10) asm volatile("cp.async.wait_group 1;" ::: "memory");
        else        asm volatile("cp.async.wait_group 0;" ::: "memory");
        __syncthreads();
        if (s + 2 < 12) issue(s + 2);
        const int buf = s % 3;
        const uint32_t ab = sb + buf * GL_ASTG;
        const uint32_t bb = sb + 49152 + buf * GL_ASTG;
#pragma unroll
        for (int ks = 0; ks < 4; ks++) {
            uint32_t af[2][4];
#pragma unroll
            for (int mt = 0; mt < 2; mt++)
                ldsm4(af[mt], ab + SWZ128((arow + mt * 16) * 128 + ks * 32 + ach));
            uint32_t bf[4][4];
#pragma unroll
            for (int np = 0; np < 4; np++)
                ldsm4(bf[np], bb + SWZ128((brow + np * 16) * 128 + ks * 32 + bch));
#pragma unroll
            for (int nt = 0; nt < 8; nt++) {
                const unsigned* bp = &bf[nt >> 1][(nt & 1) * 2];
#pragma unroll
                for (int mt = 0; mt < 2; mt++)
                    mma16(acc[mt][nt], af[mt], bp);
            }
        }
    }

    const int g = lane >> 2, tig = lane & 3;
#pragma unroll
    for (int mt = 0; mt < 2; mt++) {
        const int row = m0 + wm * 32 + mt * 16 + g;
        bool v0 = true, v1 = true;
        if (HASVALID) { v0 = valid[row] != 0; v1 = valid[row + 8] != 0; }
#pragma unroll
        for (int nt = 0; nt < 8; nt++) {
            const int col = n0 + wn * 64 + nt * 8 + tig * 2;
            if (col < Nstore) {
                float a0 = acc[mt][nt][0], a1 = acc[mt][nt][1];
                float a2 = acc[mt][nt][2], a3 = acc[mt][nt][3];
                if (bias) {
                    const float b0 = bias[col], b1 = bias[col + 1];
                    a0 += b0; a1 += b1; a2 += b0; a3 += b1;
                }
                if (RELU) {
                    a0 = fmaxf(a0, 0.f); a1 = fmaxf(a1, 0.f);
                    a2 = fmaxf(a2, 0.f); a3 = fmaxf(a3, 0.f);
                }
                if (HASVALID) {
                    if (!v0) { a0 = 0.f; a1 = 0.f; }
                    if (!v1) { a2 = 0.f; a3 = 0.f; }
                }
                if (OUTH) {
                    __half* Ch = (__half*)C;
                    *(unsigned*)(Ch + (size_t)row * ldc + col) = pkh2(a0, a1);
                    *(unsigned*)(Ch + (size_t)(row + 8) * ldc + col) = pkh2(a2, a3);
                } else {
                    *(float2*)(C + (size_t)row * ldc + col) = make_float2(a0, a1);
                    *(float2*)(C + (size_t)(row + 8) * ldc + col) = make_float2(a2, a3);
                }
            }
        }
    }
}

// =============================================================================
// fp32 -> fp16 conversion kernels
// =============================================================================
__global__ void cvt_half_k(const float* __restrict__ s, __half* __restrict__ d, int n8)
{
    for (int i = blockIdx.x * blockDim.x + threadIdx.x; i < n8;
         i += gridDim.x * blockDim.x) {
        const float4 a = ((const float4*)s)[i * 2];
        const float4 b = ((const float4*)s)[i * 2 + 1];
        ((uint4*)d)[i] = make_uint4(pkh2(a.x, a.y), pkh2(a.z, a.w),
                                    pkh2(b.x, b.y), pkh2(b.z, b.w));
    }
}

__global__ void cvt_pad_k(const float* __restrict__ s, __half* __restrict__ d)
{
    const int i = blockIdx.x * blockDim.x + threadIdx.x;
    if (i >= PPADB * HD / 8) return;
    const int row = (i * 8) / HD;
    uint4 v = make_uint4(0u, 0u, 0u, 0u);
    if (row < PDIM) {
        const float4 a = ((const float4*)s)[i * 2];
        const float4 b = ((const float4*)s)[i * 2 + 1];
        v = make_uint4(pkh2(a.x, a.y), pkh2(a.z, a.w),
                       pkh2(b.x, b.y), pkh2(b.z, b.w));
    }
    ((uint4*)d)[i] = v;
}

// =============================================================================
// Split-tf32 GEMM (exact path for flagged rows) — unchanged
// =============================================================================
__global__ void __launch_bounds__(256, 2) gemm_split(
    const float* __restrict__ A, const float* __restrict__ B,
    float* __restrict__ C, const float* __restrict__ bias,
    const unsigned char* __restrict__ valid,
    int Nstore, int NloadB, int K, int lda, int ldb, int ldc)
{
    extern __shared__ float sm[];
    float* AH = sm;
    float* BH = sm + 8192;
    float* AL = sm + 12288;
    float* BL = sm + 20480;
    __shared__ int s_any;

    const int tid = threadIdx.x;
    const int m0 = blockIdx.y * 128;
    const int n0 = blockIdx.x * 64;

    if (valid != nullptr) {
        if (tid == 0) s_any = 0;
        __syncthreads();
        if (tid < 128 && valid[m0 + tid]) s_any = 1;
        __syncthreads();
        if (!s_any) return;
    }

    const int warp = tid >> 5, lane = tid & 31;
    const int wm = warp & 3;
    const int wn = warp >> 2;

    float acc[2][4][4];
#pragma unroll
    for (int i = 0; i < 2; i++)
#pragma unroll
        for (int j = 0; j < 4; j++)
#pragma unroll
            for (int r = 0; r < 4; r++) acc[i][j][r] = 0.f;

    int aBase[4]; const float* Ap[4];
#pragma unroll
    for (int i = 0; i < 4; i++) {
        const int idx = tid + 256 * i;
        const int r = idx >> 3, c4 = idx & 7;
        const int ks = c4 >> 1, khi = c4 & 1, mi = r >> 4, rr = r & 15;
        aBase[i] = ((ks * 8 + mi) * 32 + (rr & 7) * 4) * 4 + (rr >> 3) + (khi << 1);
        Ap[i] = A + (size_t)(m0 + r) * lda + c4 * 4;
    }
    int bBase[2]; const float* Bp[2]; bool bok[2];
#pragma unroll
    for (int i = 0; i < 2; i++) {
        const int idx = tid + 256 * i;
        const int n = idx >> 3, c4 = idx & 7;
        const int ks = c4 >> 1, khi = c4 & 1;
        bBase[i] = ((ks * 8 + (n >> 3)) * 32 + (n & 7) * 4) * 2 + khi;
        bok[i] = (n0 + n) < NloadB;
        Bp[i] = B + (size_t)(n0 + n) * ldb + c4 * 4;
    }

    const float4 z4 = make_float4(0.f, 0.f, 0.f, 0.f);
    float4 ar[4], br[2];

    auto stage = [&](int buf) {
        const int ao = buf * 4096, bo = buf * 2048;
#pragma unroll
        for (int i = 0; i < 4; i++) {
            const float h0 = f2tf(ar[i].x), h1 = f2tf(ar[i].y);
            const float h2 = f2tf(ar[i].z), h3 = f2tf(ar[i].w);
            AH[ao + aBase[i] + 0]  = h0; AH[ao + aBase[i] + 4]  = h1;
            AH[ao + aBase[i] + 8]  = h2; AH[ao + aBase[i] + 12] = h3;
            AL[ao + aBase[i] + 0]  = f2tf(ar[i].x - h0);
            AL[ao + aBase[i] + 4]  = f2tf(ar[i].y - h1);
            AL[ao + aBase[i] + 8]  = f2tf(ar[i].z - h2);
            AL[ao + aBase[i] + 12] = f2tf(ar[i].w - h3);
        }
#pragma unroll
        for (int i = 0; i < 2; i++) {
            const float h0 = f2tf(br[i].x), h1 = f2tf(br[i].y);
            const float h2 = f2tf(br[i].z), h3 = f2tf(br[i].w);
            BH[bo + bBase[i] + 0] = h0; BH[bo + bBase[i] + 2] = h1;
            BH[bo + bBase[i] + 4] = h2; BH[bo + bBase[i] + 6] = h3;
            BL[bo + bBase[i] + 0] = f2tf(br[i].x - h0);
            BL[bo + bBase[i] + 2] = f2tf(br[i].y - h1);
            BL[bo + bBase[i] + 4] = f2tf(br[i].z - h2);
            BL[bo + bBase[i] + 6] = f2tf(br[i].w - h3);
        }
    };

#pragma unroll
    for (int i = 0; i < 4; i++) ar[i] = *(const float4*)Ap[i];
#pragma unroll
    for (int i = 0; i < 2; i++) br[i] = bok[i] ? *(const float4*)Bp[i] : z4;
    stage(0);
    int cur = 0;

    const int nk = K / 32;
    for (int kt = 0; kt < nk; kt++) {
        if (kt + 1 < nk) {
            const int ko = (kt + 1) * 32;
#pragma unroll
            for (int i = 0; i < 4; i++) ar[i] = *(const float4*)(Ap[i] + ko);
#pragma unroll
            for (int i = 0; i < 2; i++) br[i] = bok[i] ? *(const float4*)(Bp[i] + ko) : z4;
        }
        __syncthreads();
        const int ao = cur * 4096, bo = cur * 2048;
#pragma unroll
        for (int ks = 0; ks < 4; ks++) {
            float4 ah[2], al[2];
#pragma unroll
            for (int mt = 0; mt < 2; mt++) {
                const int off = ((ks * 8 + wm * 2 + mt) * 32 + lane) * 4;
                ah[mt] = *(const float4*)&AH[ao + off];
                al[mt] = *(const float4*)&AL[ao + off];
            }
#pragma unroll
            for (int nt = 0; nt < 4; nt++) {
                const int off = ((ks * 8 + wn * 4 + nt) * 32 + lane) * 2;
                float2 bh = *(const float2*)&BH[bo + off];
                float2 bl = *(const float2*)&BL[bo + off];
#pragma unroll
                for (int mt = 0; mt < 2; mt++) {
                    mma8(acc[mt][nt], (const unsigned*)&ah[mt], (const unsigned*)&bh);
                    mma8(acc[mt][nt], (const unsigned*)&ah[mt], (const unsigned*)&bl);
                    mma8(acc[mt][nt], (const unsigned*)&al[mt], (const unsigned*)&bh);
                }
            }
        }
        if (kt + 1 < nk) { stage(cur ^ 1); cur ^= 1; }
    }

    const int g = lane >> 2, tig = lane & 3;
#pragma unroll
    for (int mt = 0; mt < 2; mt++) {
        const int row = m0 + wm * 32 + mt * 16 + g;
        bool v0 = true, v1 = true;
        if (valid != nullptr) { v0 = valid[row] != 0; v1 = valid[row + 8] != 0; }
#pragma unroll
        for (int nt = 0; nt < 4; nt++) {
            const int col = n0 + wn * 32 + nt * 8 + tig * 2;
            if (col < Nstore) {
                float a0 = acc[mt][nt][0], a1 = acc[mt][nt][1];
                float a2 = acc[mt][nt][2], a3 = acc[mt][nt][3];
                if (bias) {
                    const float b0 = bias[col], b1 = bias[col + 1];
                    a0 += b0; a1 += b1; a2 += b0; a3 += b1;
                }
                a0 = fmaxf(a0, 0.f); a1 = fmaxf(a1, 0.f);
                a2 = fmaxf(a2, 0.f); a3 = fmaxf(a3, 0.f);
                if (!v0) { a0 = 0.f; a1 = 0.f; }
                if (!v1) { a2 = 0.f; a3 = 0.f; }
                *(float2*)(C + (size_t)row * ldc + col) = make_float2(a0, a1);
                *(float2*)(C + (size_t)(row + 8) * ldc + col) = make_float2(a2, a3);
            }
        }
    }
}

// =============================================================================
// Bio head + ambiguity flags
// =============================================================================
__global__ void __launch_bounds__(256) head_kernel(
    const float* __restrict__ Hb, const float* __restrict__ W2,
    const float* __restrict__ b2, float* __restrict__ out0,
    int* __restrict__ pred, int* __restrict__ fixrows, int* __restrict__ nfix)
{
    __shared__ float w2s[3 * HD];
    __shared__ float b2s[3];
    const int tid = threadIdx.x;
    for (int i = tid; i < 3 * HD; i += 256) w2s[i] = W2[i];
    if (tid < 3) b2s[tid] = b2[tid];
    __syncthreads();

    const int warp = tid >> 5, lane = tid & 31;
    const int row = blockIdx.x * 8 + warp;
    const float* hr = Hb + (size_t)row * HD;
    float d0 = 0.f, d1 = 0.f, d2 = 0.f;
#pragma unroll
    for (int q = 0; q < 6; q++) {
        const int off = q * 128 + lane * 4;
        const float4 h  = *(const float4*)(hr + off);
        const float4 w0 = *(const float4*)(w2s + 0 * HD + off);
        const float4 w1 = *(const float4*)(w2s + 1 * HD + off);
        const float4 w2v = *(const float4*)(w2s + 2 * HD + off);
        d0 += h.x * w0.x + h.y * w0.y + h.z * w0.z + h.w * w0.w;
        d1 += h.x * w1.x + h.y * w1.y + h.z * w1.z + h.w * w1.w;
        d2 += h.x * w2v.x + h.y * w2v.y + h.z * w2v.z + h.w * w2v.w;
    }
#pragma unroll
    for (int o = 16; o >= 1; o >>= 1) {
        d0 += __shfl_xor_sync(0xffffffffu, d0, o);
        d1 += __shfl_xor_sync(0xffffffffu, d1, o);
        d2 += __shfl_xor_sync(0xffffffffu, d2, o);
    }
    if (lane == 0) {
        const float l0 = d0 + b2s[0], l1 = d1 + b2s[1], l2 = d2 + b2s[2];
        const float m = fmaxf(l0, fmaxf(l1, l2));
        const float s = __expf(l0 - m) + __expf(l1 - m) + __expf(l2 - m);
        const float lse = m + __logf(s);
        out0[row * 3 + 0] = l0 - lse;
        out0[row * 3 + 1] = l1 - lse;
        out0[row * 3 + 2] = l2 - lse;
        int p = 0; float bst = l0, sec;
        if (l1 > bst) { sec = bst; bst = l1; p = 1; } else sec = l1;
        if (l2 > bst) { sec = bst; bst = l2; p = 2; }
        else if (l2 > sec) sec = l2;
        pred[row] = p;
        if (bst - sec < GAP_THRESH) {
            const int ix = atomicAdd(nfix, 1);
            if (ix < MAXFIX) fixrows[ix] = row;
        }
    }
}

__global__ void gather_fix(const float* __restrict__ hidden,
                           const int* __restrict__ fixrows,
                           const int* __restrict__ nfix,
                           float* __restrict__ fixX,
                           unsigned char* __restrict__ fixvalid)
{
    const int b = blockIdx.x;
    int n = *nfix; if (n > MAXFIX) n = MAXFIX;
    if (b >= n) return;
    const int row = fixrows[b];
    const float4* src = (const float4*)(hidden + (size_t)row * HD);
    float4* dst = (float4*)(fixX + (size_t)b * HD);
    if (threadIdx.x < 192) dst[threadIdx.x] = src[threadIdx.x];
    if (threadIdx.x == 0) fixvalid[b] = 1;
}

__global__ void __launch_bounds__(256) head_fix(
    const float* __restrict__ Hf, const float* __restrict__ W2,
    const float* __restrict__ b2, const int* __restrict__ fixrows,
    const int* __restrict__ nfix, float* __restrict__ out0,
    int* __restrict__ pred)
{
    __shared__ float w2s[3 * HD];
    __shared__ float b2s[3];
    const int tid = threadIdx.x;
    int n = *nfix; if (n > MAXFIX) n = MAXFIX;
    if (blockIdx.x * 8 >= n) return;
    for (int i = tid; i < 3 * HD; i += 256) w2s[i] = W2[i];
    if (tid < 3) b2s[tid] = b2[tid];
    __syncthreads();

    const int warp = tid >> 5, lane = tid & 31;
    const int slot = blockIdx.x * 8 + warp;
    if (slot >= n) return;
    const int row = fixrows[slot];
    const float* hr = Hf + (size_t)slot * HD;
    float d0 = 0.f, d1 = 0.f, d2 = 0.f;
#pragma unroll
    for (int q = 0; q < 6; q++) {
        const int off = q * 128 + lane * 4;
        const float4 h  = *(const float4*)(hr + off);
        const float4 w0 = *(const float4*)(w2s + 0 * HD + off);
        const float4 w1 = *(const float4*)(w2s + 1 * HD + off);
        const float4 w2v = *(const float4*)(w2s + 2 * HD + off);
        d0 += h.x * w0.x + h.y * w0.y + h.z * w0.z + h.w * w0.w;
        d1 += h.x * w1.x + h.y * w1.y + h.z * w1.z + h.w * w1.w;
        d2 += h.x * w2v.x + h.y * w2v.y + h.z * w2v.z + h.w * w2v.w;
    }
#pragma unroll
    for (int o = 16; o >= 1; o >>= 1) {
        d0 += __shfl_xor_sync(0xffffffffu, d0, o);
        d1 += __shfl_xor_sync(0xffffffffu, d1, o);
        d2 += __shfl_xor_sync(0xffffffffu, d2, o);
    }
    if (lane == 0) {
        const float l0 = d0 + b2s[0], l1 = d1 + b2s[1], l2 = d2 + b2s[2];
        const float m = fmaxf(l0, fmaxf(l1, l2));
        const float s = __expf(l0 - m) + __expf(l1 - m) + __expf(l2 - m);
        const float lse = m + __logf(s);
        out0[row * 3 + 0] = l0 - lse;
        out0[row * 3 + 1] = l1 - lse;
        out0[row * 3 + 2] = l2 - lse;
        int p = 0; float bst = l0;
        if (l1 > bst) { bst = l1; p = 1; }
        if (l2 > bst) { p = 2; }
        pred[row] = p;
    }
}

// =============================================================================
// Segment scan + dest + pool (pool writes fp16)
// =============================================================================
__global__ void seg_scan(const int* __restrict__ lab,
                         unsigned int* __restrict__ segse, int* __restrict__ nseg)
{
    __shared__ int L[TB];
    const int b = blockIdx.x;
    for (int i = threadIdx.x; i < TB; i += blockDim.x) L[i] = lab[b * TB + i];
    __syncthreads();
    if (threadIdx.x == 0) {
        int ns = 0, start = 0, count = 0;
#pragma unroll 8
        for (int t = 0; t < TB; t++) {
            const int l = L[t];
            if (l == 1) {
                if (count > 0)
                    segse[b * TB + ns++] = (unsigned)start | ((unsigned)t << 16);
                start = t; count = 1;
            } else if (l != 0) {
                count++;
            }
        }
        if (count > 0)
            segse[b * TB + ns++] = (unsigned)start | ((unsigned)TB << 16);
        nseg[b] = ns;
    }
}

__global__ void seg_dest(const int* __restrict__ nseg, int* __restrict__ dest)
{
    if (threadIdx.x == 0) {
        int p = 0;
        for (int i = 0; i < NB; i++) dest[i] = (nseg[i] > 0) ? p++ : -1;
    }
}

__global__ void __launch_bounds__(192) pool_phase2(
    const float* __restrict__ hidden, const int* __restrict__ lab,
    const unsigned int* __restrict__ segse, const int* __restrict__ nseg,
    const int* __restrict__ dest, __half* __restrict__ pooledh,
    unsigned char* __restrict__ valid)
{
    const int b = blockIdx.y, r = blockIdx.x;
    if (r >= nseg[b]) return;
    const unsigned se = segse[b * TB + r];
    const int start = (int)(se & 0xffffu), end = (int)(se >> 16);
    const int tid = threadIdx.x;
    float4 a = make_float4(0.f, 0.f, 0.f, 0.f);
    int cnt = 0;
    for (int t = start; t < end; t++) {
        const int l = lab[b * TB + t];
        if (l != 0) {
            const float4 v = ((const float4*)(hidden + (size_t)(b * TB + t) * HD))[tid];
            a.x += v.x; a.y += v.y; a.z += v.z; a.w += v.w;
            cnt++;
        }
    }
    const float c = (float)cnt;
    const int outr = dest[b] * TB + r;
    uint2 w = make_uint2(pkh2(a.x / c, a.y / c), pkh2(a.z / c, a.w / c));
    ((uint2*)(pooledh + (size_t)outr * HD))[tid] = w;
    if (tid == 0) valid[outr] = 1;
}

// =============================================================================
// Fused score + log_softmax: cp.async + ldmatrix, fp16 inputs.
// Block = 64-row pm band (resident in smem, 48KB, staged once),
// pd streamed in 128x64h tiles through 3-deep cp.async ring (96 stages).
// Online max/sumexp per row; raw store; L2-hot in-place lse fixup.
// =============================================================================
#define SCL_B0 49152
#define SCL_SMEM 98304

__global__ void __launch_bounds__(256) score_ld(
    const __half* __restrict__ pmh, const __half* __restrict__ pdh,
    const unsigned char* __restrict__ valid, float* __restrict__ out)
{
    extern __shared__ char smc[];
    const uint32_t sb = s2u(smc);
    __shared__ float partM[256], partS[256], lse[64];
    __shared__ int s_any;

    const int tid = threadIdx.x;
    const int m0 = blockIdx.x * 64;
    if (tid == 0) s_any = 0;
    __syncthreads();
    if (tid < 64 && valid[m0 + tid]) s_any = 1;
    __syncthreads();

    float* orow = out + (size_t)m0 * NENT;
    if (!s_any) {
        const float C0 = -7.6246190f;   // -ln(2048)
        const float4 v = make_float4(C0, C0, C0, C0);
        float4* o4 = (float4*)orow;
        for (int i = tid; i < 64 * NENT / 4; i += 256) o4[i] = v;
        return;
    }

    // --- stage A (pm band 64 x 384h) : 6 chunks of [64rows x 64h], swizzled
#pragma unroll
    for (int kc = 0; kc < 6; kc++) {
#pragma unroll
        for (int i = 0; i < 2; i++) {
            const int idx = tid + 256 * i;
            const int row = idx >> 3, j = idx & 7;
            cpa16(sb + kc * 8192 + SWZ128(row * 128 + j * 16),
                  pmh + (size_t)(m0 + row) * PPADB + kc * 64 + j * 8);
        }
    }

    auto issueB = [&](int gidx) {
        const int nt = gidx / 6, kc = gidx % 6;
        const uint32_t bb = sb + SCL_B0 + (gidx % 3) * 16384;
        const __half* src = pdh + (size_t)(nt * 128) * PPADB + kc * 64;
#pragma unroll
        for (int i = 0; i < 4; i++) {
            const int idx = tid + 256 * i;
            const int row = idx >> 3, j = idx & 7;
            cpa16(bb + SWZ128(row * 128 + j * 16), src + (size_t)row * PPADB + j * 8);
        }
        cpa_commit();
    };

    issueB(0);   // group0 = A chunks + B0
    issueB(1);   // group1 = B1

    const int warp = tid >> 5, lane = tid & 31;
    const int wm = warp & 1;
    const int wn = warp >> 1;
    const int g = lane >> 2, tig = lane & 3;
    const int arow = wm * 32 + (lane & 15);
    const int ach  = (lane >> 4) << 4;
    const int brow = wn * 32 + ((lane >> 4) << 3) + (lane & 7);
    const int bch  = ((lane >> 3) & 1) << 4;

    float Mr[4] = { -3.0e38f, -3.0e38f, -3.0e38f, -3.0e38f };
    float Sr[4] = { 0.f, 0.f, 0.f, 0.f };
    float acc[2][4][4];

    for (int G = 0; G < 96; G++) {
        const int NT = G / 6, kc = G % 6;
        if (G < 94) asm volatile("cp.async.wait_group 1;" ::: "memory");
        else        asm volatile("cp.async.wait_group 0;" ::: "memory");
        __syncthreads();
        if (G + 2 < 96) issueB(G + 2);
        if (kc == 0) {
#pragma unroll
            for (int i = 0; i < 2; i++)
#pragma unroll
                for (int j = 0; j < 4; j++)
#pragma unroll
                    for (int r = 0; r < 4; r++) acc[i][j][r] = 0.f;
        }
        const uint32_t ab = sb + kc * 8192;
        const uint32_t bb = sb + SCL_B0 + (G % 3) * 16384;
#pragma unroll
        for (int ks = 0; ks < 4; ks++) {
            uint32_t af[2][4];
#pragma unroll
            for (int mt = 0; mt < 2; mt++)
                ldsm4(af[mt], ab + SWZ128((arow + mt * 16) * 128 + ks * 32 + ach));
            uint32_t bf[2][4];
#pragma unroll
            for (int np = 0; np < 2; np++)
                ldsm4(bf[np], bb + SWZ128((brow + np * 16) * 128 + ks * 32 + bch));
#pragma unroll
            for (int nt2 = 0; nt2 < 4; nt2++) {
                const unsigned* bp = &bf[nt2 >> 1][(nt2 & 1) * 2];
#pragma unroll
                for (int mt = 0; mt < 2; mt++)
                    mma16(acc[mt][nt2], af[mt], bp);
            }
        }
        if (kc == 5) {
            const int n0 = NT * 128;
#pragma unroll
            for (int mt = 0; mt < 2; mt++)
#pragma unroll
                for (int h = 0; h < 2; h++) {
                    const int s = mt * 2 + h;
                    float v[8];
#pragma unroll
                    for (int j = 0; j < 4; j++) {
                        v[j * 2 + 0] = acc[mt][j][h * 2 + 0];
                        v[j * 2 + 1] = acc[mt][j][h * 2 + 1];
                    }
                    float tm = v[0];
#pragma unroll
                    for (int j = 1; j < 8; j++) tm = fmaxf(tm, v[j]);
                    const float nm = fmaxf(Mr[s], tm);
                    float add = 0.f;
#pragma unroll
                    for (int j = 0; j < 8; j++) add += __expf(v[j] - nm);
                    Sr[s] = Sr[s] * __expf(Mr[s] - nm) + add;
                    Mr[s] = nm;
                }
#pragma unroll
            for (int mt = 0; mt < 2; mt++) {
                const int row = m0 + wm * 32 + mt * 16 + g;
#pragma unroll
                for (int j = 0; j < 4; j++) {
                    const int col = n0 + wn * 32 + j * 8 + tig * 2;
                    *(float2*)(out + (size_t)row * NENT + col) =
                        make_float2(acc[mt][j][0], acc[mt][j][1]);
                    *(float2*)(out + (size_t)(row + 8) * NENT + col) =
                        make_float2(acc[mt][j][2], acc[mt][j][3]);
                }
            }
        }
    }

    // reduce lse across quad + warps
#pragma unroll
    for (int s = 0; s < 4; s++) {
#pragma unroll
        for (int off = 1; off <= 2; off <<= 1) {
            const float oM = __shfl_xor_sync(0xffffffffu, Mr[s], off);
            const float oS = __shfl_xor_sync(0xffffffffu, Sr[s], off);
            const float nm = fmaxf(Mr[s], oM);
            Sr[s] = Sr[s] * __expf(Mr[s] - nm) + oS * __expf(oM - nm);
            Mr[s] = nm;
        }
    }
    __syncthreads();
    if (tig == 0) {
#pragma unroll
        for (int s = 0; s < 4; s++) {
            const int r = wm * 32 + (s >> 1) * 16 + (s & 1) * 8 + g;
            partM[wn * 64 + r] = Mr[s];
            partS[wn * 64 + r] = Sr[s];
        }
    }
    __syncthreads();
    if (tid < 64) {
        float M = partM[tid];
#pragma unroll
        for (int w = 1; w < 4; w++) M = fmaxf(M, partM[w * 64 + tid]);
        float S = 0.f;
#pragma unroll
        for (int w = 0; w < 4; w++)
            S += partS[w * 64 + tid] * __expf(partM[w * 64 + tid] - M);
        lse[tid] = M + __logf(S);
    }
    __syncthreads();   // lse ready; raw writes visible block-wide

    float4* o4 = (float4*)orow;
    for (int i = tid; i < 64 * NENT / 4; i += 256) {
        const int r = i >> 9;
        const float cc = lse[r];
        float4 v = o4[i];
        v.x -= cc; v.y -= cc; v.z -= cc; v.w -= cc;
        o4[i] = v;
    }
}

// =============================================================================
extern "C" void kernel_launch(void* const* d_in, const int* in_sizes, int n_in,
                              void* d_out, int out_size)
{
    (void)in_sizes; (void)n_in; (void)out_size;
    const int*   labels = (const int*)d_in[0];
    const float* hidden = (const float*)d_in[1];
    const float* ent    = (const float*)d_in[2];
    const float* W1     = (const float*)d_in[3];
    const float* b1     = (const float*)d_in[4];
    const float* W2     = (const float*)d_in[5];
    const float* b2     = (const float*)d_in[6];
    const float* Wm     = (const float*)d_in[7];
    const float* Wd     = (const float*)d_in[8];

    float* out0 = (float*)d_out;
    float* out1 = out0 + (size_t)MTOK * 3;
    float* out2 = out1 + (size_t)MTOK * NENT;

    float *pH, *pFixX, *pFixH;
    __half *pXh, *pPooledh, *pW1h, *pEnth, *pWmh, *pWdh, *pPmh, *pPdh;
    unsigned char *pV1, *pV2, *pFixV;
    int *pPred, *pNseg, *pDest, *pFixRows, *pNfix;
    unsigned int *pSegse;
    cudaGetSymbolAddress((void**)&pH,      g_H);
    cudaGetSymbolAddress((void**)&pXh,     g_Xh);
    cudaGetSymbolAddress((void**)&pPooledh,g_pooledh);
    cudaGetSymbolAddress((void**)&pW1h,    g_W1h);
    cudaGetSymbolAddress((void**)&pEnth,   g_enth);
    cudaGetSymbolAddress((void**)&pWmh,    g_Wmh);
    cudaGetSymbolAddress((void**)&pWdh,    g_Wdh);
    cudaGetSymbolAddress((void**)&pPmh,    g_pmh);
    cudaGetSymbolAddress((void**)&pPdh,    g_pdh);
    cudaGetSymbolAddress((void**)&pFixX,   g_fixX);
    cudaGetSymbolAddress((void**)&pFixH,   g_fixH);
    cudaGetSymbolAddress((void**)&pV1,     g_valid1);
    cudaGetSymbolAddress((void**)&pV2,     g_valid2);
    cudaGetSymbolAddress((void**)&pFixV,   g_fixvalid);
    cudaGetSymbolAddress((void**)&pPred,   g_pred);
    cudaGetSymbolAddress((void**)&pNseg,   g_nseg);
    cudaGetSymbolAddress((void**)&pDest,   g_dest);
    cudaGetSymbolAddress((void**)&pFixRows,g_fixrows);
    cudaGetSymbolAddress((void**)&pNfix,   g_nfix);
    cudaGetSymbolAddress((void**)&pSegse,  g_segse);

    const int SMEM_SPLIT = 24576 * 4;   // 96KB
    cudaFuncSetAttribute(gemm_ld<1, 0, 0>, cudaFuncAttributeMaxDynamicSharedMemorySize, GL_SMEM);
    cudaFuncSetAttribute(gemm_ld<0, 0, 1>, cudaFuncAttributeMaxDynamicSharedMemorySize, GL_SMEM);
    cudaFuncSetAttribute(gemm_ld<0, 1, 1>, cudaFuncAttributeMaxDynamicSharedMemorySize, GL_SMEM);
    cudaFuncSetAttribute(gemm_split, cudaFuncAttributeMaxDynamicSharedMemorySize, SMEM_SPLIT);
    cudaFuncSetAttribute(score_ld, cudaFuncAttributeMaxDynamicSharedMemorySize, SCL_SMEM);

    cudaMemsetAsync(pNfix, 0, sizeof(int));
    cudaMemsetAsync(pFixV, 0, MAXFIX);
    cudaMemsetAsync(pV1, 0, MTOK);
    cudaMemsetAsync(pV2, 0, MTOK);

    // 0) fp32 -> fp16 conversions (once)
    cvt_half_k<<<3072, 256>>>(hidden, pXh, MTOK * HD / 8);
    cvt_half_k<<<288, 256>>>(W1, pW1h, HD * HD / 8);
    cvt_half_k<<<768, 256>>>(ent, pEnth, NENT * HD / 8);
    cvt_pad_k<<<(PPADB * HD / 8 + 255) / 256, 256>>>(Wm, pWmh);
    cvt_pad_k<<<(PPADB * HD / 8 + 255) / 256, 256>>>(Wd, pWdh);

    // 1) h = relu(X@W1^T + b1)
    gemm_ld<1, 0, 0><<<dim3(HD / 128, MTOK / 128), 256, GL_SMEM>>>(
        pXh, pW1h, pH, b1, nullptr, HD, HD);

    // 2) bio head + ambiguity flags
    head_kernel<<<MTOK / 8, 256>>>(pH, W2, b2, out0, pPred, pFixRows, pNfix);

    // 2b) exact recompute of flagged rows (split tf32 ~ fp32)
    gather_fix<<<MAXFIX, 192>>>(hidden, pFixRows, pNfix, pFixX, pFixV);
    gemm_split<<<dim3(HD / 64, MAXFIX / 128), 256, SMEM_SPLIT>>>(
        pFixX, W1, pFixH, b1, pFixV, HD, HD, HD, HD, HD, HD);
    head_fix<<<MAXFIX / 8, 256>>>(pFixH, W2, b2, pFixRows, pNfix, out0, pPred);

    // 3) pdh = ent @ Wd^T (fp16 out, cols 300..383 zero)
    gemm_ld<0, 0, 1><<<dim3(PPADB / 128, NENT / 128), 256, GL_SMEM>>>(
        pEnth, pWdh, (float*)pPdh, nullptr, nullptr, PPADB, PPADB);

    // ---- pass 1: true labels ----
    seg_scan<<<NB, 128>>>(labels, pSegse, pNseg);
    seg_dest<<<1, 32>>>(pNseg, pDest);
    pool_phase2<<<dim3(TB, NB), 192>>>(hidden, labels, pSegse, pNseg, pDest,
                                       pPooledh, pV1);
    gemm_ld<0, 1, 1><<<dim3(PPADB / 128, MTOK / 128), 256, GL_SMEM>>>(
        pPooledh, pWmh, (float*)pPmh, nullptr, pV1, PPADB, PPADB);
    score_ld<<<MTOK / 64, 256, SCL_SMEM>>>(pPmh, pPdh, pV1, out1);

    // ---- pass 2: predicted labels ----
    seg_scan<<<NB, 128>>>(pPred, pSegse, pNseg);
    seg_dest<<<1, 32>>>(pNseg, pDest);
    pool_phase2<<<dim3(TB, NB), 192>>>(hidden, pPred, pSegse, pNseg, pDest,
                                       pPooledh, pV2);
    gemm_ld<0, 1, 1><<<dim3(PPADB / 128, MTOK / 128), 256, GL_SMEM>>>(
        pPooledh, pWmh, (float*)pPmh, nullptr, pV2, PPADB, PPADB);
    score_ld<<<MTOK / 64, 256, SCL_SMEM>>>(pPmh, pPdh, pV2, out2);
}